// round 10
// baseline (speedup 1.0000x reference)
#include <cuda_runtime.h>
#include <math.h>

#define NRES 768
#define CSD  384
#define CZD  128
#define NHD  12
#define INF_ 100000.0f

typedef unsigned long long u64;

// ---------------- packed f32x2 helpers ----------------
__device__ __forceinline__ void ffma2(u64& d, u64 a, u64 b) {
    asm("fma.rn.f32x2 %0, %1, %2, %0;" : "+l"(d) : "l"(a), "l"(b));
}
__device__ __forceinline__ u64 dup2(float x) {
    u64 r; asm("mov.b64 %0, {%1, %1};" : "=l"(r) : "f"(x)); return r;
}
__device__ __forceinline__ u64 pk2(float lo, float hi) {
    u64 r; asm("mov.b64 %0, {%1, %2};" : "=l"(r) : "f"(lo), "f"(hi)); return r;
}
__device__ __forceinline__ float2 up2(u64 v) {
    float lo, hi; asm("mov.b64 {%0, %1}, %2;" : "=f"(lo), "=f"(hi) : "l"(v));
    return make_float2(lo, hi);
}
// ---------------- cp.async helpers ----------------
__device__ __forceinline__ void cpa16(void* dst, const void* src) {
    unsigned sdst = (unsigned)__cvta_generic_to_shared(dst);
    asm volatile("cp.async.cg.shared.global [%0], [%1], 16;" :: "r"(sdst), "l"(src));
}
__device__ __forceinline__ void cpa_commit() { asm volatile("cp.async.commit_group;"); }
__device__ __forceinline__ void cpa_wait0() { asm volatile("cp.async.wait_group 0;"); }

// ---------------- scratch (device globals; no allocation) ----------------
__device__ float g_se[NRES * CSD];
__device__ float g_proj[NRES * 1152];
__device__ float g_qhat[NRES * 336];
__device__ float g_khat[NRES * 336];
__device__ float g_kc[NRES * NHD];
__device__ float g_vall[NRES * NHD * 40];
__device__ float g_cat[NRES * 2112];
__device__ float g_part[4][NRES * CSD];
__device__ float g_logits[NHD * NRES * NRES]; // [i][h][j]: qk-logits, then unnormalized exp
__device__ float g_Sinv[NRES * NHD];          // 1/S per (i,h)

// =====================================================================
// fp32 GEMM (64x64, BK=16) with FFMA2 — used for the se GEMM only.
// =====================================================================
__device__ __forceinline__ void mm16(const float* Ab, const float* Wb,
                                     int ty, int tx, u64 acc2[4][2]) {
    #pragma unroll
    for (int k = 0; k < 16; k++) {
        float4 av = *(const float4*)(Ab + k * 68 + ty * 4);
        ulonglong2 wv = *(const ulonglong2*)(Wb + k * 68 + tx * 4);
        u64 a0 = dup2(av.x), a1 = dup2(av.y), a2 = dup2(av.z), a3 = dup2(av.w);
        ffma2(acc2[0][0], a0, wv.x); ffma2(acc2[0][1], a0, wv.y);
        ffma2(acc2[1][0], a1, wv.x); ffma2(acc2[1][1], a1, wv.y);
        ffma2(acc2[2][0], a2, wv.x); ffma2(acc2[2][1], a2, wv.y);
        ffma2(acc2[3][0], a3, wv.x); ffma2(acc2[3][1], a3, wv.y);
    }
}

__global__ __launch_bounds__(256) void k_gemm64(
    const float* __restrict__ A, const float* __restrict__ W,
    const float* __restrict__ bias, float* __restrict__ C,
    int ld, int ldc, int nkt, int add_bias, int partStride)
{
    __shared__ __align__(16) float As[2][16][68];
    __shared__ __align__(16) float Ws[2][16][68];
    int t  = threadIdx.x;
    int m0 = blockIdx.y * 64, n0 = blockIdx.x * 64;
    int kt0 = blockIdx.z * nkt;
    C += (size_t)blockIdx.z * partStride;
    int lr = t >> 2, lk = (t & 3) * 4;
    const float* arow = A + (size_t)(m0 + lr) * ld + kt0 * 16 + lk;
    const float* wrow = W + (size_t)(n0 + lr) * ld + kt0 * 16 + lk;
    int tx = t & 15, ty = t >> 4;

    u64 acc2[4][2] = {};
    float4 ra = *(const float4*)arow;
    float4 rw = *(const float4*)wrow;
    int buf = 0;
    As[0][lk+0][lr]=ra.x; As[0][lk+1][lr]=ra.y; As[0][lk+2][lr]=ra.z; As[0][lk+3][lr]=ra.w;
    Ws[0][lk+0][lr]=rw.x; Ws[0][lk+1][lr]=rw.y; Ws[0][lk+2][lr]=rw.z; Ws[0][lk+3][lr]=rw.w;

    for (int kt = 0; kt < nkt - 1; kt++) {
        __syncthreads();
        ra = *(const float4*)(arow + (kt + 1) * 16);
        rw = *(const float4*)(wrow + (kt + 1) * 16);
        mm16(&As[buf][0][0], &Ws[buf][0][0], ty, tx, acc2);
        int nb = buf ^ 1;
        As[nb][lk+0][lr]=ra.x; As[nb][lk+1][lr]=ra.y; As[nb][lk+2][lr]=ra.z; As[nb][lk+3][lr]=ra.w;
        Ws[nb][lk+0][lr]=rw.x; Ws[nb][lk+1][lr]=rw.y; Ws[nb][lk+2][lr]=rw.z; Ws[nb][lk+3][lr]=rw.w;
        buf = nb;
    }
    __syncthreads();
    mm16(&As[buf][0][0], &Ws[buf][0][0], ty, tx, acc2);

    float4 bv = make_float4(0.f, 0.f, 0.f, 0.f);
    if (add_bias) bv = *(const float4*)(bias + n0 + tx * 4);
    #pragma unroll
    for (int a = 0; a < 4; a++) {
        float2 p0 = up2(acc2[a][0]), p1 = up2(acc2[a][1]);
        float4 r = make_float4(p0.x + bv.x, p0.y + bv.y, p1.x + bv.z, p1.y + bv.w);
        *(float4*)(C + (size_t)(m0 + ty * 4 + a) * ldc + n0 + tx * 4) = r;
    }
}

// =====================================================================
// 128x128x16 GEMM, 256 threads, 8x8 microtile. C = A@W^T (+bias, split-K).
// =====================================================================
__device__ __forceinline__ void mm128_step(const float* Ab, const float* Wb,
                                           int ty, int tx, u64 acc[8][4]) {
    #pragma unroll
    for (int k = 0; k < 16; k++) {
        float4 av0 = *(const float4*)(Ab + k * 132 + ty * 4);
        float4 av1 = *(const float4*)(Ab + k * 132 + 64 + ty * 4);
        ulonglong2 wv0 = *(const ulonglong2*)(Wb + k * 132 + tx * 4);
        ulonglong2 wv1 = *(const ulonglong2*)(Wb + k * 132 + 64 + tx * 4);
        u64 a[8];
        a[0]=dup2(av0.x); a[1]=dup2(av0.y); a[2]=dup2(av0.z); a[3]=dup2(av0.w);
        a[4]=dup2(av1.x); a[5]=dup2(av1.y); a[6]=dup2(av1.z); a[7]=dup2(av1.w);
        #pragma unroll
        for (int r = 0; r < 8; r++) {
            ffma2(acc[r][0], a[r], wv0.x);
            ffma2(acc[r][1], a[r], wv0.y);
            ffma2(acc[r][2], a[r], wv1.x);
            ffma2(acc[r][3], a[r], wv1.y);
        }
    }
}

__global__ __launch_bounds__(256) void k_gemm128(
    const float* __restrict__ A, const float* __restrict__ W,
    const float* __restrict__ bias, float* __restrict__ C,
    int ld, int ldc, int nkt, int add_bias, int partStride)
{
    __shared__ __align__(16) float As[2][16][132];
    __shared__ __align__(16) float Ws[2][16][132];
    int t  = threadIdx.x;
    int m0 = blockIdx.y * 128, n0 = blockIdx.x * 128;
    int kt0 = blockIdx.z * nkt;
    C += (size_t)blockIdx.z * partStride;
    int lr = t >> 1, lk = (t & 1) * 8;
    const float* arow = A + (size_t)(m0 + lr) * ld + kt0 * 16 + lk;
    const float* wrow = W + (size_t)(n0 + lr) * ld + kt0 * 16 + lk;
    int tx = t & 15, ty = t >> 4;

    u64 acc[8][4] = {};
    float4 ra0 = *(const float4*)arow,       ra1 = *(const float4*)(arow + 4);
    float4 rw0 = *(const float4*)wrow,       rw1 = *(const float4*)(wrow + 4);
    int buf = 0;
    As[0][lk+0][lr]=ra0.x; As[0][lk+1][lr]=ra0.y; As[0][lk+2][lr]=ra0.z; As[0][lk+3][lr]=ra0.w;
    As[0][lk+4][lr]=ra1.x; As[0][lk+5][lr]=ra1.y; As[0][lk+6][lr]=ra1.z; As[0][lk+7][lr]=ra1.w;
    Ws[0][lk+0][lr]=rw0.x; Ws[0][lk+1][lr]=rw0.y; Ws[0][lk+2][lr]=rw0.z; Ws[0][lk+3][lr]=rw0.w;
    Ws[0][lk+4][lr]=rw1.x; Ws[0][lk+5][lr]=rw1.y; Ws[0][lk+6][lr]=rw1.z; Ws[0][lk+7][lr]=rw1.w;

    for (int kt = 0; kt < nkt - 1; kt++) {
        __syncthreads();
        ra0 = *(const float4*)(arow + (kt + 1) * 16);
        ra1 = *(const float4*)(arow + (kt + 1) * 16 + 4);
        rw0 = *(const float4*)(wrow + (kt + 1) * 16);
        rw1 = *(const float4*)(wrow + (kt + 1) * 16 + 4);
        mm128_step(&As[buf][0][0], &Ws[buf][0][0], ty, tx, acc);
        int nb = buf ^ 1;
        As[nb][lk+0][lr]=ra0.x; As[nb][lk+1][lr]=ra0.y; As[nb][lk+2][lr]=ra0.z; As[nb][lk+3][lr]=ra0.w;
        As[nb][lk+4][lr]=ra1.x; As[nb][lk+5][lr]=ra1.y; As[nb][lk+6][lr]=ra1.z; As[nb][lk+7][lr]=ra1.w;
        Ws[nb][lk+0][lr]=rw0.x; Ws[nb][lk+1][lr]=rw0.y; Ws[nb][lk+2][lr]=rw0.z; Ws[nb][lk+3][lr]=rw0.w;
        Ws[nb][lk+4][lr]=rw1.x; Ws[nb][lk+5][lr]=rw1.y; Ws[nb][lk+6][lr]=rw1.z; Ws[nb][lk+7][lr]=rw1.w;
        buf = nb;
    }
    __syncthreads();
    mm128_step(&As[buf][0][0], &Ws[buf][0][0], ty, tx, acc);

    #pragma unroll
    for (int half = 0; half < 2; half++) {
        #pragma unroll
        for (int a = 0; a < 4; a++) {
            int r = half * 4 + a;
            int m = m0 + half * 64 + ty * 4 + a;
            #pragma unroll
            for (int hn = 0; hn < 2; hn++) {
                int nc = n0 + hn * 64 + tx * 4;
                float2 p0 = up2(acc[r][hn * 2]), p1 = up2(acc[r][hn * 2 + 1]);
                float4 bv = make_float4(0.f, 0.f, 0.f, 0.f);
                if (add_bias) bv = *(const float4*)(bias + nc);
                float4 rr = make_float4(p0.x + bv.x, p0.y + bv.y, p1.x + bv.z, p1.y + bv.w);
                *(float4*)(C + (size_t)m * ldc + nc) = rr;
            }
        }
    }
}

// Fused projection GEMM at 128x128: row-wise weight select.
__device__ __forceinline__ float proj_bias(int n, const float* bq, const float* bkv,
                                           const float* bqp, const float* bkvp) {
    if (n < 192) return bq[n];
    if (n < 576) return bkv[n - 192];
    if (n < 720) return bqp[n - 576];
    return bkvp[n - 720];
}

__global__ __launch_bounds__(256) void k_gemm_proj128(
    const float* __restrict__ wq,  const float* __restrict__ bq,
    const float* __restrict__ wkv, const float* __restrict__ bkv,
    const float* __restrict__ wqp, const float* __restrict__ bqp,
    const float* __restrict__ wkvp,const float* __restrict__ bkvp)
{
    __shared__ __align__(16) float As[2][16][132];
    __shared__ __align__(16) float Ws[2][16][132];
    int t  = threadIdx.x;
    int m0 = blockIdx.y * 128, n0 = blockIdx.x * 128;
    int lr = t >> 1, lk = (t & 1) * 8;
    const float* arow = g_se + (size_t)(m0 + lr) * 384 + lk;
    int n = n0 + lr;
    const float* wbase; int nl;
    if      (n < 192) { wbase = wq;   nl = n; }
    else if (n < 576) { wbase = wkv;  nl = n - 192; }
    else if (n < 720) { wbase = wqp;  nl = n - 576; }
    else              { wbase = wkvp; nl = n - 720; }
    const float* wrow = wbase + (size_t)nl * 384 + lk;
    int tx = t & 15, ty = t >> 4;

    u64 acc[8][4] = {};
    float4 ra0 = *(const float4*)arow,       ra1 = *(const float4*)(arow + 4);
    float4 rw0 = *(const float4*)wrow,       rw1 = *(const float4*)(wrow + 4);
    int buf = 0;
    As[0][lk+0][lr]=ra0.x; As[0][lk+1][lr]=ra0.y; As[0][lk+2][lr]=ra0.z; As[0][lk+3][lr]=ra0.w;
    As[0][lk+4][lr]=ra1.x; As[0][lk+5][lr]=ra1.y; As[0][lk+6][lr]=ra1.z; As[0][lk+7][lr]=ra1.w;
    Ws[0][lk+0][lr]=rw0.x; Ws[0][lk+1][lr]=rw0.y; Ws[0][lk+2][lr]=rw0.z; Ws[0][lk+3][lr]=rw0.w;
    Ws[0][lk+4][lr]=rw1.x; Ws[0][lk+5][lr]=rw1.y; Ws[0][lk+6][lr]=rw1.z; Ws[0][lk+7][lr]=rw1.w;

    const int nkt = 24;
    for (int kt = 0; kt < nkt - 1; kt++) {
        __syncthreads();
        ra0 = *(const float4*)(arow + (kt + 1) * 16);
        ra1 = *(const float4*)(arow + (kt + 1) * 16 + 4);
        rw0 = *(const float4*)(wrow + (kt + 1) * 16);
        rw1 = *(const float4*)(wrow + (kt + 1) * 16 + 4);
        mm128_step(&As[buf][0][0], &Ws[buf][0][0], ty, tx, acc);
        int nb = buf ^ 1;
        As[nb][lk+0][lr]=ra0.x; As[nb][lk+1][lr]=ra0.y; As[nb][lk+2][lr]=ra0.z; As[nb][lk+3][lr]=ra0.w;
        As[nb][lk+4][lr]=ra1.x; As[nb][lk+5][lr]=ra1.y; As[nb][lk+6][lr]=ra1.z; As[nb][lk+7][lr]=ra1.w;
        Ws[nb][lk+0][lr]=rw0.x; Ws[nb][lk+1][lr]=rw0.y; Ws[nb][lk+2][lr]=rw0.z; Ws[nb][lk+3][lr]=rw0.w;
        Ws[nb][lk+4][lr]=rw1.x; Ws[nb][lk+5][lr]=rw1.y; Ws[nb][lk+6][lr]=rw1.z; Ws[nb][lk+7][lr]=rw1.w;
        buf = nb;
    }
    __syncthreads();
    mm128_step(&As[buf][0][0], &Ws[buf][0][0], ty, tx, acc);

    #pragma unroll
    for (int half = 0; half < 2; half++) {
        #pragma unroll
        for (int a = 0; a < 4; a++) {
            int r = half * 4 + a;
            int m = m0 + half * 64 + ty * 4 + a;
            #pragma unroll
            for (int hn = 0; hn < 2; hn++) {
                int nc = n0 + hn * 64 + tx * 4;
                float2 p0 = up2(acc[r][hn * 2]), p1 = up2(acc[r][hn * 2 + 1]);
                float4 rr = make_float4(
                    p0.x + proj_bias(nc + 0, bq, bkv, bqp, bkvp),
                    p0.y + proj_bias(nc + 1, bq, bkv, bqp, bkvp),
                    p1.x + proj_bias(nc + 2, bq, bkv, bqp, bkvp),
                    p1.y + proj_bias(nc + 3, bq, bkv, bqp, bkvp));
                *(float4*)(g_proj + (size_t)m * 1152 + nc) = rr;
            }
        }
    }
}

__global__ void k_combine(const float* __restrict__ bout, float* __restrict__ out) {
    int i = blockIdx.x * 256 + threadIdx.x;
    out[i] = g_part[0][i] + g_part[1][i] + g_part[2][i] + g_part[3][i] + bout[i % 384];
}

// ---------------- LayerNorm ----------------
__global__ void k_ln(const float* __restrict__ gamma, const float* __restrict__ beta) {
    int n = blockIdx.x, t = threadIdx.x;
    float* row = g_se + (size_t)n * CSD;
    float x0 = row[t], x1 = row[t + 128], x2 = row[t + 256];
    float s1 = x0 + x1 + x2;
    float s2 = x0 * x0 + x1 * x1 + x2 * x2;
    __shared__ float r1[4], r2[4];
    #pragma unroll
    for (int o = 16; o; o >>= 1) {
        s1 += __shfl_xor_sync(0xffffffffu, s1, o);
        s2 += __shfl_xor_sync(0xffffffffu, s2, o);
    }
    if ((t & 31) == 0) { r1[t >> 5] = s1; r2[t >> 5] = s2; }
    __syncthreads();
    float ts1 = r1[0] + r1[1] + r1[2] + r1[3];
    float ts2 = r2[0] + r2[1] + r2[2] + r2[3];
    float mu  = ts1 * (1.f / 384.f);
    float var = ts2 * (1.f / 384.f) - mu * mu;
    float inv = rsqrtf(var + 1e-5f);
    row[t]       = (x0 - mu) * inv * gamma[t]       + beta[t];
    row[t + 128] = (x1 - mu) * inv * gamma[t + 128] + beta[t + 128];
    row[t + 256] = (x2 - mu) * inv * gamma[t + 256] + beta[t + 256];
}

// ---------------- assemble qhat/khat/kc/v/v_pts (warp per n) ----------------
__global__ void k_assemble(const float* __restrict__ r_rot, const float* __restrict__ r_trans,
                           const float* __restrict__ head_w) {
    int gw   = blockIdx.x * 8 + (threadIdx.x >> 5);
    int lane = threadIdx.x & 31;
    if (gw >= NRES || lane >= NHD) return;
    int n = gw, h = lane;
    float rot[9], t0[3];
    #pragma unroll
    for (int i = 0; i < 9; i++) rot[i] = r_rot[n * 45 + i];
    #pragma unroll
    for (int i = 0; i < 3; i++) t0[i] = r_trans[n * 15 + i];
    float hw = log1pf(expf(head_w[h])) * rsqrtf(54.0f);
    const float c1 = rsqrtf(48.0f);
    const float* P = g_proj + (size_t)n * 1152;
    float* qh = g_qhat + (size_t)n * 336 + h * 28;
    float* kh = g_khat + (size_t)n * 336 + h * 28;
    float* va = g_vall + ((size_t)n * NHD + h) * 40;
    #pragma unroll
    for (int c = 0; c < 16; c++) {
        qh[c] = c1 * P[h * 16 + c];
        kh[c] = P[192 + h * 32 + c];
        va[c] = P[192 + h * 32 + 16 + c];
    }
    #pragma unroll
    for (int pp = 0; pp < 4; pp++) {
        float l0 = P[576 +   0 + h * 4 + pp];
        float l1 = P[576 +  48 + h * 4 + pp];
        float l2 = P[576 +  96 + h * 4 + pp];
        #pragma unroll
        for (int i = 0; i < 3; i++) {
            float o = rot[i * 3] * l0 + rot[i * 3 + 1] * l1 + rot[i * 3 + 2] * l2 + t0[i];
            qh[16 + pp * 3 + i] = hw * o;
        }
    }
    float kc = 0.f;
    #pragma unroll
    for (int pp = 0; pp < 4; pp++) {
        float l0 = P[720 +   0 + h * 12 + pp];
        float l1 = P[720 + 144 + h * 12 + pp];
        float l2 = P[720 + 288 + h * 12 + pp];
        #pragma unroll
        for (int i = 0; i < 3; i++) {
            float o = rot[i * 3] * l0 + rot[i * 3 + 1] * l1 + rot[i * 3 + 2] * l2 + t0[i];
            kh[16 + pp * 3 + i] = o;
            kc += o * o;
        }
    }
    g_kc[n * NHD + h] = -0.5f * hw * kc;
    #pragma unroll
    for (int pv = 0; pv < 8; pv++) {
        int pp = 4 + pv;
        float l0 = P[720 +   0 + h * 12 + pp];
        float l1 = P[720 + 144 + h * 12 + pp];
        float l2 = P[720 + 288 + h * 12 + pp];
        #pragma unroll
        for (int i = 0; i < 3; i++) {
            float o = rot[i * 3] * l0 + rot[i * 3 + 1] * l1 + rot[i * 3 + 2] * l2 + t0[i];
            va[16 + pv * 3 + i] = o;
        }
    }
}

// ---------------- qk logits (K=28 GEMM) + kc + mask per head ----------------
__global__ __launch_bounds__(256) void k_qk(const float* __restrict__ mask) {
    __shared__ __align__(16) float Qs[28][68];
    __shared__ __align__(16) float Ks[28][68];
    __shared__ float kcs[64], uli[64], ulj[64];
    int h = blockIdx.z, i0 = blockIdx.y * 64, j0 = blockIdx.x * 64;
    int t = threadIdx.x;
    for (int idx = t; idx < 64 * 28; idx += 256) {
        int m = idx / 28, k = idx % 28;
        Qs[k][m] = g_qhat[(size_t)(i0 + m) * 336 + h * 28 + k];
        Ks[k][m] = g_khat[(size_t)(j0 + m) * 336 + h * 28 + k];
    }
    if (t < 64) {
        kcs[t] = g_kc[(j0 + t) * NHD + h];
        uli[t] = mask[(i0 + t) * 5];
        ulj[t] = mask[(j0 + t) * 5];
    }
    __syncthreads();
    int tx = t & 15, ty = t >> 4;
    u64 acc2[4][2] = {};
    #pragma unroll
    for (int k = 0; k < 28; k++) {
        float4 av = *(const float4*)(&Qs[k][ty * 4]);
        ulonglong2 wv = *(const ulonglong2*)(&Ks[k][tx * 4]);
        u64 a0 = dup2(av.x), a1 = dup2(av.y), a2 = dup2(av.z), a3 = dup2(av.w);
        ffma2(acc2[0][0], a0, wv.x); ffma2(acc2[0][1], a0, wv.y);
        ffma2(acc2[1][0], a1, wv.x); ffma2(acc2[1][1], a1, wv.y);
        ffma2(acc2[2][0], a2, wv.x); ffma2(acc2[2][1], a2, wv.y);
        ffma2(acc2[3][0], a3, wv.x); ffma2(acc2[3][1], a3, wv.y);
    }
    int jb = tx * 4;
    #pragma unroll
    for (int a = 0; a < 4; a++) {
        int i = i0 + ty * 4 + a;
        float mi = uli[ty * 4 + a];
        float2 p0 = up2(acc2[a][0]), p1 = up2(acc2[a][1]);
        float4 r;
        r.x = p0.x + kcs[jb + 0] + INF_ * (mi * ulj[jb + 0] - 1.f);
        r.y = p0.y + kcs[jb + 1] + INF_ * (mi * ulj[jb + 1] - 1.f);
        r.z = p1.x + kcs[jb + 2] + INF_ * (mi * ulj[jb + 2] - 1.f);
        r.w = p1.y + kcs[jb + 3] + INF_ * (mi * ulj[jb + 3] - 1.f);
        *(float4*)(&g_logits[((size_t)i * NHD + h) * NRES + j0 + jb]) = r;
    }
}

// ---------------- persistent fused z-pass per i: bias + exp + S + o_pair ----
#define ZT_STRIDE 132
#define ZTILE (64 * ZT_STRIDE)
#define ZAT_ES   (2 * ZTILE * 4)                 // 67584
#define ZAT_WB2  (ZAT_ES + 64 * 12 * 4)          // 70656
#define ZAT_PH   (ZAT_WB2 + 128 * 6 * 8)         // 76800
#define ZAT_SS   (ZAT_PH + 256 * 6 * 8)          // 89088
#define ZAT_SMEM (ZAT_SS + 64)                   // 89152

__global__ __launch_bounds__(256) void k_zattn(const float* __restrict__ z,
                                               const float* __restrict__ wb) {
    extern __shared__ __align__(16) unsigned char smraw[];
    float* zs  = (float*)smraw;
    float* es  = (float*)(smraw + ZAT_ES);
    u64*   wb2 = (u64*)(smraw + ZAT_WB2);
    u64*   ph  = (u64*)(smraw + ZAT_PH);
    float* Ssum= (float*)(smraw + ZAT_SS);

    int i = blockIdx.x;
    int t = threadIdx.x;
    int lane = t & 31, warp = t >> 5;
    const float c2 = 0.57735026918962576f;  // sqrt(1/3)

    for (int e = t; e < 768; e += 256) {
        int c = e / 6, p = e % 6;
        wb2[e] = pk2(c2 * wb[(2 * p) * 128 + c], c2 * wb[(2 * p + 1) * 128 + c]);
    }

    const float4* zbase = (const float4*)(z + (size_t)i * NRES * CZD);
    // prologue: prefetch tile 0
    #pragma unroll
    for (int l = 0; l < 8; l++) {
        int idx = t + l * 256;
        cpa16(zs + (idx >> 5) * ZT_STRIDE + (idx & 31) * 4, zbase + idx);
    }
    cpa_commit();

    u64 accO[6] = {};
    float sacc[2] = {0.f, 0.f};
    int buf = 0;

    for (int jt = 0; jt < 12; jt++) {
        cpa_wait0();
        __syncthreads();
        const float* zt = zs + buf * ZTILE;

        // phase 1: quarter-row z.wb dots (j = t&63, q = t>>6)
        {
            int j = t & 63, q = t >> 6;
            const float* zj = zt + j * ZT_STRIDE + q * 32;
            u64 acc[6] = {};
            #pragma unroll
            for (int c4 = 0; c4 < 8; c4++) {
                float4 v = *(const float4*)(zj + c4 * 4);
                int cb = (q * 32 + c4 * 4) * 6;
                u64 z0 = dup2(v.x), z1 = dup2(v.y), z2 = dup2(v.z), z3 = dup2(v.w);
                {
                    ulonglong2 wA = *(const ulonglong2*)(wb2 + cb);
                    ulonglong2 wB = *(const ulonglong2*)(wb2 + cb + 2);
                    ulonglong2 wC = *(const ulonglong2*)(wb2 + cb + 4);
                    ffma2(acc[0], z0, wA.x); ffma2(acc[1], z0, wA.y);
                    ffma2(acc[2], z0, wB.x); ffma2(acc[3], z0, wB.y);
                    ffma2(acc[4], z0, wC.x); ffma2(acc[5], z0, wC.y);
                }
                {
                    ulonglong2 wA = *(const ulonglong2*)(wb2 + cb + 6);
                    ulonglong2 wB = *(const ulonglong2*)(wb2 + cb + 8);
                    ulonglong2 wC = *(const ulonglong2*)(wb2 + cb + 10);
                    ffma2(acc[0], z1, wA.x); ffma2(acc[1], z1, wA.y);
                    ffma2(acc[2], z1, wB.x); ffma2(acc[3], z1, wB.y);
                    ffma2(acc[4], z1, wC.x); ffma2(acc[5], z1, wC.y);
                }
                {
                    ulonglong2 wA = *(const ulonglong2*)(wb2 + cb + 12);
                    ulonglong2 wB = *(const ulonglong2*)(wb2 + cb + 14);
                    ulonglong2 wC = *(const ulonglong2*)(wb2 + cb + 16);
                    ffma2(acc[0], z2, wA.x); ffma2(acc[1], z2, wA.y);
                    ffma2(acc[2], z2, wB.x); ffma2(acc[3], z2, wB.y);
                    ffma2(acc[4], z2, wC.x); ffma2(acc[5], z2, wC.y);
                }
                {
                    ulonglong2 wA = *(const ulonglong2*)(wb2 + cb + 18);
                    ulonglong2 wB = *(const ulonglong2*)(wb2 + cb + 20);
                    ulonglong2 wC = *(const ulonglong2*)(wb2 + cb + 22);
                    ffma2(acc[0], z3, wA.x); ffma2(acc[1], z3, wA.y);
                    ffma2(acc[2], z3, wB.x); ffma2(acc[3], z3, wB.y);
                    ffma2(acc[4], z3, wC.x); ffma2(acc[5], z3, wC.y);
                }
            }
            #pragma unroll
            for (int p = 0; p < 6; p++) ph[t * 6 + p] = acc[p];
        }
        __syncthreads();

        // combine 4 quarters + qk logits + exp (unnormalized)
        if (t < 64) {
            int j = t, j0 = jt * 64;
            #pragma unroll
            for (int p = 0; p < 6; p++) {
                float2 s0 = up2(ph[(t) * 6 + p]);
                float2 s1 = up2(ph[(t + 64) * 6 + p]);
                float2 s2 = up2(ph[(t + 128) * 6 + p]);
                float2 s3 = up2(ph[(t + 192) * 6 + p]);
                float sx = s0.x + s1.x + s2.x + s3.x;
                float sy = s0.y + s1.y + s2.y + s3.y;
                int h0 = 2 * p, h1 = 2 * p + 1;
                size_t gi0 = ((size_t)i * NHD + h0) * NRES + j0 + j;
                size_t gi1 = ((size_t)i * NHD + h1) * NRES + j0 + j;
                float e0 = __expf(g_logits[gi0] + sx);
                float e1 = __expf(g_logits[gi1] + sy);
                g_logits[gi0] = e0; g_logits[gi1] = e1;
                es[j * 12 + h0] = e0; es[j * 12 + h1] = e1;
            }
        }
        __syncthreads();

        // early prefetch of next tile into buf^1 (its last readers finished
        // before this tile's first barrier)
        if (jt < 11) {
            float* zb = zs + (buf ^ 1) * ZTILE;
            const float4* zrow = zbase + (jt + 1) * 2048;
            #pragma unroll
            for (int l = 0; l < 8; l++) {
                int idx = t + l * 256;
                cpa16(zb + (idx >> 5) * ZT_STRIDE + (idx & 31) * 4, zrow + idx);
            }
            cpa_commit();
        }

        // partial S per head (register accumulation across tiles)
        {
            int cnt = 0;
            for (int h = warp; h < NHD; h += 8, cnt++) {
                float s = es[lane * 12 + h] + es[(lane + 32) * 12 + h];
                #pragma unroll
                for (int o = 16; o; o >>= 1) s += __shfl_xor_sync(0xffffffffu, s, o);
                sacc[cnt] += s;
            }
        }

        // phase 2: accumulate o_pair partials in registers
        {
            int c = t & 127, g = t >> 7;
            #pragma unroll 4
            for (int jj = 0; jj < 32; jj++) {
                int j = g * 32 + jj;
                u64 zd = dup2(zt[j * ZT_STRIDE + c]);
                const ulonglong2* aj = (const ulonglong2*)(es + j * 12);
                ulonglong2 a0 = aj[0], a1 = aj[1], a2 = aj[2];
                ffma2(accO[0], zd, a0.x); ffma2(accO[1], zd, a0.y);
                ffma2(accO[2], zd, a1.x); ffma2(accO[3], zd, a1.y);
                ffma2(accO[4], zd, a2.x); ffma2(accO[5], zd, a2.y);
            }
        }
        buf ^= 1;
    }

    // finalize S
    if (lane == 0) {
        int cnt = 0;
        for (int h = warp; h < NHD; h += 8, cnt++) Ssum[h] = sacc[cnt];
    }
    __syncthreads();
    if (t < NHD) {
        float inv = 1.0f / Ssum[t];
        Ssum[t] = inv;
        g_Sinv[i * NHD + t] = inv;
    }
    __syncthreads();

    // reduce o_pair halves, normalize, write
    {
        float* red = zs;
        int c = t & 127, g = t >> 7;
        #pragma unroll
        for (int p = 0; p < 6; p++) {
            float2 v = up2(accO[p]);
            red[(g * 12 + 2 * p) * 128 + c]     = v.x;
            red[(g * 12 + 2 * p + 1) * 128 + c] = v.y;
        }
        __syncthreads();
        for (int e = t; e < 1536; e += 256)
            g_cat[(size_t)i * 2112 + 576 + e] = (red[e] + red[1536 + e]) * Ssum[e >> 7];
    }
}

// ---------------- o = (e@v)/S, o_pt = inv-frame((e@v_pts)/S) fused ----------
#define OV_AT   0
#define OV_VS   17408
#define OV_RED  27648
#define OV_OPT  48128
#define OV_SMEM 54272

__global__ __launch_bounds__(256) void k_ov(const float* __restrict__ r_rot,
                                            const float* __restrict__ r_trans) {
    extern __shared__ __align__(16) unsigned char sm[];
    float* a_t  = (float*)(sm + OV_AT);    // [k][r] 64x68
    float* v_s  = (float*)(sm + OV_VS);    // [k][c] 64x40
    u64*   red  = (u64*)(sm + OV_RED);     // 128x20
    float* opts = (float*)(sm + OV_OPT);   // [r][24]
    int i0 = blockIdx.x * 64;
    int h  = blockIdx.y;
    int t  = threadIdx.x;
    int rq = t & 15, cq = (t >> 4) & 3, ks = t >> 6;
    u64 acc[4][5] = {};
    for (int jt = 0; jt < 12; jt++) {
        #pragma unroll
        for (int l = 0; l < 16; l++) {
            int idx = t + l * 256;
            int r = idx >> 6, k = idx & 63;
            a_t[k * 68 + r] = g_logits[((size_t)(i0 + r) * NHD + h) * NRES + jt * 64 + k];
        }
        #pragma unroll
        for (int l = 0; l < 10; l++) {
            int idx = t + l * 256;
            v_s[idx] = g_vall[((size_t)(jt * 64 + idx / 40) * NHD + h) * 40 + idx % 40];
        }
        __syncthreads();
        #pragma unroll
        for (int kk = 0; kk < 16; kk++) {
            int k = ks * 16 + kk;
            float4 av = *(const float4*)(a_t + k * 68 + rq * 4);
            const u64* vv = (const u64*)(v_s + k * 40 + cq * 10);
            u64 v0 = vv[0], v1 = vv[1], v2 = vv[2], v3 = vv[3], v4 = vv[4];
            u64 a0 = dup2(av.x), a1 = dup2(av.y), a2 = dup2(av.z), a3 = dup2(av.w);
            ffma2(acc[0][0], a0, v0); ffma2(acc[0][1], a0, v1); ffma2(acc[0][2], a0, v2);
            ffma2(acc[0][3], a0, v3); ffma2(acc[0][4], a0, v4);
            ffma2(acc[1][0], a1, v0); ffma2(acc[1][1], a1, v1); ffma2(acc[1][2], a1, v2);
            ffma2(acc[1][3], a1, v3); ffma2(acc[1][4], a1, v4);
            ffma2(acc[2][0], a2, v0); ffma2(acc[2][1], a2, v1); ffma2(acc[2][2], a2, v2);
            ffma2(acc[2][3], a2, v3); ffma2(acc[2][4], a2, v4);
            ffma2(acc[3][0], a3, v0); ffma2(acc[3][1], a3, v1); ffma2(acc[3][2], a3, v2);
            ffma2(acc[3][3], a3, v3); ffma2(acc[3][4], a3, v4);
        }
        __syncthreads();
    }
    int slot = t & 63;
    if (ks >= 2) {
        u64* dst = red + ((ks - 2) * 64 + slot) * 20;
        #pragma unroll
        for (int rr = 0; rr < 4; rr++)
            #pragma unroll
            for (int p = 0; p < 5; p++) dst[rr * 5 + p] = acc[rr][p];
    }
    __syncthreads();
    if (ks < 2) {
        const u64* src = red + (ks * 64 + slot) * 20;
        #pragma unroll
        for (int rr = 0; rr < 4; rr++)
            #pragma unroll
            for (int p = 0; p < 5; p++) {
                float2 a = up2(acc[rr][p]), b = up2(src[rr * 5 + p]);
                acc[rr][p] = pk2(a.x + b.x, a.y + b.y);
            }
    }
    __syncthreads();
    if (ks == 1) {
        u64* dst = red + slot * 20;
        #pragma unroll
        for (int rr = 0; rr < 4; rr++)
            #pragma unroll
            for (int p = 0; p < 5; p++) dst[rr * 5 + p] = acc[rr][p];
    }
    __syncthreads();
    if (ks == 0) {
        const u64* src = red + slot * 20;
        #pragma unroll
        for (int rr = 0; rr < 4; rr++) {
            int rl = rq * 4 + rr;
            float inv = g_Sinv[(i0 + rl) * NHD + h];
            #pragma unroll
            for (int p = 0; p < 5; p++) {
                float2 a = up2(acc[rr][p]), b = up2(src[rr * 5 + p]);
                float vx = (a.x + b.x) * inv, vy = (a.y + b.y) * inv;
                int c0 = cq * 10 + 2 * p;
                if (c0 < 16)     g_cat[(size_t)(i0 + rl) * 2112 + h * 16 + c0] = vx;
                else             opts[rl * 24 + (c0 - 16)] = vx;
                int c1 = c0 + 1;
                if (c1 < 16)     g_cat[(size_t)(i0 + rl) * 2112 + h * 16 + c1] = vy;
                else             opts[rl * 24 + (c1 - 16)] = vy;
            }
        }
    }
    __syncthreads();
    for (int e2 = t; e2 < 512; e2 += 256) {
        int rl = e2 >> 3, pv = e2 & 7;
        int n = i0 + rl;
        const float* pp = opts + rl * 24 + pv * 3;
        float d0 = pp[0] - r_trans[n * 15 + 0];
        float d1 = pp[1] - r_trans[n * 15 + 1];
        float d2 = pp[2] - r_trans[n * 15 + 2];
        const float* R = r_rot + n * 45;
        float o0 = R[0] * d0 + R[3] * d1 + R[6] * d2;
        float o1 = R[1] * d0 + R[4] * d1 + R[7] * d2;
        float o2 = R[2] * d0 + R[5] * d1 + R[8] * d2;
        float nm = sqrtf(o0 * o0 + o1 * o1 + o2 * o2 + 1e-8f);
        float* cb = g_cat + (size_t)n * 2112 + 192;
        int rr2 = h * 8 + pv;
        cb[rr2] = o0; cb[96 + rr2] = o1; cb[192 + rr2] = o2; cb[288 + rr2] = nm;
    }
}

// ---------------- launch ----------------
extern "C" void kernel_launch(void* const* d_in, const int* in_sizes, int n_in,
                              void* d_out, int out_size) {
    const float* s       = (const float*)d_in[0];
    const float* z       = (const float*)d_in[1];
    const float* r_rot   = (const float*)d_in[2];
    const float* r_trans = (const float*)d_in[3];
    const float* mask    = (const float*)d_in[4];
    const float* wq      = (const float*)d_in[5];
    const float* bq      = (const float*)d_in[6];
    const float* wkv     = (const float*)d_in[7];
    const float* bkv     = (const float*)d_in[8];
    const float* wqp     = (const float*)d_in[9];
    const float* bqp     = (const float*)d_in[10];
    const float* wkvp    = (const float*)d_in[11];
    const float* bkvp    = (const float*)d_in[12];
    const float* wb      = (const float*)d_in[13];
    const float* head_w  = (const float*)d_in[15];
    const float* wout    = (const float*)d_in[16];
    const float* bout    = (const float*)d_in[17];
    const float* wexp    = (const float*)d_in[18];
    const float* bexp    = (const float*)d_in[19];
    const float* ln_g    = (const float*)d_in[20];
    const float* ln_b    = (const float*)d_in[21];
    float* out = (float*)d_out;

    float *p_se = nullptr, *p_cat = nullptr, *p_part = nullptr;
    cudaGetSymbolAddress((void**)&p_se,   g_se);
    cudaGetSymbolAddress((void**)&p_cat,  g_cat);
    cudaGetSymbolAddress((void**)&p_part, g_part);

    static int attn_cfg = 0;
    if (!attn_cfg) {
        cudaFuncSetAttribute(k_zattn, cudaFuncAttributeMaxDynamicSharedMemorySize, ZAT_SMEM);
        cudaFuncSetAttribute(k_ov, cudaFuncAttributeMaxDynamicSharedMemorySize, OV_SMEM);
        attn_cfg = 1;
    }

    k_gemm64<<<dim3(6, 12, 1), 256>>>(s, wexp, bexp, p_se, 384, 384, 24, 1, 0);
    k_ln<<<768, 128>>>(ln_g, ln_b);
    k_gemm_proj128<<<dim3(9, 6), 256>>>(wq, bq, wkv, bkv, wqp, bqp, wkvp, bkvp);
    k_assemble<<<96, 256>>>(r_rot, r_trans, head_w);
    k_qk<<<dim3(12, 12, 12), 256>>>(mask);
    k_zattn<<<768, 256, ZAT_SMEM>>>(z, wb);
    k_ov<<<dim3(12, 12), 256, OV_SMEM>>>(r_rot, r_trans);
    k_gemm128<<<dim3(3, 6, 4), 256>>>(p_cat, wout, nullptr, p_part, 2112, 384, 33, 0, NRES * CSD);
    k_combine<<<1152, 256>>>(bout, out);
}

// round 11
// speedup vs baseline: 1.0689x; 1.0689x over previous
#include <cuda_runtime.h>
#include <math.h>

#define NRES 768
#define CSD  384
#define CZD  128
#define NHD  12
#define INF_ 100000.0f

typedef unsigned long long u64;

// ---------------- packed f32x2 helpers ----------------
__device__ __forceinline__ void ffma2(u64& d, u64 a, u64 b) {
    asm("fma.rn.f32x2 %0, %1, %2, %0;" : "+l"(d) : "l"(a), "l"(b));
}
__device__ __forceinline__ u64 dup2(float x) {
    u64 r; asm("mov.b64 %0, {%1, %1};" : "=l"(r) : "f"(x)); return r;
}
__device__ __forceinline__ u64 pk2(float lo, float hi) {
    u64 r; asm("mov.b64 %0, {%1, %2};" : "=l"(r) : "f"(lo), "f"(hi)); return r;
}
__device__ __forceinline__ float2 up2(u64 v) {
    float lo, hi; asm("mov.b64 {%0, %1}, %2;" : "=f"(lo), "=f"(hi) : "l"(v));
    return make_float2(lo, hi);
}
// ---------------- cp.async helpers ----------------
__device__ __forceinline__ void cpa16(void* dst, const void* src) {
    unsigned sdst = (unsigned)__cvta_generic_to_shared(dst);
    asm volatile("cp.async.cg.shared.global [%0], [%1], 16;" :: "r"(sdst), "l"(src));
}
__device__ __forceinline__ void cpa_commit() { asm volatile("cp.async.commit_group;"); }
__device__ __forceinline__ void cpa_wait1() { asm volatile("cp.async.wait_group 1;"); }
__device__ __forceinline__ void cpa_wait0() { asm volatile("cp.async.wait_group 0;"); }

// ---------------- scratch (device globals; no allocation) ----------------
__device__ float g_se[NRES * CSD];
__device__ float g_proj[NRES * 1152];
__device__ float g_qhat[NRES * 336];
__device__ float g_khat[NRES * 336];
__device__ float g_kc[NRES * NHD];
__device__ float g_vall[NRES * NHD * 40];
__device__ float g_cat[NRES * 2112];
__device__ float g_part[2][NRES * CSD];
__device__ float g_logits[NHD * NRES * NRES]; // [i][h][j]: qk-logits, then unnormalized exp
__device__ float g_Sinv[NRES * NHD];          // 1/S per (i,h)

// =====================================================================
// fp32 GEMM with FFMA2: C = A(MxK) @ W(NxK)^T [+ bias]; 64x64 tile, BK=16.
// =====================================================================
__device__ __forceinline__ void mm16(const float* Ab, const float* Wb,
                                     int ty, int tx, u64 acc2[4][2]) {
    #pragma unroll
    for (int k = 0; k < 16; k++) {
        float4 av = *(const float4*)(Ab + k * 68 + ty * 4);
        ulonglong2 wv = *(const ulonglong2*)(Wb + k * 68 + tx * 4);
        u64 a0 = dup2(av.x), a1 = dup2(av.y), a2 = dup2(av.z), a3 = dup2(av.w);
        ffma2(acc2[0][0], a0, wv.x); ffma2(acc2[0][1], a0, wv.y);
        ffma2(acc2[1][0], a1, wv.x); ffma2(acc2[1][1], a1, wv.y);
        ffma2(acc2[2][0], a2, wv.x); ffma2(acc2[2][1], a2, wv.y);
        ffma2(acc2[3][0], a3, wv.x); ffma2(acc2[3][1], a3, wv.y);
    }
}

__global__ __launch_bounds__(256) void k_gemm64(
    const float* __restrict__ A, const float* __restrict__ W,
    const float* __restrict__ bias, float* __restrict__ C,
    int ld, int ldc, int nkt, int add_bias, int partStride)
{
    __shared__ __align__(16) float As[2][16][68];
    __shared__ __align__(16) float Ws[2][16][68];
    int t  = threadIdx.x;
    int m0 = blockIdx.y * 64, n0 = blockIdx.x * 64;
    int kt0 = blockIdx.z * nkt;
    C += (size_t)blockIdx.z * partStride;
    int lr = t >> 2, lk = (t & 3) * 4;
    const float* arow = A + (size_t)(m0 + lr) * ld + kt0 * 16 + lk;
    const float* wrow = W + (size_t)(n0 + lr) * ld + kt0 * 16 + lk;
    int tx = t & 15, ty = t >> 4;

    u64 acc2[4][2] = {};
    float4 ra = *(const float4*)arow;
    float4 rw = *(const float4*)wrow;
    int buf = 0;
    As[0][lk+0][lr]=ra.x; As[0][lk+1][lr]=ra.y; As[0][lk+2][lr]=ra.z; As[0][lk+3][lr]=ra.w;
    Ws[0][lk+0][lr]=rw.x; Ws[0][lk+1][lr]=rw.y; Ws[0][lk+2][lr]=rw.z; Ws[0][lk+3][lr]=rw.w;

    for (int kt = 0; kt < nkt - 1; kt++) {
        __syncthreads();
        ra = *(const float4*)(arow + (kt + 1) * 16);
        rw = *(const float4*)(wrow + (kt + 1) * 16);
        mm16(&As[buf][0][0], &Ws[buf][0][0], ty, tx, acc2);
        int nb = buf ^ 1;
        As[nb][lk+0][lr]=ra.x; As[nb][lk+1][lr]=ra.y; As[nb][lk+2][lr]=ra.z; As[nb][lk+3][lr]=ra.w;
        Ws[nb][lk+0][lr]=rw.x; Ws[nb][lk+1][lr]=rw.y; Ws[nb][lk+2][lr]=rw.z; Ws[nb][lk+3][lr]=rw.w;
        buf = nb;
    }
    __syncthreads();
    mm16(&As[buf][0][0], &Ws[buf][0][0], ty, tx, acc2);

    float4 bv = make_float4(0.f, 0.f, 0.f, 0.f);
    if (add_bias) bv = *(const float4*)(bias + n0 + tx * 4);
    #pragma unroll
    for (int a = 0; a < 4; a++) {
        float2 p0 = up2(acc2[a][0]), p1 = up2(acc2[a][1]);
        float4 r = make_float4(p0.x + bv.x, p0.y + bv.y, p1.x + bv.z, p1.y + bv.w);
        *(float4*)(C + (size_t)(m0 + ty * 4 + a) * ldc + n0 + tx * 4) = r;
    }
}

__device__ __forceinline__ float proj_bias(int n, const float* bq, const float* bkv,
                                           const float* bqp, const float* bkvp) {
    if (n < 192) return bq[n];
    if (n < 576) return bkv[n - 192];
    if (n < 720) return bqp[n - 576];
    return bkvp[n - 720];
}

__global__ __launch_bounds__(256) void k_gemm_proj(
    const float* __restrict__ wq,  const float* __restrict__ bq,
    const float* __restrict__ wkv, const float* __restrict__ bkv,
    const float* __restrict__ wqp, const float* __restrict__ bqp,
    const float* __restrict__ wkvp,const float* __restrict__ bkvp)
{
    __shared__ __align__(16) float As[2][16][68];
    __shared__ __align__(16) float Ws[2][16][68];
    int t  = threadIdx.x;
    int m0 = blockIdx.y * 64, n0 = blockIdx.x * 64;
    int lr = t >> 2, lk = (t & 3) * 4;
    const float* arow = g_se + (size_t)(m0 + lr) * 384 + lk;
    int n = n0 + lr;
    const float* wbase; int nl;
    if      (n < 192) { wbase = wq;   nl = n; }
    else if (n < 576) { wbase = wkv;  nl = n - 192; }
    else if (n < 720) { wbase = wqp;  nl = n - 576; }
    else              { wbase = wkvp; nl = n - 720; }
    const float* wrow = wbase + (size_t)nl * 384 + lk;
    int tx = t & 15, ty = t >> 4;

    u64 acc2[4][2] = {};
    float4 ra = *(const float4*)arow;
    float4 rw = *(const float4*)wrow;
    int buf = 0;
    As[0][lk+0][lr]=ra.x; As[0][lk+1][lr]=ra.y; As[0][lk+2][lr]=ra.z; As[0][lk+3][lr]=ra.w;
    Ws[0][lk+0][lr]=rw.x; Ws[0][lk+1][lr]=rw.y; Ws[0][lk+2][lr]=rw.z; Ws[0][lk+3][lr]=rw.w;

    const int nkt = 24;
    for (int kt = 0; kt < nkt - 1; kt++) {
        __syncthreads();
        ra = *(const float4*)(arow + (kt + 1) * 16);
        rw = *(const float4*)(wrow + (kt + 1) * 16);
        mm16(&As[buf][0][0], &Ws[buf][0][0], ty, tx, acc2);
        int nb = buf ^ 1;
        As[nb][lk+0][lr]=ra.x; As[nb][lk+1][lr]=ra.y; As[nb][lk+2][lr]=ra.z; As[nb][lk+3][lr]=ra.w;
        Ws[nb][lk+0][lr]=rw.x; Ws[nb][lk+1][lr]=rw.y; Ws[nb][lk+2][lr]=rw.z; Ws[nb][lk+3][lr]=rw.w;
        buf = nb;
    }
    __syncthreads();
    mm16(&As[buf][0][0], &Ws[buf][0][0], ty, tx, acc2);

    int nc = n0 + tx * 4;
    float4 bv = make_float4(proj_bias(nc + 0, bq, bkv, bqp, bkvp),
                            proj_bias(nc + 1, bq, bkv, bqp, bkvp),
                            proj_bias(nc + 2, bq, bkv, bqp, bkvp),
                            proj_bias(nc + 3, bq, bkv, bqp, bkvp));
    #pragma unroll
    for (int a = 0; a < 4; a++) {
        float2 p0 = up2(acc2[a][0]), p1 = up2(acc2[a][1]);
        float4 r = make_float4(p0.x + bv.x, p0.y + bv.y, p1.x + bv.z, p1.y + bv.w);
        *(float4*)(g_proj + (size_t)(m0 + ty * 4 + a) * 1152 + nc) = r;
    }
}

__global__ void k_combine(const float* __restrict__ bout, float* __restrict__ out) {
    int i = blockIdx.x * 256 + threadIdx.x;
    out[i] = g_part[0][i] + g_part[1][i] + bout[i % 384];
}

// ---------------- LayerNorm ----------------
__global__ void k_ln(const float* __restrict__ gamma, const float* __restrict__ beta) {
    int n = blockIdx.x, t = threadIdx.x;
    float* row = g_se + (size_t)n * CSD;
    float x0 = row[t], x1 = row[t + 128], x2 = row[t + 256];
    float s1 = x0 + x1 + x2;
    float s2 = x0 * x0 + x1 * x1 + x2 * x2;
    __shared__ float r1[4], r2[4];
    #pragma unroll
    for (int o = 16; o; o >>= 1) {
        s1 += __shfl_xor_sync(0xffffffffu, s1, o);
        s2 += __shfl_xor_sync(0xffffffffu, s2, o);
    }
    if ((t & 31) == 0) { r1[t >> 5] = s1; r2[t >> 5] = s2; }
    __syncthreads();
    float ts1 = r1[0] + r1[1] + r1[2] + r1[3];
    float ts2 = r2[0] + r2[1] + r2[2] + r2[3];
    float mu  = ts1 * (1.f / 384.f);
    float var = ts2 * (1.f / 384.f) - mu * mu;
    float inv = rsqrtf(var + 1e-5f);
    row[t]       = (x0 - mu) * inv * gamma[t]       + beta[t];
    row[t + 128] = (x1 - mu) * inv * gamma[t + 128] + beta[t + 128];
    row[t + 256] = (x2 - mu) * inv * gamma[t + 256] + beta[t + 256];
}

// ---------------- assemble qhat/khat/kc/v/v_pts (warp per n) ----------------
__global__ void k_assemble(const float* __restrict__ r_rot, const float* __restrict__ r_trans,
                           const float* __restrict__ head_w) {
    int gw   = blockIdx.x * 8 + (threadIdx.x >> 5);
    int lane = threadIdx.x & 31;
    if (gw >= NRES || lane >= NHD) return;
    int n = gw, h = lane;
    float rot[9], t0[3];
    #pragma unroll
    for (int i = 0; i < 9; i++) rot[i] = r_rot[n * 45 + i];
    #pragma unroll
    for (int i = 0; i < 3; i++) t0[i] = r_trans[n * 15 + i];
    float hw = log1pf(expf(head_w[h])) * rsqrtf(54.0f);
    const float c1 = rsqrtf(48.0f);
    const float* P = g_proj + (size_t)n * 1152;
    float* qh = g_qhat + (size_t)n * 336 + h * 28;
    float* kh = g_khat + (size_t)n * 336 + h * 28;
    float* va = g_vall + ((size_t)n * NHD + h) * 40;
    #pragma unroll
    for (int c = 0; c < 16; c++) {
        qh[c] = c1 * P[h * 16 + c];
        kh[c] = P[192 + h * 32 + c];
        va[c] = P[192 + h * 32 + 16 + c];
    }
    #pragma unroll
    for (int pp = 0; pp < 4; pp++) {
        float l0 = P[576 +   0 + h * 4 + pp];
        float l1 = P[576 +  48 + h * 4 + pp];
        float l2 = P[576 +  96 + h * 4 + pp];
        #pragma unroll
        for (int i = 0; i < 3; i++) {
            float o = rot[i * 3] * l0 + rot[i * 3 + 1] * l1 + rot[i * 3 + 2] * l2 + t0[i];
            qh[16 + pp * 3 + i] = hw * o;
        }
    }
    float kc = 0.f;
    #pragma unroll
    for (int pp = 0; pp < 4; pp++) {
        float l0 = P[720 +   0 + h * 12 + pp];
        float l1 = P[720 + 144 + h * 12 + pp];
        float l2 = P[720 + 288 + h * 12 + pp];
        #pragma unroll
        for (int i = 0; i < 3; i++) {
            float o = rot[i * 3] * l0 + rot[i * 3 + 1] * l1 + rot[i * 3 + 2] * l2 + t0[i];
            kh[16 + pp * 3 + i] = o;
            kc += o * o;
        }
    }
    g_kc[n * NHD + h] = -0.5f * hw * kc;
    #pragma unroll
    for (int pv = 0; pv < 8; pv++) {
        int pp = 4 + pv;
        float l0 = P[720 +   0 + h * 12 + pp];
        float l1 = P[720 + 144 + h * 12 + pp];
        float l2 = P[720 + 288 + h * 12 + pp];
        #pragma unroll
        for (int i = 0; i < 3; i++) {
            float o = rot[i * 3] * l0 + rot[i * 3 + 1] * l1 + rot[i * 3 + 2] * l2 + t0[i];
            va[16 + pv * 3 + i] = o;
        }
    }
}

// ---------------- qk logits (K=28 GEMM) + kc + mask per head ----------------
__global__ __launch_bounds__(256) void k_qk(const float* __restrict__ mask) {
    __shared__ __align__(16) float Qs[28][68];
    __shared__ __align__(16) float Ks[28][68];
    __shared__ float kcs[64], uli[64], ulj[64];
    int h = blockIdx.z, i0 = blockIdx.y * 64, j0 = blockIdx.x * 64;
    int t = threadIdx.x;
    for (int idx = t; idx < 64 * 28; idx += 256) {
        int m = idx / 28, k = idx % 28;
        Qs[k][m] = g_qhat[(size_t)(i0 + m) * 336 + h * 28 + k];
        Ks[k][m] = g_khat[(size_t)(j0 + m) * 336 + h * 28 + k];
    }
    if (t < 64) {
        kcs[t] = g_kc[(j0 + t) * NHD + h];
        uli[t] = mask[(i0 + t) * 5];
        ulj[t] = mask[(j0 + t) * 5];
    }
    __syncthreads();
    int tx = t & 15, ty = t >> 4;
    u64 acc2[4][2] = {};
    #pragma unroll
    for (int k = 0; k < 28; k++) {
        float4 av = *(const float4*)(&Qs[k][ty * 4]);
        ulonglong2 wv = *(const ulonglong2*)(&Ks[k][tx * 4]);
        u64 a0 = dup2(av.x), a1 = dup2(av.y), a2 = dup2(av.z), a3 = dup2(av.w);
        ffma2(acc2[0][0], a0, wv.x); ffma2(acc2[0][1], a0, wv.y);
        ffma2(acc2[1][0], a1, wv.x); ffma2(acc2[1][1], a1, wv.y);
        ffma2(acc2[2][0], a2, wv.x); ffma2(acc2[2][1], a2, wv.y);
        ffma2(acc2[3][0], a3, wv.x); ffma2(acc2[3][1], a3, wv.y);
    }
    int jb = tx * 4;
    #pragma unroll
    for (int a = 0; a < 4; a++) {
        int i = i0 + ty * 4 + a;
        float mi = uli[ty * 4 + a];
        float2 p0 = up2(acc2[a][0]), p1 = up2(acc2[a][1]);
        float4 r;
        r.x = p0.x + kcs[jb + 0] + INF_ * (mi * ulj[jb + 0] - 1.f);
        r.y = p0.y + kcs[jb + 1] + INF_ * (mi * ulj[jb + 1] - 1.f);
        r.z = p1.x + kcs[jb + 2] + INF_ * (mi * ulj[jb + 2] - 1.f);
        r.w = p1.y + kcs[jb + 3] + INF_ * (mi * ulj[jb + 3] - 1.f);
        *(float4*)(&g_logits[((size_t)i * NHD + h) * NRES + j0 + jb]) = r;
    }
}

// ---------------- persistent fused z-pass: 2 i per block ----
// 12 j-tiles of 64 rows per i, cp.async double-buffered; 87KB smem -> 2 CTA/SM.
#define ZT_STRIDE 132
#define ZTILE (64 * ZT_STRIDE)
#define ZAT_ES   (2 * ZTILE * 4)                 // 67584
#define ZAT_WB2  (ZAT_ES + 64 * 12 * 4)          // 70656
#define ZAT_PH   (ZAT_WB2 + 128 * 6 * 8)         // 76800
#define ZAT_SS   (ZAT_PH + 256 * 6 * 8)          // 89088
#define ZAT_SMEM (ZAT_SS + 64)                   // 89152

__global__ __launch_bounds__(256) void k_zattn(const float* __restrict__ z,
                                               const float* __restrict__ wb) {
    extern __shared__ __align__(16) unsigned char smraw[];
    float* zs  = (float*)smraw;
    float* es  = (float*)(smraw + ZAT_ES);
    u64*   wb2 = (u64*)(smraw + ZAT_WB2);
    u64*   ph  = (u64*)(smraw + ZAT_PH);
    float* Ssum= (float*)(smraw + ZAT_SS);

    int t = threadIdx.x;
    int lane = t & 31, warp = t >> 5;
    const float c2 = 0.57735026918962576f;  // sqrt(1/3)

    for (int e = t; e < 768; e += 256) {
        int c = e / 6, p = e % 6;
        wb2[e] = pk2(c2 * wb[(2 * p) * 128 + c], c2 * wb[(2 * p + 1) * 128 + c]);
    }

    for (int ii = 0; ii < 2; ii++) {
        int i = blockIdx.x * 2 + ii;
        const float4* zbase = (const float4*)(z + (size_t)i * NRES * CZD);

        // prologue: prefetch tile 0 (barrier below orders against prior
        // output-phase reads of this buffer)
        __syncthreads();
        #pragma unroll
        for (int l = 0; l < 8; l++) {
            int idx = t + l * 256;
            cpa16(zs + (idx >> 5) * ZT_STRIDE + (idx & 31) * 4, zbase + idx);
        }
        cpa_commit();

        u64 accO[6] = {};
        float sacc[2] = {0.f, 0.f};
        int buf = 0;

        for (int jt = 0; jt < 12; jt++) {
            __syncthreads();  // closes previous tile's phase-2 reads of buf^1
            if (jt < 11) {
                float* zb = zs + (buf ^ 1) * ZTILE;
                const float4* zrow = zbase + (jt + 1) * 2048;
                #pragma unroll
                for (int l = 0; l < 8; l++) {
                    int idx = t + l * 256;
                    cpa16(zb + (idx >> 5) * ZT_STRIDE + (idx & 31) * 4, zrow + idx);
                }
                cpa_commit();
                cpa_wait1();
            } else {
                cpa_wait0();
            }
            __syncthreads();
            const float* zt = zs + buf * ZTILE;

            // phase 1: quarter-row z.wb dots (j = t&63, q = t>>6)
            {
                int j = t & 63, q = t >> 6;
                const float* zj = zt + j * ZT_STRIDE + q * 32;
                u64 acc[6] = {};
                #pragma unroll
                for (int c4 = 0; c4 < 8; c4++) {
                    float4 v = *(const float4*)(zj + c4 * 4);
                    int cb = (q * 32 + c4 * 4) * 6;
                    u64 z0 = dup2(v.x), z1 = dup2(v.y), z2 = dup2(v.z), z3 = dup2(v.w);
                    {
                        ulonglong2 wA = *(const ulonglong2*)(wb2 + cb);
                        ulonglong2 wB = *(const ulonglong2*)(wb2 + cb + 2);
                        ulonglong2 wC = *(const ulonglong2*)(wb2 + cb + 4);
                        ffma2(acc[0], z0, wA.x); ffma2(acc[1], z0, wA.y);
                        ffma2(acc[2], z0, wB.x); ffma2(acc[3], z0, wB.y);
                        ffma2(acc[4], z0, wC.x); ffma2(acc[5], z0, wC.y);
                    }
                    {
                        ulonglong2 wA = *(const ulonglong2*)(wb2 + cb + 6);
                        ulonglong2 wB = *(const ulonglong2*)(wb2 + cb + 8);
                        ulonglong2 wC = *(const ulonglong2*)(wb2 + cb + 10);
                        ffma2(acc[0], z1, wA.x); ffma2(acc[1], z1, wA.y);
                        ffma2(acc[2], z1, wB.x); ffma2(acc[3], z1, wB.y);
                        ffma2(acc[4], z1, wC.x); ffma2(acc[5], z1, wC.y);
                    }
                    {
                        ulonglong2 wA = *(const ulonglong2*)(wb2 + cb + 12);
                        ulonglong2 wB = *(const ulonglong2*)(wb2 + cb + 14);
                        ulonglong2 wC = *(const ulonglong2*)(wb2 + cb + 16);
                        ffma2(acc[0], z2, wA.x); ffma2(acc[1], z2, wA.y);
                        ffma2(acc[2], z2, wB.x); ffma2(acc[3], z2, wB.y);
                        ffma2(acc[4], z2, wC.x); ffma2(acc[5], z2, wC.y);
                    }
                    {
                        ulonglong2 wA = *(const ulonglong2*)(wb2 + cb + 18);
                        ulonglong2 wB = *(const ulonglong2*)(wb2 + cb + 20);
                        ulonglong2 wC = *(const ulonglong2*)(wb2 + cb + 22);
                        ffma2(acc[0], z3, wA.x); ffma2(acc[1], z3, wA.y);
                        ffma2(acc[2], z3, wB.x); ffma2(acc[3], z3, wB.y);
                        ffma2(acc[4], z3, wC.x); ffma2(acc[5], z3, wC.y);
                    }
                }
                #pragma unroll
                for (int p = 0; p < 6; p++) ph[t * 6 + p] = acc[p];
            }
            __syncthreads();

            // combine 4 quarters + qk logits + exp (unnormalized)
            if (t < 64) {
                int j = t, j0 = jt * 64;
                #pragma unroll
                for (int p = 0; p < 6; p++) {
                    float2 s0 = up2(ph[(t) * 6 + p]);
                    float2 s1 = up2(ph[(t + 64) * 6 + p]);
                    float2 s2 = up2(ph[(t + 128) * 6 + p]);
                    float2 s3 = up2(ph[(t + 192) * 6 + p]);
                    float sx = s0.x + s1.x + s2.x + s3.x;
                    float sy = s0.y + s1.y + s2.y + s3.y;
                    int h0 = 2 * p, h1 = 2 * p + 1;
                    size_t gi0 = ((size_t)i * NHD + h0) * NRES + j0 + j;
                    size_t gi1 = ((size_t)i * NHD + h1) * NRES + j0 + j;
                    float e0 = __expf(g_logits[gi0] + sx);
                    float e1 = __expf(g_logits[gi1] + sy);
                    g_logits[gi0] = e0; g_logits[gi1] = e1;
                    es[j * 12 + h0] = e0; es[j * 12 + h1] = e1;
                }
            }
            __syncthreads();

            // partial S per head (register accumulation across tiles)
            {
                int cnt = 0;
                for (int h = warp; h < NHD; h += 8, cnt++) {
                    float s = es[lane * 12 + h] + es[(lane + 32) * 12 + h];
                    #pragma unroll
                    for (int o = 16; o; o >>= 1) s += __shfl_xor_sync(0xffffffffu, s, o);
                    sacc[cnt] += s;
                }
            }

            // phase 2: accumulate o_pair partials in registers
            {
                int c = t & 127, g = t >> 7;
                #pragma unroll 4
                for (int jj = 0; jj < 32; jj++) {
                    int j = g * 32 + jj;
                    u64 zd = dup2(zt[j * ZT_STRIDE + c]);
                    const ulonglong2* aj = (const ulonglong2*)(es + j * 12);
                    ulonglong2 a0 = aj[0], a1 = aj[1], a2 = aj[2];
                    ffma2(accO[0], zd, a0.x); ffma2(accO[1], zd, a0.y);
                    ffma2(accO[2], zd, a1.x); ffma2(accO[3], zd, a1.y);
                    ffma2(accO[4], zd, a2.x); ffma2(accO[5], zd, a2.y);
                }
            }
            buf ^= 1;
        }

        // finalize S
        if (lane == 0) {
            int cnt = 0;
            for (int h = warp; h < NHD; h += 8, cnt++) Ssum[h] = sacc[cnt];
        }
        __syncthreads();
        if (t < NHD) {
            float inv = 1.0f / Ssum[t];
            Ssum[t] = inv;
            g_Sinv[i * NHD + t] = inv;
        }
        __syncthreads();

        // reduce o_pair halves, normalize, write
        {
            float* red = zs;
            int c = t & 127, g = t >> 7;
            #pragma unroll
            for (int p = 0; p < 6; p++) {
                float2 v = up2(accO[p]);
                red[(g * 12 + 2 * p) * 128 + c]     = v.x;
                red[(g * 12 + 2 * p + 1) * 128 + c] = v.y;
            }
            __syncthreads();
            for (int e = t; e < 1536; e += 256)
                g_cat[(size_t)i * 2112 + 576 + e] = (red[e] + red[1536 + e]) * Ssum[e >> 7];
        }
    }
}

// ---------------- o = (e@v)/S, o_pt = inv-frame((e@v_pts)/S) fused ----------
#define OV_AT   0
#define OV_VS   17408
#define OV_RED  27648
#define OV_OPT  48128
#define OV_SMEM 54272

__global__ __launch_bounds__(256) void k_ov(const float* __restrict__ r_rot,
                                            const float* __restrict__ r_trans) {
    extern __shared__ __align__(16) unsigned char sm[];
    float* a_t  = (float*)(sm + OV_AT);    // [k][r] 64x68
    float* v_s  = (float*)(sm + OV_VS);    // [k][c] 64x40
    u64*   red  = (u64*)(sm + OV_RED);     // 128x20
    float* opts = (float*)(sm + OV_OPT);   // [r][24]
    int i0 = blockIdx.x * 64;
    int h  = blockIdx.y;
    int t  = threadIdx.x;
    int rq = t & 15, cq = (t >> 4) & 3, ks = t >> 6;
    u64 acc[4][5] = {};
    for (int jt = 0; jt < 12; jt++) {
        #pragma unroll
        for (int l = 0; l < 16; l++) {
            int idx = t + l * 256;
            int r = idx >> 6, k = idx & 63;
            a_t[k * 68 + r] = g_logits[((size_t)(i0 + r) * NHD + h) * NRES + jt * 64 + k];
        }
        #pragma unroll
        for (int l = 0; l < 10; l++) {
            int idx = t + l * 256;
            v_s[idx] = g_vall[((size_t)(jt * 64 + idx / 40) * NHD + h) * 40 + idx % 40];
        }
        __syncthreads();
        #pragma unroll
        for (int kk = 0; kk < 16; kk++) {
            int k = ks * 16 + kk;
            float4 av = *(const float4*)(a_t + k * 68 + rq * 4);
            const u64* vv = (const u64*)(v_s + k * 40 + cq * 10);
            u64 v0 = vv[0], v1 = vv[1], v2 = vv[2], v3 = vv[3], v4 = vv[4];
            u64 a0 = dup2(av.x), a1 = dup2(av.y), a2 = dup2(av.z), a3 = dup2(av.w);
            ffma2(acc[0][0], a0, v0); ffma2(acc[0][1], a0, v1); ffma2(acc[0][2], a0, v2);
            ffma2(acc[0][3], a0, v3); ffma2(acc[0][4], a0, v4);
            ffma2(acc[1][0], a1, v0); ffma2(acc[1][1], a1, v1); ffma2(acc[1][2], a1, v2);
            ffma2(acc[1][3], a1, v3); ffma2(acc[1][4], a1, v4);
            ffma2(acc[2][0], a2, v0); ffma2(acc[2][1], a2, v1); ffma2(acc[2][2], a2, v2);
            ffma2(acc[2][3], a2, v3); ffma2(acc[2][4], a2, v4);
            ffma2(acc[3][0], a3, v0); ffma2(acc[3][1], a3, v1); ffma2(acc[3][2], a3, v2);
            ffma2(acc[3][3], a3, v3); ffma2(acc[3][4], a3, v4);
        }
        __syncthreads();
    }
    int slot = t & 63;
    if (ks >= 2) {
        u64* dst = red + ((ks - 2) * 64 + slot) * 20;
        #pragma unroll
        for (int rr = 0; rr < 4; rr++)
            #pragma unroll
            for (int p = 0; p < 5; p++) dst[rr * 5 + p] = acc[rr][p];
    }
    __syncthreads();
    if (ks < 2) {
        const u64* src = red + (ks * 64 + slot) * 20;
        #pragma unroll
        for (int rr = 0; rr < 4; rr++)
            #pragma unroll
            for (int p = 0; p < 5; p++) {
                float2 a = up2(acc[rr][p]), b = up2(src[rr * 5 + p]);
                acc[rr][p] = pk2(a.x + b.x, a.y + b.y);
            }
    }
    __syncthreads();
    if (ks == 1) {
        u64* dst = red + slot * 20;
        #pragma unroll
        for (int rr = 0; rr < 4; rr++)
            #pragma unroll
            for (int p = 0; p < 5; p++) dst[rr * 5 + p] = acc[rr][p];
    }
    __syncthreads();
    if (ks == 0) {
        const u64* src = red + slot * 20;
        #pragma unroll
        for (int rr = 0; rr < 4; rr++) {
            int rl = rq * 4 + rr;
            float inv = g_Sinv[(i0 + rl) * NHD + h];
            #pragma unroll
            for (int p = 0; p < 5; p++) {
                float2 a = up2(acc[rr][p]), b = up2(src[rr * 5 + p]);
                float vx = (a.x + b.x) * inv, vy = (a.y + b.y) * inv;
                int c0 = cq * 10 + 2 * p;
                if (c0 < 16)     g_cat[(size_t)(i0 + rl) * 2112 + h * 16 + c0] = vx;
                else             opts[rl * 24 + (c0 - 16)] = vx;
                int c1 = c0 + 1;
                if (c1 < 16)     g_cat[(size_t)(i0 + rl) * 2112 + h * 16 + c1] = vy;
                else             opts[rl * 24 + (c1 - 16)] = vy;
            }
        }
    }
    __syncthreads();
    for (int e2 = t; e2 < 512; e2 += 256) {
        int rl = e2 >> 3, pv = e2 & 7;
        int n = i0 + rl;
        const float* pp = opts + rl * 24 + pv * 3;
        float d0 = pp[0] - r_trans[n * 15 + 0];
        float d1 = pp[1] - r_trans[n * 15 + 1];
        float d2 = pp[2] - r_trans[n * 15 + 2];
        const float* R = r_rot + n * 45;
        float o0 = R[0] * d0 + R[3] * d1 + R[6] * d2;
        float o1 = R[1] * d0 + R[4] * d1 + R[7] * d2;
        float o2 = R[2] * d0 + R[5] * d1 + R[8] * d2;
        float nm = sqrtf(o0 * o0 + o1 * o1 + o2 * o2 + 1e-8f);
        float* cb = g_cat + (size_t)n * 2112 + 192;
        int rr2 = h * 8 + pv;
        cb[rr2] = o0; cb[96 + rr2] = o1; cb[192 + rr2] = o2; cb[288 + rr2] = nm;
    }
}

// ---------------- launch ----------------
extern "C" void kernel_launch(void* const* d_in, const int* in_sizes, int n_in,
                              void* d_out, int out_size) {
    const float* s       = (const float*)d_in[0];
    const float* z       = (const float*)d_in[1];
    const float* r_rot   = (const float*)d_in[2];
    const float* r_trans = (const float*)d_in[3];
    const float* mask    = (const float*)d_in[4];
    const float* wq      = (const float*)d_in[5];
    const float* bq      = (const float*)d_in[6];
    const float* wkv     = (const float*)d_in[7];
    const float* bkv     = (const float*)d_in[8];
    const float* wqp     = (const float*)d_in[9];
    const float* bqp     = (const float*)d_in[10];
    const float* wkvp    = (const float*)d_in[11];
    const float* bkvp    = (const float*)d_in[12];
    const float* wb      = (const float*)d_in[13];
    const float* head_w  = (const float*)d_in[15];
    const float* wout    = (const float*)d_in[16];
    const float* bout    = (const float*)d_in[17];
    const float* wexp    = (const float*)d_in[18];
    const float* bexp    = (const float*)d_in[19];
    const float* ln_g    = (const float*)d_in[20];
    const float* ln_b    = (const float*)d_in[21];
    float* out = (float*)d_out;

    float *p_se = nullptr, *p_cat = nullptr, *p_part = nullptr;
    cudaGetSymbolAddress((void**)&p_se,   g_se);
    cudaGetSymbolAddress((void**)&p_cat,  g_cat);
    cudaGetSymbolAddress((void**)&p_part, g_part);

    static int attn_cfg = 0;
    if (!attn_cfg) {
        cudaFuncSetAttribute(k_zattn, cudaFuncAttributeMaxDynamicSharedMemorySize, ZAT_SMEM);
        cudaFuncSetAttribute(k_ov, cudaFuncAttributeMaxDynamicSharedMemorySize, OV_SMEM);
        attn_cfg = 1;
    }

    k_gemm64<<<dim3(6, 12, 1), 256>>>(s, wexp, bexp, p_se, 384, 384, 24, 1, 0);
    k_ln<<<768, 128>>>(ln_g, ln_b);
    k_gemm_proj<<<dim3(18, 12), 256>>>(wq, bq, wkv, bkv, wqp, bqp, wkvp, bkvp);
    k_assemble<<<96, 256>>>(r_rot, r_trans, head_w);
    k_qk<<<dim3(12, 12, 12), 256>>>(mask);
    k_zattn<<<384, 256, ZAT_SMEM>>>(z, wb);
    k_ov<<<dim3(12, 12), 256, OV_SMEM>>>(r_rot, r_trans);
    k_gemm64<<<dim3(6, 12, 2), 256>>>(p_cat, wout, nullptr, p_part, 2112, 384, 66, 0, NRES * CSD);
    k_combine<<<1152, 256>>>(bout, out);
}

// round 12
// speedup vs baseline: 1.1535x; 1.0792x over previous
#include <cuda_runtime.h>
#include <math.h>

#define NRES 768
#define CSD  384
#define CZD  128
#define NHD  12
#define INF_ 100000.0f

typedef unsigned long long u64;

// ---------------- packed f32x2 helpers ----------------
__device__ __forceinline__ void ffma2(u64& d, u64 a, u64 b) {
    asm("fma.rn.f32x2 %0, %1, %2, %0;" : "+l"(d) : "l"(a), "l"(b));
}
__device__ __forceinline__ u64 dup2(float x) {
    u64 r; asm("mov.b64 %0, {%1, %1};" : "=l"(r) : "f"(x)); return r;
}
__device__ __forceinline__ u64 pk2(float lo, float hi) {
    u64 r; asm("mov.b64 %0, {%1, %2};" : "=l"(r) : "f"(lo), "f"(hi)); return r;
}
__device__ __forceinline__ float2 up2(u64 v) {
    float lo, hi; asm("mov.b64 {%0, %1}, %2;" : "=f"(lo), "=f"(hi) : "l"(v));
    return make_float2(lo, hi);
}
// ---------------- cp.async helpers ----------------
__device__ __forceinline__ void cpa16(void* dst, const void* src) {
    unsigned sdst = (unsigned)__cvta_generic_to_shared(dst);
    asm volatile("cp.async.cg.shared.global [%0], [%1], 16;" :: "r"(sdst), "l"(src));
}
__device__ __forceinline__ void cpa_commit() { asm volatile("cp.async.commit_group;"); }
__device__ __forceinline__ void cpa_wait1() { asm volatile("cp.async.wait_group 1;"); }
__device__ __forceinline__ void cpa_wait0() { asm volatile("cp.async.wait_group 0;"); }

// ---------------- scratch (device globals; no allocation) ----------------
__device__ float g_se[NRES * CSD];
__device__ float g_proj[NRES * 1152];
__device__ float g_qhat[NRES * 336];
__device__ float g_khat[NRES * 336];
__device__ float g_kc[NRES * NHD];
__device__ float g_vall[NRES * NHD * 40];
__device__ float g_cat[NRES * 2112];
__device__ float g_part[4][NRES * CSD];
__device__ float g_logits[NHD * NRES * NRES]; // [i][h][j]: qk-logits, then unnormalized exp
__device__ float g_Sinv[NRES * NHD];          // 1/S per (i,h)

// =====================================================================
// fp32 GEMM with FFMA2: C = A(MxK) @ W(NxK)^T [+ bias]; 64x64 tile, BK=16.
// =====================================================================
__device__ __forceinline__ void mm16(const float* Ab, const float* Wb,
                                     int ty, int tx, u64 acc2[4][2]) {
    #pragma unroll
    for (int k = 0; k < 16; k++) {
        float4 av = *(const float4*)(Ab + k * 68 + ty * 4);
        ulonglong2 wv = *(const ulonglong2*)(Wb + k * 68 + tx * 4);
        u64 a0 = dup2(av.x), a1 = dup2(av.y), a2 = dup2(av.z), a3 = dup2(av.w);
        ffma2(acc2[0][0], a0, wv.x); ffma2(acc2[0][1], a0, wv.y);
        ffma2(acc2[1][0], a1, wv.x); ffma2(acc2[1][1], a1, wv.y);
        ffma2(acc2[2][0], a2, wv.x); ffma2(acc2[2][1], a2, wv.y);
        ffma2(acc2[3][0], a3, wv.x); ffma2(acc2[3][1], a3, wv.y);
    }
}

__global__ __launch_bounds__(256) void k_gemm64(
    const float* __restrict__ A, const float* __restrict__ W,
    const float* __restrict__ bias, float* __restrict__ C,
    int ld, int ldc, int nkt, int add_bias, int partStride)
{
    __shared__ __align__(16) float As[2][16][68];
    __shared__ __align__(16) float Ws[2][16][68];
    int t  = threadIdx.x;
    int m0 = blockIdx.y * 64, n0 = blockIdx.x * 64;
    int kt0 = blockIdx.z * nkt;
    C += (size_t)blockIdx.z * partStride;
    int lr = t >> 2, lk = (t & 3) * 4;
    const float* arow = A + (size_t)(m0 + lr) * ld + kt0 * 16 + lk;
    const float* wrow = W + (size_t)(n0 + lr) * ld + kt0 * 16 + lk;
    int tx = t & 15, ty = t >> 4;

    u64 acc2[4][2] = {};
    float4 ra = *(const float4*)arow;
    float4 rw = *(const float4*)wrow;
    int buf = 0;
    As[0][lk+0][lr]=ra.x; As[0][lk+1][lr]=ra.y; As[0][lk+2][lr]=ra.z; As[0][lk+3][lr]=ra.w;
    Ws[0][lk+0][lr]=rw.x; Ws[0][lk+1][lr]=rw.y; Ws[0][lk+2][lr]=rw.z; Ws[0][lk+3][lr]=rw.w;

    for (int kt = 0; kt < nkt - 1; kt++) {
        __syncthreads();
        ra = *(const float4*)(arow + (kt + 1) * 16);
        rw = *(const float4*)(wrow + (kt + 1) * 16);
        mm16(&As[buf][0][0], &Ws[buf][0][0], ty, tx, acc2);
        int nb = buf ^ 1;
        As[nb][lk+0][lr]=ra.x; As[nb][lk+1][lr]=ra.y; As[nb][lk+2][lr]=ra.z; As[nb][lk+3][lr]=ra.w;
        Ws[nb][lk+0][lr]=rw.x; Ws[nb][lk+1][lr]=rw.y; Ws[nb][lk+2][lr]=rw.z; Ws[nb][lk+3][lr]=rw.w;
        buf = nb;
    }
    __syncthreads();
    mm16(&As[buf][0][0], &Ws[buf][0][0], ty, tx, acc2);

    float4 bv = make_float4(0.f, 0.f, 0.f, 0.f);
    if (add_bias) bv = *(const float4*)(bias + n0 + tx * 4);
    #pragma unroll
    for (int a = 0; a < 4; a++) {
        float2 p0 = up2(acc2[a][0]), p1 = up2(acc2[a][1]);
        float4 r = make_float4(p0.x + bv.x, p0.y + bv.y, p1.x + bv.z, p1.y + bv.w);
        *(float4*)(C + (size_t)(m0 + ty * 4 + a) * ldc + n0 + tx * 4) = r;
    }
}

__device__ __forceinline__ float proj_bias(int n, const float* bq, const float* bkv,
                                           const float* bqp, const float* bkvp) {
    if (n < 192) return bq[n];
    if (n < 576) return bkv[n - 192];
    if (n < 720) return bqp[n - 576];
    return bkvp[n - 720];
}

__global__ __launch_bounds__(256) void k_gemm_proj(
    const float* __restrict__ wq,  const float* __restrict__ bq,
    const float* __restrict__ wkv, const float* __restrict__ bkv,
    const float* __restrict__ wqp, const float* __restrict__ bqp,
    const float* __restrict__ wkvp,const float* __restrict__ bkvp)
{
    __shared__ __align__(16) float As[2][16][68];
    __shared__ __align__(16) float Ws[2][16][68];
    int t  = threadIdx.x;
    int m0 = blockIdx.y * 64, n0 = blockIdx.x * 64;
    int lr = t >> 2, lk = (t & 3) * 4;
    const float* arow = g_se + (size_t)(m0 + lr) * 384 + lk;
    int n = n0 + lr;
    const float* wbase; int nl;
    if      (n < 192) { wbase = wq;   nl = n; }
    else if (n < 576) { wbase = wkv;  nl = n - 192; }
    else if (n < 720) { wbase = wqp;  nl = n - 576; }
    else              { wbase = wkvp; nl = n - 720; }
    const float* wrow = wbase + (size_t)nl * 384 + lk;
    int tx = t & 15, ty = t >> 4;

    u64 acc2[4][2] = {};
    float4 ra = *(const float4*)arow;
    float4 rw = *(const float4*)wrow;
    int buf = 0;
    As[0][lk+0][lr]=ra.x; As[0][lk+1][lr]=ra.y; As[0][lk+2][lr]=ra.z; As[0][lk+3][lr]=ra.w;
    Ws[0][lk+0][lr]=rw.x; Ws[0][lk+1][lr]=rw.y; Ws[0][lk+2][lr]=rw.z; Ws[0][lk+3][lr]=rw.w;

    const int nkt = 24;
    for (int kt = 0; kt < nkt - 1; kt++) {
        __syncthreads();
        ra = *(const float4*)(arow + (kt + 1) * 16);
        rw = *(const float4*)(wrow + (kt + 1) * 16);
        mm16(&As[buf][0][0], &Ws[buf][0][0], ty, tx, acc2);
        int nb = buf ^ 1;
        As[nb][lk+0][lr]=ra.x; As[nb][lk+1][lr]=ra.y; As[nb][lk+2][lr]=ra.z; As[nb][lk+3][lr]=ra.w;
        Ws[nb][lk+0][lr]=rw.x; Ws[nb][lk+1][lr]=rw.y; Ws[nb][lk+2][lr]=rw.z; Ws[nb][lk+3][lr]=rw.w;
        buf = nb;
    }
    __syncthreads();
    mm16(&As[buf][0][0], &Ws[buf][0][0], ty, tx, acc2);

    int nc = n0 + tx * 4;
    float4 bv = make_float4(proj_bias(nc + 0, bq, bkv, bqp, bkvp),
                            proj_bias(nc + 1, bq, bkv, bqp, bkvp),
                            proj_bias(nc + 2, bq, bkv, bqp, bkvp),
                            proj_bias(nc + 3, bq, bkv, bqp, bkvp));
    #pragma unroll
    for (int a = 0; a < 4; a++) {
        float2 p0 = up2(acc2[a][0]), p1 = up2(acc2[a][1]);
        float4 r = make_float4(p0.x + bv.x, p0.y + bv.y, p1.x + bv.z, p1.y + bv.w);
        *(float4*)(g_proj + (size_t)(m0 + ty * 4 + a) * 1152 + nc) = r;
    }
}

__global__ void k_combine(const float* __restrict__ bout, float* __restrict__ out) {
    int i = blockIdx.x * 256 + threadIdx.x;
    out[i] = g_part[0][i] + g_part[1][i] + g_part[2][i] + g_part[3][i] + bout[i % 384];
}

// ---------------- LayerNorm ----------------
__global__ void k_ln(const float* __restrict__ gamma, const float* __restrict__ beta) {
    int n = blockIdx.x, t = threadIdx.x;
    float* row = g_se + (size_t)n * CSD;
    float x0 = row[t], x1 = row[t + 128], x2 = row[t + 256];
    float s1 = x0 + x1 + x2;
    float s2 = x0 * x0 + x1 * x1 + x2 * x2;
    __shared__ float r1[4], r2[4];
    #pragma unroll
    for (int o = 16; o; o >>= 1) {
        s1 += __shfl_xor_sync(0xffffffffu, s1, o);
        s2 += __shfl_xor_sync(0xffffffffu, s2, o);
    }
    if ((t & 31) == 0) { r1[t >> 5] = s1; r2[t >> 5] = s2; }
    __syncthreads();
    float ts1 = r1[0] + r1[1] + r1[2] + r1[3];
    float ts2 = r2[0] + r2[1] + r2[2] + r2[3];
    float mu  = ts1 * (1.f / 384.f);
    float var = ts2 * (1.f / 384.f) - mu * mu;
    float inv = rsqrtf(var + 1e-5f);
    row[t]       = (x0 - mu) * inv * gamma[t]       + beta[t];
    row[t + 128] = (x1 - mu) * inv * gamma[t + 128] + beta[t + 128];
    row[t + 256] = (x2 - mu) * inv * gamma[t + 256] + beta[t + 256];
}

// ---------------- assemble qhat/khat/kc/v/v_pts (warp per n) ----------------
__global__ void k_assemble(const float* __restrict__ r_rot, const float* __restrict__ r_trans,
                           const float* __restrict__ head_w) {
    int gw   = blockIdx.x * 8 + (threadIdx.x >> 5);
    int lane = threadIdx.x & 31;
    if (gw >= NRES || lane >= NHD) return;
    int n = gw, h = lane;
    float rot[9], t0[3];
    #pragma unroll
    for (int i = 0; i < 9; i++) rot[i] = r_rot[n * 45 + i];
    #pragma unroll
    for (int i = 0; i < 3; i++) t0[i] = r_trans[n * 15 + i];
    float hw = log1pf(expf(head_w[h])) * rsqrtf(54.0f);
    const float c1 = rsqrtf(48.0f);
    const float* P = g_proj + (size_t)n * 1152;
    float* qh = g_qhat + (size_t)n * 336 + h * 28;
    float* kh = g_khat + (size_t)n * 336 + h * 28;
    float* va = g_vall + ((size_t)n * NHD + h) * 40;
    #pragma unroll
    for (int c = 0; c < 16; c++) {
        qh[c] = c1 * P[h * 16 + c];
        kh[c] = P[192 + h * 32 + c];
        va[c] = P[192 + h * 32 + 16 + c];
    }
    #pragma unroll
    for (int pp = 0; pp < 4; pp++) {
        float l0 = P[576 +   0 + h * 4 + pp];
        float l1 = P[576 +  48 + h * 4 + pp];
        float l2 = P[576 +  96 + h * 4 + pp];
        #pragma unroll
        for (int i = 0; i < 3; i++) {
            float o = rot[i * 3] * l0 + rot[i * 3 + 1] * l1 + rot[i * 3 + 2] * l2 + t0[i];
            qh[16 + pp * 3 + i] = hw * o;
        }
    }
    float kc = 0.f;
    #pragma unroll
    for (int pp = 0; pp < 4; pp++) {
        float l0 = P[720 +   0 + h * 12 + pp];
        float l1 = P[720 + 144 + h * 12 + pp];
        float l2 = P[720 + 288 + h * 12 + pp];
        #pragma unroll
        for (int i = 0; i < 3; i++) {
            float o = rot[i * 3] * l0 + rot[i * 3 + 1] * l1 + rot[i * 3 + 2] * l2 + t0[i];
            kh[16 + pp * 3 + i] = o;
            kc += o * o;
        }
    }
    g_kc[n * NHD + h] = -0.5f * hw * kc;
    #pragma unroll
    for (int pv = 0; pv < 8; pv++) {
        int pp = 4 + pv;
        float l0 = P[720 +   0 + h * 12 + pp];
        float l1 = P[720 + 144 + h * 12 + pp];
        float l2 = P[720 + 288 + h * 12 + pp];
        #pragma unroll
        for (int i = 0; i < 3; i++) {
            float o = rot[i * 3] * l0 + rot[i * 3 + 1] * l1 + rot[i * 3 + 2] * l2 + t0[i];
            va[16 + pv * 3 + i] = o;
        }
    }
}

// ---------------- qk logits (K=28 GEMM) + kc + mask per head ----------------
__global__ __launch_bounds__(256) void k_qk(const float* __restrict__ mask) {
    __shared__ __align__(16) float Qs[28][68];
    __shared__ __align__(16) float Ks[28][68];
    __shared__ float kcs[64], uli[64], ulj[64];
    int h = blockIdx.z, i0 = blockIdx.y * 64, j0 = blockIdx.x * 64;
    int t = threadIdx.x;
    for (int idx = t; idx < 64 * 28; idx += 256) {
        int m = idx / 28, k = idx % 28;
        Qs[k][m] = g_qhat[(size_t)(i0 + m) * 336 + h * 28 + k];
        Ks[k][m] = g_khat[(size_t)(j0 + m) * 336 + h * 28 + k];
    }
    if (t < 64) {
        kcs[t] = g_kc[(j0 + t) * NHD + h];
        uli[t] = mask[(i0 + t) * 5];
        ulj[t] = mask[(j0 + t) * 5];
    }
    __syncthreads();
    int tx = t & 15, ty = t >> 4;
    u64 acc2[4][2] = {};
    #pragma unroll
    for (int k = 0; k < 28; k++) {
        float4 av = *(const float4*)(&Qs[k][ty * 4]);
        ulonglong2 wv = *(const ulonglong2*)(&Ks[k][tx * 4]);
        u64 a0 = dup2(av.x), a1 = dup2(av.y), a2 = dup2(av.z), a3 = dup2(av.w);
        ffma2(acc2[0][0], a0, wv.x); ffma2(acc2[0][1], a0, wv.y);
        ffma2(acc2[1][0], a1, wv.x); ffma2(acc2[1][1], a1, wv.y);
        ffma2(acc2[2][0], a2, wv.x); ffma2(acc2[2][1], a2, wv.y);
        ffma2(acc2[3][0], a3, wv.x); ffma2(acc2[3][1], a3, wv.y);
    }
    int jb = tx * 4;
    #pragma unroll
    for (int a = 0; a < 4; a++) {
        int i = i0 + ty * 4 + a;
        float mi = uli[ty * 4 + a];
        float2 p0 = up2(acc2[a][0]), p1 = up2(acc2[a][1]);
        float4 r;
        r.x = p0.x + kcs[jb + 0] + INF_ * (mi * ulj[jb + 0] - 1.f);
        r.y = p0.y + kcs[jb + 1] + INF_ * (mi * ulj[jb + 1] - 1.f);
        r.z = p1.x + kcs[jb + 2] + INF_ * (mi * ulj[jb + 2] - 1.f);
        r.w = p1.y + kcs[jb + 3] + INF_ * (mi * ulj[jb + 3] - 1.f);
        *(float4*)(&g_logits[((size_t)i * NHD + h) * NRES + j0 + jb]) = r;
    }
}

// ---------------- persistent fused z-pass per i: bias + exp + S + o_pair ----
// One block per i; 12 j-tiles of 64 rows, cp.async double-buffered.
// 87KB smem -> 2 CTA/SM for sync-bubble overlap.
#define ZT_STRIDE 132
#define ZTILE (64 * ZT_STRIDE)
#define ZAT_ES   (2 * ZTILE * 4)                 // 67584
#define ZAT_WB2  (ZAT_ES + 64 * 12 * 4)          // 70656
#define ZAT_PH   (ZAT_WB2 + 128 * 6 * 8)         // 76800
#define ZAT_SS   (ZAT_PH + 256 * 6 * 8)          // 89088
#define ZAT_SMEM (ZAT_SS + 64)                   // 89152

__global__ __launch_bounds__(256) void k_zattn(const float* __restrict__ z,
                                               const float* __restrict__ wb) {
    extern __shared__ __align__(16) unsigned char smraw[];
    float* zs  = (float*)smraw;
    float* es  = (float*)(smraw + ZAT_ES);
    u64*   wb2 = (u64*)(smraw + ZAT_WB2);
    u64*   ph  = (u64*)(smraw + ZAT_PH);
    float* Ssum= (float*)(smraw + ZAT_SS);

    int i = blockIdx.x;
    int t = threadIdx.x;
    int lane = t & 31, warp = t >> 5;
    const float c2 = 0.57735026918962576f;  // sqrt(1/3)

    for (int e = t; e < 768; e += 256) {
        int c = e / 6, p = e % 6;
        wb2[e] = pk2(c2 * wb[(2 * p) * 128 + c], c2 * wb[(2 * p + 1) * 128 + c]);
    }

    const float4* zbase = (const float4*)(z + (size_t)i * NRES * CZD);
    // prologue: prefetch tile 0 (64 rows x 32 float4 = 2048)
    #pragma unroll
    for (int l = 0; l < 8; l++) {
        int idx = t + l * 256;
        cpa16(zs + (idx >> 5) * ZT_STRIDE + (idx & 31) * 4, zbase + idx);
    }
    cpa_commit();

    u64 accO[6] = {};
    float sacc[2] = {0.f, 0.f};
    int buf = 0;

    for (int jt = 0; jt < 12; jt++) {
        __syncthreads();  // closes previous tile's phase-2 reads of buf^1
        if (jt < 11) {
            float* zb = zs + (buf ^ 1) * ZTILE;
            const float4* zrow = zbase + (jt + 1) * 2048;
            #pragma unroll
            for (int l = 0; l < 8; l++) {
                int idx = t + l * 256;
                cpa16(zb + (idx >> 5) * ZT_STRIDE + (idx & 31) * 4, zrow + idx);
            }
            cpa_commit();
            cpa_wait1();
        } else {
            cpa_wait0();
        }
        __syncthreads();
        const float* zt = zs + buf * ZTILE;

        // phase 1: quarter-row z.wb dots (j = t&63, q = t>>6)
        {
            int j = t & 63, q = t >> 6;
            const float* zj = zt + j * ZT_STRIDE + q * 32;
            u64 acc[6] = {};
            #pragma unroll
            for (int c4 = 0; c4 < 8; c4++) {
                float4 v = *(const float4*)(zj + c4 * 4);
                int cb = (q * 32 + c4 * 4) * 6;
                u64 z0 = dup2(v.x), z1 = dup2(v.y), z2 = dup2(v.z), z3 = dup2(v.w);
                {
                    ulonglong2 wA = *(const ulonglong2*)(wb2 + cb);
                    ulonglong2 wB = *(const ulonglong2*)(wb2 + cb + 2);
                    ulonglong2 wC = *(const ulonglong2*)(wb2 + cb + 4);
                    ffma2(acc[0], z0, wA.x); ffma2(acc[1], z0, wA.y);
                    ffma2(acc[2], z0, wB.x); ffma2(acc[3], z0, wB.y);
                    ffma2(acc[4], z0, wC.x); ffma2(acc[5], z0, wC.y);
                }
                {
                    ulonglong2 wA = *(const ulonglong2*)(wb2 + cb + 6);
                    ulonglong2 wB = *(const ulonglong2*)(wb2 + cb + 8);
                    ulonglong2 wC = *(const ulonglong2*)(wb2 + cb + 10);
                    ffma2(acc[0], z1, wA.x); ffma2(acc[1], z1, wA.y);
                    ffma2(acc[2], z1, wB.x); ffma2(acc[3], z1, wB.y);
                    ffma2(acc[4], z1, wC.x); ffma2(acc[5], z1, wC.y);
                }
                {
                    ulonglong2 wA = *(const ulonglong2*)(wb2 + cb + 12);
                    ulonglong2 wB = *(const ulonglong2*)(wb2 + cb + 14);
                    ulonglong2 wC = *(const ulonglong2*)(wb2 + cb + 16);
                    ffma2(acc[0], z2, wA.x); ffma2(acc[1], z2, wA.y);
                    ffma2(acc[2], z2, wB.x); ffma2(acc[3], z2, wB.y);
                    ffma2(acc[4], z2, wC.x); ffma2(acc[5], z2, wC.y);
                }
                {
                    ulonglong2 wA = *(const ulonglong2*)(wb2 + cb + 18);
                    ulonglong2 wB = *(const ulonglong2*)(wb2 + cb + 20);
                    ulonglong2 wC = *(const ulonglong2*)(wb2 + cb + 22);
                    ffma2(acc[0], z3, wA.x); ffma2(acc[1], z3, wA.y);
                    ffma2(acc[2], z3, wB.x); ffma2(acc[3], z3, wB.y);
                    ffma2(acc[4], z3, wC.x); ffma2(acc[5], z3, wC.y);
                }
            }
            #pragma unroll
            for (int p = 0; p < 6; p++) ph[t * 6 + p] = acc[p];
        }
        __syncthreads();

        // combine 4 quarters + qk logits + exp (unnormalized)
        if (t < 64) {
            int j = t, j0 = jt * 64;
            #pragma unroll
            for (int p = 0; p < 6; p++) {
                float2 s0 = up2(ph[(t) * 6 + p]);
                float2 s1 = up2(ph[(t + 64) * 6 + p]);
                float2 s2 = up2(ph[(t + 128) * 6 + p]);
                float2 s3 = up2(ph[(t + 192) * 6 + p]);
                float sx = s0.x + s1.x + s2.x + s3.x;
                float sy = s0.y + s1.y + s2.y + s3.y;
                int h0 = 2 * p, h1 = 2 * p + 1;
                size_t gi0 = ((size_t)i * NHD + h0) * NRES + j0 + j;
                size_t gi1 = ((size_t)i * NHD + h1) * NRES + j0 + j;
                float e0 = __expf(g_logits[gi0] + sx);
                float e1 = __expf(g_logits[gi1] + sy);
                g_logits[gi0] = e0; g_logits[gi1] = e1;
                es[j * 12 + h0] = e0; es[j * 12 + h1] = e1;
            }
        }
        __syncthreads();

        // partial S per head (register accumulation across tiles)
        {
            int cnt = 0;
            for (int h = warp; h < NHD; h += 8, cnt++) {
                float s = es[lane * 12 + h] + es[(lane + 32) * 12 + h];
                #pragma unroll
                for (int o = 16; o; o >>= 1) s += __shfl_xor_sync(0xffffffffu, s, o);
                sacc[cnt] += s;
            }
        }

        // phase 2: accumulate o_pair partials in registers
        {
            int c = t & 127, g = t >> 7;
            #pragma unroll 4
            for (int jj = 0; jj < 32; jj++) {
                int j = g * 32 + jj;
                u64 zd = dup2(zt[j * ZT_STRIDE + c]);
                const ulonglong2* aj = (const ulonglong2*)(es + j * 12);
                ulonglong2 a0 = aj[0], a1 = aj[1], a2 = aj[2];
                ffma2(accO[0], zd, a0.x); ffma2(accO[1], zd, a0.y);
                ffma2(accO[2], zd, a1.x); ffma2(accO[3], zd, a1.y);
                ffma2(accO[4], zd, a2.x); ffma2(accO[5], zd, a2.y);
            }
        }
        buf ^= 1;
    }

    // finalize S
    if (lane == 0) {
        int cnt = 0;
        for (int h = warp; h < NHD; h += 8, cnt++) Ssum[h] = sacc[cnt];
    }
    __syncthreads();
    if (t < NHD) {
        float inv = 1.0f / Ssum[t];
        Ssum[t] = inv;
        g_Sinv[i * NHD + t] = inv;
    }
    __syncthreads();

    // reduce o_pair halves, normalize, write
    {
        float* red = zs;
        int c = t & 127, g = t >> 7;
        #pragma unroll
        for (int p = 0; p < 6; p++) {
            float2 v = up2(accO[p]);
            red[(g * 12 + 2 * p) * 128 + c]     = v.x;
            red[(g * 12 + 2 * p + 1) * 128 + c] = v.y;
        }
        __syncthreads();
        for (int e = t; e < 1536; e += 256)
            g_cat[(size_t)i * 2112 + 576 + e] = (red[e] + red[1536 + e]) * Ssum[e >> 7];
    }
}

// ---------------- o = (e@v)/S, o_pt = inv-frame((e@v_pts)/S) fused ----------
#define OV_AT   0
#define OV_VS   17408
#define OV_RED  27648
#define OV_OPT  48128
#define OV_SMEM 54272

__global__ __launch_bounds__(256) void k_ov(const float* __restrict__ r_rot,
                                            const float* __restrict__ r_trans) {
    extern __shared__ __align__(16) unsigned char sm[];
    float* a_t  = (float*)(sm + OV_AT);    // [k][r] 64x68
    float* v_s  = (float*)(sm + OV_VS);    // [k][c] 64x40
    u64*   red  = (u64*)(sm + OV_RED);     // 128x20
    float* opts = (float*)(sm + OV_OPT);   // [r][24]
    int i0 = blockIdx.x * 64;
    int h  = blockIdx.y;
    int t  = threadIdx.x;
    int rq = t & 15, cq = (t >> 4) & 3, ks = t >> 6;
    u64 acc[4][5] = {};
    for (int jt = 0; jt < 12; jt++) {
        #pragma unroll
        for (int l = 0; l < 16; l++) {
            int idx = t + l * 256;
            int r = idx >> 6, k = idx & 63;
            a_t[k * 68 + r] = g_logits[((size_t)(i0 + r) * NHD + h) * NRES + jt * 64 + k];
        }
        #pragma unroll
        for (int l = 0; l < 10; l++) {
            int idx = t + l * 256;
            v_s[idx] = g_vall[((size_t)(jt * 64 + idx / 40) * NHD + h) * 40 + idx % 40];
        }
        __syncthreads();
        #pragma unroll
        for (int kk = 0; kk < 16; kk++) {
            int k = ks * 16 + kk;
            float4 av = *(const float4*)(a_t + k * 68 + rq * 4);
            const u64* vv = (const u64*)(v_s + k * 40 + cq * 10);
            u64 v0 = vv[0], v1 = vv[1], v2 = vv[2], v3 = vv[3], v4 = vv[4];
            u64 a0 = dup2(av.x), a1 = dup2(av.y), a2 = dup2(av.z), a3 = dup2(av.w);
            ffma2(acc[0][0], a0, v0); ffma2(acc[0][1], a0, v1); ffma2(acc[0][2], a0, v2);
            ffma2(acc[0][3], a0, v3); ffma2(acc[0][4], a0, v4);
            ffma2(acc[1][0], a1, v0); ffma2(acc[1][1], a1, v1); ffma2(acc[1][2], a1, v2);
            ffma2(acc[1][3], a1, v3); ffma2(acc[1][4], a1, v4);
            ffma2(acc[2][0], a2, v0); ffma2(acc[2][1], a2, v1); ffma2(acc[2][2], a2, v2);
            ffma2(acc[2][3], a2, v3); ffma2(acc[2][4], a2, v4);
            ffma2(acc[3][0], a3, v0); ffma2(acc[3][1], a3, v1); ffma2(acc[3][2], a3, v2);
            ffma2(acc[3][3], a3, v3); ffma2(acc[3][4], a3, v4);
        }
        __syncthreads();
    }
    int slot = t & 63;
    if (ks >= 2) {
        u64* dst = red + ((ks - 2) * 64 + slot) * 20;
        #pragma unroll
        for (int rr = 0; rr < 4; rr++)
            #pragma unroll
            for (int p = 0; p < 5; p++) dst[rr * 5 + p] = acc[rr][p];
    }
    __syncthreads();
    if (ks < 2) {
        const u64* src = red + (ks * 64 + slot) * 20;
        #pragma unroll
        for (int rr = 0; rr < 4; rr++)
            #pragma unroll
            for (int p = 0; p < 5; p++) {
                float2 a = up2(acc[rr][p]), b = up2(src[rr * 5 + p]);
                acc[rr][p] = pk2(a.x + b.x, a.y + b.y);
            }
    }
    __syncthreads();
    if (ks == 1) {
        u64* dst = red + slot * 20;
        #pragma unroll
        for (int rr = 0; rr < 4; rr++)
            #pragma unroll
            for (int p = 0; p < 5; p++) dst[rr * 5 + p] = acc[rr][p];
    }
    __syncthreads();
    if (ks == 0) {
        const u64* src = red + slot * 20;
        #pragma unroll
        for (int rr = 0; rr < 4; rr++) {
            int rl = rq * 4 + rr;
            float inv = g_Sinv[(i0 + rl) * NHD + h];
            #pragma unroll
            for (int p = 0; p < 5; p++) {
                float2 a = up2(acc[rr][p]), b = up2(src[rr * 5 + p]);
                float vx = (a.x + b.x) * inv, vy = (a.y + b.y) * inv;
                int c0 = cq * 10 + 2 * p;
                if (c0 < 16)     g_cat[(size_t)(i0 + rl) * 2112 + h * 16 + c0] = vx;
                else             opts[rl * 24 + (c0 - 16)] = vx;
                int c1 = c0 + 1;
                if (c1 < 16)     g_cat[(size_t)(i0 + rl) * 2112 + h * 16 + c1] = vy;
                else             opts[rl * 24 + (c1 - 16)] = vy;
            }
        }
    }
    __syncthreads();
    for (int e2 = t; e2 < 512; e2 += 256) {
        int rl = e2 >> 3, pv = e2 & 7;
        int n = i0 + rl;
        const float* pp = opts + rl * 24 + pv * 3;
        float d0 = pp[0] - r_trans[n * 15 + 0];
        float d1 = pp[1] - r_trans[n * 15 + 1];
        float d2 = pp[2] - r_trans[n * 15 + 2];
        const float* R = r_rot + n * 45;
        float o0 = R[0] * d0 + R[3] * d1 + R[6] * d2;
        float o1 = R[1] * d0 + R[4] * d1 + R[7] * d2;
        float o2 = R[2] * d0 + R[5] * d1 + R[8] * d2;
        float nm = sqrtf(o0 * o0 + o1 * o1 + o2 * o2 + 1e-8f);
        float* cb = g_cat + (size_t)n * 2112 + 192;
        int rr2 = h * 8 + pv;
        cb[rr2] = o0; cb[96 + rr2] = o1; cb[192 + rr2] = o2; cb[288 + rr2] = nm;
    }
}

// ---------------- launch ----------------
extern "C" void kernel_launch(void* const* d_in, const int* in_sizes, int n_in,
                              void* d_out, int out_size) {
    const float* s       = (const float*)d_in[0];
    const float* z       = (const float*)d_in[1];
    const float* r_rot   = (const float*)d_in[2];
    const float* r_trans = (const float*)d_in[3];
    const float* mask    = (const float*)d_in[4];
    const float* wq      = (const float*)d_in[5];
    const float* bq      = (const float*)d_in[6];
    const float* wkv     = (const float*)d_in[7];
    const float* bkv     = (const float*)d_in[8];
    const float* wqp     = (const float*)d_in[9];
    const float* bqp     = (const float*)d_in[10];
    const float* wkvp    = (const float*)d_in[11];
    const float* bkvp    = (const float*)d_in[12];
    const float* wb      = (const float*)d_in[13];
    const float* head_w  = (const float*)d_in[15];
    const float* wout    = (const float*)d_in[16];
    const float* bout    = (const float*)d_in[17];
    const float* wexp    = (const float*)d_in[18];
    const float* bexp    = (const float*)d_in[19];
    const float* ln_g    = (const float*)d_in[20];
    const float* ln_b    = (const float*)d_in[21];
    float* out = (float*)d_out;

    float *p_se = nullptr, *p_cat = nullptr, *p_part = nullptr;
    cudaGetSymbolAddress((void**)&p_se,   g_se);
    cudaGetSymbolAddress((void**)&p_cat,  g_cat);
    cudaGetSymbolAddress((void**)&p_part, g_part);

    static int attn_cfg = 0;
    if (!attn_cfg) {
        cudaFuncSetAttribute(k_zattn, cudaFuncAttributeMaxDynamicSharedMemorySize, ZAT_SMEM);
        cudaFuncSetAttribute(k_ov, cudaFuncAttributeMaxDynamicSharedMemorySize, OV_SMEM);
        attn_cfg = 1;
    }

    k_gemm64<<<dim3(6, 12, 1), 256>>>(s, wexp, bexp, p_se, 384, 384, 24, 1, 0);
    k_ln<<<768, 128>>>(ln_g, ln_b);
    k_gemm_proj<<<dim3(18, 12), 256>>>(wq, bq, wkv, bkv, wqp, bqp, wkvp, bkvp);
    k_assemble<<<96, 256>>>(r_rot, r_trans, head_w);
    k_qk<<<dim3(12, 12, 12), 256>>>(mask);
    k_zattn<<<768, 256, ZAT_SMEM>>>(z, wb);
    k_ov<<<dim3(12, 12), 256, OV_SMEM>>>(r_rot, r_trans);
    k_gemm64<<<dim3(6, 12, 4), 256>>>(p_cat, wout, nullptr, p_part, 2112, 384, 33, 0, NRES * CSD);
    k_combine<<<1152, 256>>>(bout, out);
}

// round 13
// speedup vs baseline: 1.2056x; 1.0451x over previous
#include <cuda_runtime.h>
#include <math.h>

#define NRES 768
#define CSD  384
#define CZD  128
#define NHD  12
#define INF_ 100000.0f

typedef unsigned long long u64;

// ---------------- packed f32x2 helpers ----------------
__device__ __forceinline__ void ffma2(u64& d, u64 a, u64 b) {
    asm("fma.rn.f32x2 %0, %1, %2, %0;" : "+l"(d) : "l"(a), "l"(b));
}
__device__ __forceinline__ u64 dup2(float x) {
    u64 r; asm("mov.b64 %0, {%1, %1};" : "=l"(r) : "f"(x)); return r;
}
__device__ __forceinline__ u64 pk2(float lo, float hi) {
    u64 r; asm("mov.b64 %0, {%1, %2};" : "=l"(r) : "f"(lo), "f"(hi)); return r;
}
__device__ __forceinline__ float2 up2(u64 v) {
    float lo, hi; asm("mov.b64 {%0, %1}, %2;" : "=f"(lo), "=f"(hi) : "l"(v));
    return make_float2(lo, hi);
}
// ---------------- cp.async helpers ----------------
__device__ __forceinline__ void cpa16(void* dst, const void* src) {
    unsigned sdst = (unsigned)__cvta_generic_to_shared(dst);
    asm volatile("cp.async.cg.shared.global [%0], [%1], 16;" :: "r"(sdst), "l"(src));
}
__device__ __forceinline__ void cpa_commit() { asm volatile("cp.async.commit_group;"); }
__device__ __forceinline__ void cpa_wait1() { asm volatile("cp.async.wait_group 1;"); }
__device__ __forceinline__ void cpa_wait0() { asm volatile("cp.async.wait_group 0;"); }

// ---------------- scratch (device globals; no allocation) ----------------
__device__ float g_se[NRES * CSD];
__device__ float g_proj[NRES * 1152];
__device__ float g_qhat[NRES * 336];
__device__ float g_khat[NRES * 336];
__device__ float g_kc[NRES * NHD];
__device__ float g_vall[NRES * NHD * 40];
__device__ float g_cat[NRES * 2112];
__device__ float g_part[4][NRES * CSD];
__device__ float g_logits[NHD * NRES * NRES]; // [i][h][j]: qk-logits, then unnormalized exp
__device__ float g_Sinv[NRES * NHD];          // 1/S per (i,h)

// =====================================================================
// fp32 GEMM with FFMA2: C = A(MxK) @ W(NxK)^T [+ bias]; 64x64 tile, BK=16.
// =====================================================================
__device__ __forceinline__ void mm16(const float* Ab, const float* Wb,
                                     int ty, int tx, u64 acc2[4][2]) {
    #pragma unroll
    for (int k = 0; k < 16; k++) {
        float4 av = *(const float4*)(Ab + k * 68 + ty * 4);
        ulonglong2 wv = *(const ulonglong2*)(Wb + k * 68 + tx * 4);
        u64 a0 = dup2(av.x), a1 = dup2(av.y), a2 = dup2(av.z), a3 = dup2(av.w);
        ffma2(acc2[0][0], a0, wv.x); ffma2(acc2[0][1], a0, wv.y);
        ffma2(acc2[1][0], a1, wv.x); ffma2(acc2[1][1], a1, wv.y);
        ffma2(acc2[2][0], a2, wv.x); ffma2(acc2[2][1], a2, wv.y);
        ffma2(acc2[3][0], a3, wv.x); ffma2(acc2[3][1], a3, wv.y);
    }
}

__global__ __launch_bounds__(256) void k_gemm64(
    const float* __restrict__ A, const float* __restrict__ W,
    const float* __restrict__ bias, float* __restrict__ C,
    int ld, int ldc, int nkt, int add_bias, int partStride)
{
    __shared__ __align__(16) float As[2][16][68];
    __shared__ __align__(16) float Ws[2][16][68];
    int t  = threadIdx.x;
    int m0 = blockIdx.y * 64, n0 = blockIdx.x * 64;
    int kt0 = blockIdx.z * nkt;
    C += (size_t)blockIdx.z * partStride;
    int lr = t >> 2, lk = (t & 3) * 4;
    const float* arow = A + (size_t)(m0 + lr) * ld + kt0 * 16 + lk;
    const float* wrow = W + (size_t)(n0 + lr) * ld + kt0 * 16 + lk;
    int tx = t & 15, ty = t >> 4;

    u64 acc2[4][2] = {};
    float4 ra = *(const float4*)arow;
    float4 rw = *(const float4*)wrow;
    int buf = 0;
    As[0][lk+0][lr]=ra.x; As[0][lk+1][lr]=ra.y; As[0][lk+2][lr]=ra.z; As[0][lk+3][lr]=ra.w;
    Ws[0][lk+0][lr]=rw.x; Ws[0][lk+1][lr]=rw.y; Ws[0][lk+2][lr]=rw.z; Ws[0][lk+3][lr]=rw.w;

    for (int kt = 0; kt < nkt - 1; kt++) {
        __syncthreads();
        ra = *(const float4*)(arow + (kt + 1) * 16);
        rw = *(const float4*)(wrow + (kt + 1) * 16);
        mm16(&As[buf][0][0], &Ws[buf][0][0], ty, tx, acc2);
        int nb = buf ^ 1;
        As[nb][lk+0][lr]=ra.x; As[nb][lk+1][lr]=ra.y; As[nb][lk+2][lr]=ra.z; As[nb][lk+3][lr]=ra.w;
        Ws[nb][lk+0][lr]=rw.x; Ws[nb][lk+1][lr]=rw.y; Ws[nb][lk+2][lr]=rw.z; Ws[nb][lk+3][lr]=rw.w;
        buf = nb;
    }
    __syncthreads();
    mm16(&As[buf][0][0], &Ws[buf][0][0], ty, tx, acc2);

    float4 bv = make_float4(0.f, 0.f, 0.f, 0.f);
    if (add_bias) bv = *(const float4*)(bias + n0 + tx * 4);
    #pragma unroll
    for (int a = 0; a < 4; a++) {
        float2 p0 = up2(acc2[a][0]), p1 = up2(acc2[a][1]);
        float4 r = make_float4(p0.x + bv.x, p0.y + bv.y, p1.x + bv.z, p1.y + bv.w);
        *(float4*)(C + (size_t)(m0 + ty * 4 + a) * ldc + n0 + tx * 4) = r;
    }
}

__device__ __forceinline__ float proj_bias(int n, const float* bq, const float* bkv,
                                           const float* bqp, const float* bkvp) {
    if (n < 192) return bq[n];
    if (n < 576) return bkv[n - 192];
    if (n < 720) return bqp[n - 576];
    return bkvp[n - 720];
}

__global__ __launch_bounds__(256) void k_gemm_proj(
    const float* __restrict__ wq,  const float* __restrict__ bq,
    const float* __restrict__ wkv, const float* __restrict__ bkv,
    const float* __restrict__ wqp, const float* __restrict__ bqp,
    const float* __restrict__ wkvp,const float* __restrict__ bkvp)
{
    __shared__ __align__(16) float As[2][16][68];
    __shared__ __align__(16) float Ws[2][16][68];
    int t  = threadIdx.x;
    int m0 = blockIdx.y * 64, n0 = blockIdx.x * 64;
    int lr = t >> 2, lk = (t & 3) * 4;
    const float* arow = g_se + (size_t)(m0 + lr) * 384 + lk;
    int n = n0 + lr;
    const float* wbase; int nl;
    if      (n < 192) { wbase = wq;   nl = n; }
    else if (n < 576) { wbase = wkv;  nl = n - 192; }
    else if (n < 720) { wbase = wqp;  nl = n - 576; }
    else              { wbase = wkvp; nl = n - 720; }
    const float* wrow = wbase + (size_t)nl * 384 + lk;
    int tx = t & 15, ty = t >> 4;

    u64 acc2[4][2] = {};
    float4 ra = *(const float4*)arow;
    float4 rw = *(const float4*)wrow;
    int buf = 0;
    As[0][lk+0][lr]=ra.x; As[0][lk+1][lr]=ra.y; As[0][lk+2][lr]=ra.z; As[0][lk+3][lr]=ra.w;
    Ws[0][lk+0][lr]=rw.x; Ws[0][lk+1][lr]=rw.y; Ws[0][lk+2][lr]=rw.z; Ws[0][lk+3][lr]=rw.w;

    const int nkt = 24;
    for (int kt = 0; kt < nkt - 1; kt++) {
        __syncthreads();
        ra = *(const float4*)(arow + (kt + 1) * 16);
        rw = *(const float4*)(wrow + (kt + 1) * 16);
        mm16(&As[buf][0][0], &Ws[buf][0][0], ty, tx, acc2);
        int nb = buf ^ 1;
        As[nb][lk+0][lr]=ra.x; As[nb][lk+1][lr]=ra.y; As[nb][lk+2][lr]=ra.z; As[nb][lk+3][lr]=ra.w;
        Ws[nb][lk+0][lr]=rw.x; Ws[nb][lk+1][lr]=rw.y; Ws[nb][lk+2][lr]=rw.z; Ws[nb][lk+3][lr]=rw.w;
        buf = nb;
    }
    __syncthreads();
    mm16(&As[buf][0][0], &Ws[buf][0][0], ty, tx, acc2);

    int nc = n0 + tx * 4;
    float4 bv = make_float4(proj_bias(nc + 0, bq, bkv, bqp, bkvp),
                            proj_bias(nc + 1, bq, bkv, bqp, bkvp),
                            proj_bias(nc + 2, bq, bkv, bqp, bkvp),
                            proj_bias(nc + 3, bq, bkv, bqp, bkvp));
    #pragma unroll
    for (int a = 0; a < 4; a++) {
        float2 p0 = up2(acc2[a][0]), p1 = up2(acc2[a][1]);
        float4 r = make_float4(p0.x + bv.x, p0.y + bv.y, p1.x + bv.z, p1.y + bv.w);
        *(float4*)(g_proj + (size_t)(m0 + ty * 4 + a) * 1152 + nc) = r;
    }
}

__global__ void k_combine(const float* __restrict__ bout, float* __restrict__ out) {
    int i = blockIdx.x * 256 + threadIdx.x;
    out[i] = g_part[0][i] + g_part[1][i] + g_part[2][i] + g_part[3][i] + bout[i % 384];
}

// ---------------- LayerNorm ----------------
__global__ void k_ln(const float* __restrict__ gamma, const float* __restrict__ beta) {
    int n = blockIdx.x, t = threadIdx.x;
    float* row = g_se + (size_t)n * CSD;
    float x0 = row[t], x1 = row[t + 128], x2 = row[t + 256];
    float s1 = x0 + x1 + x2;
    float s2 = x0 * x0 + x1 * x1 + x2 * x2;
    __shared__ float r1[4], r2[4];
    #pragma unroll
    for (int o = 16; o; o >>= 1) {
        s1 += __shfl_xor_sync(0xffffffffu, s1, o);
        s2 += __shfl_xor_sync(0xffffffffu, s2, o);
    }
    if ((t & 31) == 0) { r1[t >> 5] = s1; r2[t >> 5] = s2; }
    __syncthreads();
    float ts1 = r1[0] + r1[1] + r1[2] + r1[3];
    float ts2 = r2[0] + r2[1] + r2[2] + r2[3];
    float mu  = ts1 * (1.f / 384.f);
    float var = ts2 * (1.f / 384.f) - mu * mu;
    float inv = rsqrtf(var + 1e-5f);
    row[t]       = (x0 - mu) * inv * gamma[t]       + beta[t];
    row[t + 128] = (x1 - mu) * inv * gamma[t + 128] + beta[t + 128];
    row[t + 256] = (x2 - mu) * inv * gamma[t + 256] + beta[t + 256];
}

// ---------------- assemble qhat/khat/kc/v/v_pts (warp per n) ----------------
__global__ void k_assemble(const float* __restrict__ r_rot, const float* __restrict__ r_trans,
                           const float* __restrict__ head_w) {
    int gw   = blockIdx.x * 8 + (threadIdx.x >> 5);
    int lane = threadIdx.x & 31;
    if (gw >= NRES || lane >= NHD) return;
    int n = gw, h = lane;
    float rot[9], t0[3];
    #pragma unroll
    for (int i = 0; i < 9; i++) rot[i] = r_rot[n * 45 + i];
    #pragma unroll
    for (int i = 0; i < 3; i++) t0[i] = r_trans[n * 15 + i];
    float hw = log1pf(expf(head_w[h])) * rsqrtf(54.0f);
    const float c1 = rsqrtf(48.0f);
    const float* P = g_proj + (size_t)n * 1152;
    float* qh = g_qhat + (size_t)n * 336 + h * 28;
    float* kh = g_khat + (size_t)n * 336 + h * 28;
    float* va = g_vall + ((size_t)n * NHD + h) * 40;
    #pragma unroll
    for (int c = 0; c < 16; c++) {
        qh[c] = c1 * P[h * 16 + c];
        kh[c] = P[192 + h * 32 + c];
        va[c] = P[192 + h * 32 + 16 + c];
    }
    #pragma unroll
    for (int pp = 0; pp < 4; pp++) {
        float l0 = P[576 +   0 + h * 4 + pp];
        float l1 = P[576 +  48 + h * 4 + pp];
        float l2 = P[576 +  96 + h * 4 + pp];
        #pragma unroll
        for (int i = 0; i < 3; i++) {
            float o = rot[i * 3] * l0 + rot[i * 3 + 1] * l1 + rot[i * 3 + 2] * l2 + t0[i];
            qh[16 + pp * 3 + i] = hw * o;
        }
    }
    float kc = 0.f;
    #pragma unroll
    for (int pp = 0; pp < 4; pp++) {
        float l0 = P[720 +   0 + h * 12 + pp];
        float l1 = P[720 + 144 + h * 12 + pp];
        float l2 = P[720 + 288 + h * 12 + pp];
        #pragma unroll
        for (int i = 0; i < 3; i++) {
            float o = rot[i * 3] * l0 + rot[i * 3 + 1] * l1 + rot[i * 3 + 2] * l2 + t0[i];
            kh[16 + pp * 3 + i] = o;
            kc += o * o;
        }
    }
    g_kc[n * NHD + h] = -0.5f * hw * kc;
    #pragma unroll
    for (int pv = 0; pv < 8; pv++) {
        int pp = 4 + pv;
        float l0 = P[720 +   0 + h * 12 + pp];
        float l1 = P[720 + 144 + h * 12 + pp];
        float l2 = P[720 + 288 + h * 12 + pp];
        #pragma unroll
        for (int i = 0; i < 3; i++) {
            float o = rot[i * 3] * l0 + rot[i * 3 + 1] * l1 + rot[i * 3 + 2] * l2 + t0[i];
            va[16 + pv * 3 + i] = o;
        }
    }
}

// ---------------- qk logits (K=28 GEMM) + kc + mask per head ----------------
__global__ __launch_bounds__(256) void k_qk(const float* __restrict__ mask) {
    __shared__ __align__(16) float Qs[28][68];
    __shared__ __align__(16) float Ks[28][68];
    __shared__ float kcs[64], uli[64], ulj[64];
    int h = blockIdx.z, i0 = blockIdx.y * 64, j0 = blockIdx.x * 64;
    int t = threadIdx.x;
    for (int idx = t; idx < 64 * 28; idx += 256) {
        int m = idx / 28, k = idx % 28;
        Qs[k][m] = g_qhat[(size_t)(i0 + m) * 336 + h * 28 + k];
        Ks[k][m] = g_khat[(size_t)(j0 + m) * 336 + h * 28 + k];
    }
    if (t < 64) {
        kcs[t] = g_kc[(j0 + t) * NHD + h];
        uli[t] = mask[(i0 + t) * 5];
        ulj[t] = mask[(j0 + t) * 5];
    }
    __syncthreads();
    int tx = t & 15, ty = t >> 4;
    u64 acc2[4][2] = {};
    #pragma unroll
    for (int k = 0; k < 28; k++) {
        float4 av = *(const float4*)(&Qs[k][ty * 4]);
        ulonglong2 wv = *(const ulonglong2*)(&Ks[k][tx * 4]);
        u64 a0 = dup2(av.x), a1 = dup2(av.y), a2 = dup2(av.z), a3 = dup2(av.w);
        ffma2(acc2[0][0], a0, wv.x); ffma2(acc2[0][1], a0, wv.y);
        ffma2(acc2[1][0], a1, wv.x); ffma2(acc2[1][1], a1, wv.y);
        ffma2(acc2[2][0], a2, wv.x); ffma2(acc2[2][1], a2, wv.y);
        ffma2(acc2[3][0], a3, wv.x); ffma2(acc2[3][1], a3, wv.y);
    }
    int jb = tx * 4;
    #pragma unroll
    for (int a = 0; a < 4; a++) {
        int i = i0 + ty * 4 + a;
        float mi = uli[ty * 4 + a];
        float2 p0 = up2(acc2[a][0]), p1 = up2(acc2[a][1]);
        float4 r;
        r.x = p0.x + kcs[jb + 0] + INF_ * (mi * ulj[jb + 0] - 1.f);
        r.y = p0.y + kcs[jb + 1] + INF_ * (mi * ulj[jb + 1] - 1.f);
        r.z = p1.x + kcs[jb + 2] + INF_ * (mi * ulj[jb + 2] - 1.f);
        r.w = p1.y + kcs[jb + 3] + INF_ * (mi * ulj[jb + 3] - 1.f);
        *(float4*)(&g_logits[((size_t)i * NHD + h) * NRES + j0 + jb]) = r;
    }
}

// ---------------- persistent fused z-pass per i: bias + exp + S + o_pair ----
// One block per i; 12 j-tiles of 64 rows, cp.async double-buffered.
// Phase 1: 2 j rows per thread (wb LDS amortized). Phase 2: 2 c per thread
// (es LDS amortized). ~100KB smem -> 2 CTA/SM.
#define ZT_STRIDE 132
#define ZTILE (64 * ZT_STRIDE)
#define ZAT_ES   (2 * ZTILE * 4)                 // 67584
#define ZAT_WB2  (ZAT_ES + 64 * 12 * 4)          // 70656
#define ZAT_PH   (ZAT_WB2 + 128 * 6 * 8)         // 76800
#define ZAT_SS   (ZAT_PH + 256 * 12 * 8)         // 101376
#define ZAT_SMEM (ZAT_SS + 64)                   // 101440

__global__ __launch_bounds__(256) void k_zattn(const float* __restrict__ z,
                                               const float* __restrict__ wb) {
    extern __shared__ __align__(16) unsigned char smraw[];
    float* zs  = (float*)smraw;
    float* es  = (float*)(smraw + ZAT_ES);
    u64*   wb2 = (u64*)(smraw + ZAT_WB2);
    u64*   ph  = (u64*)(smraw + ZAT_PH);
    float* Ssum= (float*)(smraw + ZAT_SS);

    int i = blockIdx.x;
    int t = threadIdx.x;
    int lane = t & 31, warp = t >> 5;
    const float c2 = 0.57735026918962576f;  // sqrt(1/3)

    for (int e = t; e < 768; e += 256) {
        int c = e / 6, p = e % 6;
        wb2[e] = pk2(c2 * wb[(2 * p) * 128 + c], c2 * wb[(2 * p + 1) * 128 + c]);
    }

    const float4* zbase = (const float4*)(z + (size_t)i * NRES * CZD);
    // prologue: prefetch tile 0 (64 rows x 32 float4 = 2048)
    #pragma unroll
    for (int l = 0; l < 8; l++) {
        int idx = t + l * 256;
        cpa16(zs + (idx >> 5) * ZT_STRIDE + (idx & 31) * 4, zbase + idx);
    }
    cpa_commit();

    u64 accO[12] = {};
    float sacc[2] = {0.f, 0.f};
    int buf = 0;

    for (int jt = 0; jt < 12; jt++) {
        __syncthreads();  // closes previous tile's phase-2 reads of buf^1
        if (jt < 11) {
            float* zb = zs + (buf ^ 1) * ZTILE;
            const float4* zrow = zbase + (jt + 1) * 2048;
            #pragma unroll
            for (int l = 0; l < 8; l++) {
                int idx = t + l * 256;
                cpa16(zb + (idx >> 5) * ZT_STRIDE + (idx & 31) * 4, zrow + idx);
            }
            cpa_commit();
            cpa_wait1();
        } else {
            cpa_wait0();
        }
        __syncthreads();
        const float* zt = zs + buf * ZTILE;

        // phase 1: 2 j rows per thread (ja = t&31, jb = ja+32), 16-c eighth q8 = t>>5
        {
            int ja = t & 31, q8 = t >> 5;
            const float* zja = zt + ja * ZT_STRIDE + q8 * 16;
            const float* zjb = zja + 32 * ZT_STRIDE;
            u64 acc[12] = {};
            #pragma unroll
            for (int c4 = 0; c4 < 4; c4++) {
                float va[4], vb[4];
                *(float4*)va = *(const float4*)(zja + c4 * 4);
                *(float4*)vb = *(const float4*)(zjb + c4 * 4);
                int cb = (q8 * 16 + c4 * 4) * 6;
                #pragma unroll
                for (int cc = 0; cc < 4; cc++) {
                    u64 za = dup2(va[cc]), zb2 = dup2(vb[cc]);
                    ulonglong2 wA = *(const ulonglong2*)(wb2 + cb + cc * 6);
                    ulonglong2 wB = *(const ulonglong2*)(wb2 + cb + cc * 6 + 2);
                    ulonglong2 wC = *(const ulonglong2*)(wb2 + cb + cc * 6 + 4);
                    ffma2(acc[0], za, wA.x);  ffma2(acc[1], za, wA.y);
                    ffma2(acc[2], za, wB.x);  ffma2(acc[3], za, wB.y);
                    ffma2(acc[4], za, wC.x);  ffma2(acc[5], za, wC.y);
                    ffma2(acc[6], zb2, wA.x); ffma2(acc[7], zb2, wA.y);
                    ffma2(acc[8], zb2, wB.x); ffma2(acc[9], zb2, wB.y);
                    ffma2(acc[10], zb2, wC.x); ffma2(acc[11], zb2, wC.y);
                }
            }
            #pragma unroll
            for (int p = 0; p < 12; p++) ph[t * 12 + p] = acc[p];
        }
        __syncthreads();

        // combine 8 c-eighths + qk logits + exp (unnormalized)
        if (t < 64) {
            int j = t, j0 = jt * 64;
            int jj2 = j & 31, sub = (j >> 5) * 6;
            #pragma unroll
            for (int p = 0; p < 6; p++) {
                float sx = 0.f, sy = 0.f;
                #pragma unroll
                for (int q8 = 0; q8 < 8; q8++) {
                    float2 v = up2(ph[(q8 * 32 + jj2) * 12 + sub + p]);
                    sx += v.x; sy += v.y;
                }
                int h0 = 2 * p, h1 = 2 * p + 1;
                size_t gi0 = ((size_t)i * NHD + h0) * NRES + j0 + j;
                size_t gi1 = ((size_t)i * NHD + h1) * NRES + j0 + j;
                float e0 = __expf(g_logits[gi0] + sx);
                float e1 = __expf(g_logits[gi1] + sy);
                g_logits[gi0] = e0; g_logits[gi1] = e1;
                es[j * 12 + h0] = e0; es[j * 12 + h1] = e1;
            }
        }
        __syncthreads();

        // partial S per head (register accumulation across tiles)
        {
            int cnt = 0;
            for (int h = warp; h < NHD; h += 8, cnt++) {
                float s = es[lane * 12 + h] + es[(lane + 32) * 12 + h];
                #pragma unroll
                for (int o = 16; o; o >>= 1) s += __shfl_xor_sync(0xffffffffu, s, o);
                sacc[cnt] += s;
            }
        }

        // phase 2: 2 c per thread (c = (t&63)*2), 16-j quarter g = t>>6
        {
            int c = (t & 63) * 2, g = t >> 6;
            #pragma unroll 4
            for (int jj = 0; jj < 16; jj++) {
                int j = g * 16 + jj;
                float2 zv = *(const float2*)(zt + j * ZT_STRIDE + c);
                u64 zd0 = dup2(zv.x), zd1 = dup2(zv.y);
                const ulonglong2* aj = (const ulonglong2*)(es + j * 12);
                ulonglong2 a0 = aj[0], a1 = aj[1], a2 = aj[2];
                ffma2(accO[0], zd0, a0.x); ffma2(accO[1], zd0, a0.y);
                ffma2(accO[2], zd0, a1.x); ffma2(accO[3], zd0, a1.y);
                ffma2(accO[4], zd0, a2.x); ffma2(accO[5], zd0, a2.y);
                ffma2(accO[6], zd1, a0.x); ffma2(accO[7], zd1, a0.y);
                ffma2(accO[8], zd1, a1.x); ffma2(accO[9], zd1, a1.y);
                ffma2(accO[10], zd1, a2.x); ffma2(accO[11], zd1, a2.y);
            }
        }
        buf ^= 1;
    }

    // finalize S
    if (lane == 0) {
        int cnt = 0;
        for (int h = warp; h < NHD; h += 8, cnt++) Ssum[h] = sacc[cnt];
    }
    __syncthreads();
    if (t < NHD) {
        float inv = 1.0f / Ssum[t];
        Ssum[t] = inv;
        g_Sinv[i * NHD + t] = inv;
    }
    __syncthreads();

    // reduce o_pair across 4 j-groups, normalize, write
    {
        u64* red = (u64*)zs;   // 3 groups x 64 x 12 u64 = 18KB, z tiles done
        int cl = t & 63, g = t >> 6;
        if (g > 0) {
            u64* dst = red + ((g - 1) * 64 + cl) * 12;
            #pragma unroll
            for (int p = 0; p < 12; p++) dst[p] = accO[p];
        }
        __syncthreads();
        if (g == 0) {
            #pragma unroll
            for (int p = 0; p < 12; p++) {
                float2 a = up2(accO[p]);
                #pragma unroll
                for (int gg = 0; gg < 3; gg++) {
                    float2 b = up2(red[(gg * 64 + cl) * 12 + p]);
                    a.x += b.x; a.y += b.y;
                }
                accO[p] = pk2(a.x, a.y);
            }
            int c = cl * 2;
            float* ob = g_cat + (size_t)i * 2112 + 576;
            #pragma unroll
            for (int p = 0; p < 6; p++) {
                int h0 = 2 * p, h1 = 2 * p + 1;
                float2 vc0 = up2(accO[p]);       // (h0, h1) for column c
                float2 vc1 = up2(accO[6 + p]);   // (h0, h1) for column c+1
                float s0 = Ssum[h0], s1 = Ssum[h1];
                *(float2*)(ob + h0 * 128 + c) = make_float2(vc0.x * s0, vc1.x * s0);
                *(float2*)(ob + h1 * 128 + c) = make_float2(vc0.y * s1, vc1.y * s1);
            }
        }
    }
}

// ---------------- o = (e@v)/S, o_pt = inv-frame((e@v_pts)/S) fused ----------
#define OV_AT   0
#define OV_VS   17408
#define OV_RED  27648
#define OV_OPT  48128
#define OV_SMEM 54272

__global__ __launch_bounds__(256) void k_ov(const float* __restrict__ r_rot,
                                            const float* __restrict__ r_trans) {
    extern __shared__ __align__(16) unsigned char sm[];
    float* a_t  = (float*)(sm + OV_AT);    // [k][r] 64x68
    float* v_s  = (float*)(sm + OV_VS);    // [k][c] 64x40
    u64*   red  = (u64*)(sm + OV_RED);     // 128x20
    float* opts = (float*)(sm + OV_OPT);   // [r][24]
    int i0 = blockIdx.x * 64;
    int h  = blockIdx.y;
    int t  = threadIdx.x;
    int rq = t & 15, cq = (t >> 4) & 3, ks = t >> 6;
    u64 acc[4][5] = {};
    for (int jt = 0; jt < 12; jt++) {
        #pragma unroll
        for (int l = 0; l < 16; l++) {
            int idx = t + l * 256;
            int r = idx >> 6, k = idx & 63;
            a_t[k * 68 + r] = g_logits[((size_t)(i0 + r) * NHD + h) * NRES + jt * 64 + k];
        }
        #pragma unroll
        for (int l = 0; l < 10; l++) {
            int idx = t + l * 256;
            v_s[idx] = g_vall[((size_t)(jt * 64 + idx / 40) * NHD + h) * 40 + idx % 40];
        }
        __syncthreads();
        #pragma unroll
        for (int kk = 0; kk < 16; kk++) {
            int k = ks * 16 + kk;
            float4 av = *(const float4*)(a_t + k * 68 + rq * 4);
            const u64* vv = (const u64*)(v_s + k * 40 + cq * 10);
            u64 v0 = vv[0], v1 = vv[1], v2 = vv[2], v3 = vv[3], v4 = vv[4];
            u64 a0 = dup2(av.x), a1 = dup2(av.y), a2 = dup2(av.z), a3 = dup2(av.w);
            ffma2(acc[0][0], a0, v0); ffma2(acc[0][1], a0, v1); ffma2(acc[0][2], a0, v2);
            ffma2(acc[0][3], a0, v3); ffma2(acc[0][4], a0, v4);
            ffma2(acc[1][0], a1, v0); ffma2(acc[1][1], a1, v1); ffma2(acc[1][2], a1, v2);
            ffma2(acc[1][3], a1, v3); ffma2(acc[1][4], a1, v4);
            ffma2(acc[2][0], a2, v0); ffma2(acc[2][1], a2, v1); ffma2(acc[2][2], a2, v2);
            ffma2(acc[2][3], a2, v3); ffma2(acc[2][4], a2, v4);
            ffma2(acc[3][0], a3, v0); ffma2(acc[3][1], a3, v1); ffma2(acc[3][2], a3, v2);
            ffma2(acc[3][3], a3, v3); ffma2(acc[3][4], a3, v4);
        }
        __syncthreads();
    }
    int slot = t & 63;
    if (ks >= 2) {
        u64* dst = red + ((ks - 2) * 64 + slot) * 20;
        #pragma unroll
        for (int rr = 0; rr < 4; rr++)
            #pragma unroll
            for (int p = 0; p < 5; p++) dst[rr * 5 + p] = acc[rr][p];
    }
    __syncthreads();
    if (ks < 2) {
        const u64* src = red + (ks * 64 + slot) * 20;
        #pragma unroll
        for (int rr = 0; rr < 4; rr++)
            #pragma unroll
            for (int p = 0; p < 5; p++) {
                float2 a = up2(acc[rr][p]), b = up2(src[rr * 5 + p]);
                acc[rr][p] = pk2(a.x + b.x, a.y + b.y);
            }
    }
    __syncthreads();
    if (ks == 1) {
        u64* dst = red + slot * 20;
        #pragma unroll
        for (int rr = 0; rr < 4; rr++)
            #pragma unroll
            for (int p = 0; p < 5; p++) dst[rr * 5 + p] = acc[rr][p];
    }
    __syncthreads();
    if (ks == 0) {
        const u64* src = red + slot * 20;
        #pragma unroll
        for (int rr = 0; rr < 4; rr++) {
            int rl = rq * 4 + rr;
            float inv = g_Sinv[(i0 + rl) * NHD + h];
            #pragma unroll
            for (int p = 0; p < 5; p++) {
                float2 a = up2(acc[rr][p]), b = up2(src[rr * 5 + p]);
                float vx = (a.x + b.x) * inv, vy = (a.y + b.y) * inv;
                int c0 = cq * 10 + 2 * p;
                if (c0 < 16)     g_cat[(size_t)(i0 + rl) * 2112 + h * 16 + c0] = vx;
                else             opts[rl * 24 + (c0 - 16)] = vx;
                int c1 = c0 + 1;
                if (c1 < 16)     g_cat[(size_t)(i0 + rl) * 2112 + h * 16 + c1] = vy;
                else             opts[rl * 24 + (c1 - 16)] = vy;
            }
        }
    }
    __syncthreads();
    for (int e2 = t; e2 < 512; e2 += 256) {
        int rl = e2 >> 3, pv = e2 & 7;
        int n = i0 + rl;
        const float* pp = opts + rl * 24 + pv * 3;
        float d0 = pp[0] - r_trans[n * 15 + 0];
        float d1 = pp[1] - r_trans[n * 15 + 1];
        float d2 = pp[2] - r_trans[n * 15 + 2];
        const float* R = r_rot + n * 45;
        float o0 = R[0] * d0 + R[3] * d1 + R[6] * d2;
        float o1 = R[1] * d0 + R[4] * d1 + R[7] * d2;
        float o2 = R[2] * d0 + R[5] * d1 + R[8] * d2;
        float nm = sqrtf(o0 * o0 + o1 * o1 + o2 * o2 + 1e-8f);
        float* cb = g_cat + (size_t)n * 2112 + 192;
        int rr2 = h * 8 + pv;
        cb[rr2] = o0; cb[96 + rr2] = o1; cb[192 + rr2] = o2; cb[288 + rr2] = nm;
    }
}

// ---------------- launch ----------------
extern "C" void kernel_launch(void* const* d_in, const int* in_sizes, int n_in,
                              void* d_out, int out_size) {
    const float* s       = (const float*)d_in[0];
    const float* z       = (const float*)d_in[1];
    const float* r_rot   = (const float*)d_in[2];
    const float* r_trans = (const float*)d_in[3];
    const float* mask    = (const float*)d_in[4];
    const float* wq      = (const float*)d_in[5];
    const float* bq      = (const float*)d_in[6];
    const float* wkv     = (const float*)d_in[7];
    const float* bkv     = (const float*)d_in[8];
    const float* wqp     = (const float*)d_in[9];
    const float* bqp     = (const float*)d_in[10];
    const float* wkvp    = (const float*)d_in[11];
    const float* bkvp    = (const float*)d_in[12];
    const float* wb      = (const float*)d_in[13];
    const float* head_w  = (const float*)d_in[15];
    const float* wout    = (const float*)d_in[16];
    const float* bout    = (const float*)d_in[17];
    const float* wexp    = (const float*)d_in[18];
    const float* bexp    = (const float*)d_in[19];
    const float* ln_g    = (const float*)d_in[20];
    const float* ln_b    = (const float*)d_in[21];
    float* out = (float*)d_out;

    float *p_se = nullptr, *p_cat = nullptr, *p_part = nullptr;
    cudaGetSymbolAddress((void**)&p_se,   g_se);
    cudaGetSymbolAddress((void**)&p_cat,  g_cat);
    cudaGetSymbolAddress((void**)&p_part, g_part);

    static int attn_cfg = 0;
    if (!attn_cfg) {
        cudaFuncSetAttribute(k_zattn, cudaFuncAttributeMaxDynamicSharedMemorySize, ZAT_SMEM);
        cudaFuncSetAttribute(k_ov, cudaFuncAttributeMaxDynamicSharedMemorySize, OV_SMEM);
        attn_cfg = 1;
    }

    k_gemm64<<<dim3(6, 12, 1), 256>>>(s, wexp, bexp, p_se, 384, 384, 24, 1, 0);
    k_ln<<<768, 128>>>(ln_g, ln_b);
    k_gemm_proj<<<dim3(18, 12), 256>>>(wq, bq, wkv, bkv, wqp, bqp, wkvp, bkvp);
    k_assemble<<<96, 256>>>(r_rot, r_trans, head_w);
    k_qk<<<dim3(12, 12, 12), 256>>>(mask);
    k_zattn<<<768, 256, ZAT_SMEM>>>(z, wb);
    k_ov<<<dim3(12, 12), 256, OV_SMEM>>>(r_rot, r_trans);
    k_gemm64<<<dim3(6, 12, 4), 256>>>(p_cat, wout, nullptr, p_part, 2112, 384, 33, 0, NRES * CSD);
    k_combine<<<1152, 256>>>(bout, out);
}

// round 14
// speedup vs baseline: 1.2643x; 1.0488x over previous
#include <cuda_runtime.h>
#include <math.h>

#define NRES 768
#define CSD  384
#define CZD  128
#define NHD  12
#define INF_ 100000.0f

typedef unsigned long long u64;

// ---------------- packed f32x2 helpers ----------------
__device__ __forceinline__ void ffma2(u64& d, u64 a, u64 b) {
    asm("fma.rn.f32x2 %0, %1, %2, %0;" : "+l"(d) : "l"(a), "l"(b));
}
__device__ __forceinline__ u64 dup2(float x) {
    u64 r; asm("mov.b64 %0, {%1, %1};" : "=l"(r) : "f"(x)); return r;
}
__device__ __forceinline__ u64 pk2(float lo, float hi) {
    u64 r; asm("mov.b64 %0, {%1, %2};" : "=l"(r) : "f"(lo), "f"(hi)); return r;
}
__device__ __forceinline__ float2 up2(u64 v) {
    float lo, hi; asm("mov.b64 {%0, %1}, %2;" : "=f"(lo), "=f"(hi) : "l"(v));
    return make_float2(lo, hi);
}
// ---------------- cp.async helpers ----------------
__device__ __forceinline__ void cpa16(void* dst, const void* src) {
    unsigned sdst = (unsigned)__cvta_generic_to_shared(dst);
    asm volatile("cp.async.cg.shared.global [%0], [%1], 16;" :: "r"(sdst), "l"(src));
}
__device__ __forceinline__ void cpa_commit() { asm volatile("cp.async.commit_group;"); }
__device__ __forceinline__ void cpa_wait1() { asm volatile("cp.async.wait_group 1;"); }
__device__ __forceinline__ void cpa_wait0() { asm volatile("cp.async.wait_group 0;"); }

// ---------------- scratch (device globals; no allocation) ----------------
__device__ float g_se[NRES * CSD];
__device__ float g_proj[NRES * 1152];
__device__ float g_qhat[NRES * 336];
__device__ float g_khat[NRES * 336];
__device__ float g_kc[NRES * NHD];
__device__ float g_vall[NRES * NHD * 40];
__device__ float g_cat[NRES * 2112];
__device__ float g_part[4][NRES * CSD];
__device__ float g_logits[NHD * NRES * NRES]; // [i][h][j]: qk-logits, then unnormalized exp
__device__ float g_Sinv[NRES * NHD];          // 1/S per (i,h)

// =====================================================================
// fp32 GEMM with FFMA2: C = A(MxK) @ W(NxK)^T [+ bias]; 64x64 tile, BK=16.
// =====================================================================
__device__ __forceinline__ void mm16(const float* Ab, const float* Wb,
                                     int ty, int tx, u64 acc2[4][2]) {
    #pragma unroll
    for (int k = 0; k < 16; k++) {
        float4 av = *(const float4*)(Ab + k * 68 + ty * 4);
        ulonglong2 wv = *(const ulonglong2*)(Wb + k * 68 + tx * 4);
        u64 a0 = dup2(av.x), a1 = dup2(av.y), a2 = dup2(av.z), a3 = dup2(av.w);
        ffma2(acc2[0][0], a0, wv.x); ffma2(acc2[0][1], a0, wv.y);
        ffma2(acc2[1][0], a1, wv.x); ffma2(acc2[1][1], a1, wv.y);
        ffma2(acc2[2][0], a2, wv.x); ffma2(acc2[2][1], a2, wv.y);
        ffma2(acc2[3][0], a3, wv.x); ffma2(acc2[3][1], a3, wv.y);
    }
}

__global__ __launch_bounds__(256) void k_gemm64(
    const float* __restrict__ A, const float* __restrict__ W,
    const float* __restrict__ bias, float* __restrict__ C,
    int ld, int ldc, int nkt, int add_bias, int partStride)
{
    __shared__ __align__(16) float As[2][16][68];
    __shared__ __align__(16) float Ws[2][16][68];
    int t  = threadIdx.x;
    int m0 = blockIdx.y * 64, n0 = blockIdx.x * 64;
    int kt0 = blockIdx.z * nkt;
    C += (size_t)blockIdx.z * partStride;
    int lr = t >> 2, lk = (t & 3) * 4;
    const float* arow = A + (size_t)(m0 + lr) * ld + kt0 * 16 + lk;
    const float* wrow = W + (size_t)(n0 + lr) * ld + kt0 * 16 + lk;
    int tx = t & 15, ty = t >> 4;

    u64 acc2[4][2] = {};
    float4 ra = *(const float4*)arow;
    float4 rw = *(const float4*)wrow;
    int buf = 0;
    As[0][lk+0][lr]=ra.x; As[0][lk+1][lr]=ra.y; As[0][lk+2][lr]=ra.z; As[0][lk+3][lr]=ra.w;
    Ws[0][lk+0][lr]=rw.x; Ws[0][lk+1][lr]=rw.y; Ws[0][lk+2][lr]=rw.z; Ws[0][lk+3][lr]=rw.w;

    for (int kt = 0; kt < nkt - 1; kt++) {
        __syncthreads();
        ra = *(const float4*)(arow + (kt + 1) * 16);
        rw = *(const float4*)(wrow + (kt + 1) * 16);
        mm16(&As[buf][0][0], &Ws[buf][0][0], ty, tx, acc2);
        int nb = buf ^ 1;
        As[nb][lk+0][lr]=ra.x; As[nb][lk+1][lr]=ra.y; As[nb][lk+2][lr]=ra.z; As[nb][lk+3][lr]=ra.w;
        Ws[nb][lk+0][lr]=rw.x; Ws[nb][lk+1][lr]=rw.y; Ws[nb][lk+2][lr]=rw.z; Ws[nb][lk+3][lr]=rw.w;
        buf = nb;
    }
    __syncthreads();
    mm16(&As[buf][0][0], &Ws[buf][0][0], ty, tx, acc2);

    float4 bv = make_float4(0.f, 0.f, 0.f, 0.f);
    if (add_bias) bv = *(const float4*)(bias + n0 + tx * 4);
    #pragma unroll
    for (int a = 0; a < 4; a++) {
        float2 p0 = up2(acc2[a][0]), p1 = up2(acc2[a][1]);
        float4 r = make_float4(p0.x + bv.x, p0.y + bv.y, p1.x + bv.z, p1.y + bv.w);
        *(float4*)(C + (size_t)(m0 + ty * 4 + a) * ldc + n0 + tx * 4) = r;
    }
}

__device__ __forceinline__ float proj_bias(int n, const float* bq, const float* bkv,
                                           const float* bqp, const float* bkvp) {
    if (n < 192) return bq[n];
    if (n < 576) return bkv[n - 192];
    if (n < 720) return bqp[n - 576];
    return bkvp[n - 720];
}

__global__ __launch_bounds__(256) void k_gemm_proj(
    const float* __restrict__ wq,  const float* __restrict__ bq,
    const float* __restrict__ wkv, const float* __restrict__ bkv,
    const float* __restrict__ wqp, const float* __restrict__ bqp,
    const float* __restrict__ wkvp,const float* __restrict__ bkvp)
{
    __shared__ __align__(16) float As[2][16][68];
    __shared__ __align__(16) float Ws[2][16][68];
    int t  = threadIdx.x;
    int m0 = blockIdx.y * 64, n0 = blockIdx.x * 64;
    int lr = t >> 2, lk = (t & 3) * 4;
    const float* arow = g_se + (size_t)(m0 + lr) * 384 + lk;
    int n = n0 + lr;
    const float* wbase; int nl;
    if      (n < 192) { wbase = wq;   nl = n; }
    else if (n < 576) { wbase = wkv;  nl = n - 192; }
    else if (n < 720) { wbase = wqp;  nl = n - 576; }
    else              { wbase = wkvp; nl = n - 720; }
    const float* wrow = wbase + (size_t)nl * 384 + lk;
    int tx = t & 15, ty = t >> 4;

    u64 acc2[4][2] = {};
    float4 ra = *(const float4*)arow;
    float4 rw = *(const float4*)wrow;
    int buf = 0;
    As[0][lk+0][lr]=ra.x; As[0][lk+1][lr]=ra.y; As[0][lk+2][lr]=ra.z; As[0][lk+3][lr]=ra.w;
    Ws[0][lk+0][lr]=rw.x; Ws[0][lk+1][lr]=rw.y; Ws[0][lk+2][lr]=rw.z; Ws[0][lk+3][lr]=rw.w;

    const int nkt = 24;
    for (int kt = 0; kt < nkt - 1; kt++) {
        __syncthreads();
        ra = *(const float4*)(arow + (kt + 1) * 16);
        rw = *(const float4*)(wrow + (kt + 1) * 16);
        mm16(&As[buf][0][0], &Ws[buf][0][0], ty, tx, acc2);
        int nb = buf ^ 1;
        As[nb][lk+0][lr]=ra.x; As[nb][lk+1][lr]=ra.y; As[nb][lk+2][lr]=ra.z; As[nb][lk+3][lr]=ra.w;
        Ws[nb][lk+0][lr]=rw.x; Ws[nb][lk+1][lr]=rw.y; Ws[nb][lk+2][lr]=rw.z; Ws[nb][lk+3][lr]=rw.w;
        buf = nb;
    }
    __syncthreads();
    mm16(&As[buf][0][0], &Ws[buf][0][0], ty, tx, acc2);

    int nc = n0 + tx * 4;
    float4 bv = make_float4(proj_bias(nc + 0, bq, bkv, bqp, bkvp),
                            proj_bias(nc + 1, bq, bkv, bqp, bkvp),
                            proj_bias(nc + 2, bq, bkv, bqp, bkvp),
                            proj_bias(nc + 3, bq, bkv, bqp, bkvp));
    #pragma unroll
    for (int a = 0; a < 4; a++) {
        float2 p0 = up2(acc2[a][0]), p1 = up2(acc2[a][1]);
        float4 r = make_float4(p0.x + bv.x, p0.y + bv.y, p1.x + bv.z, p1.y + bv.w);
        *(float4*)(g_proj + (size_t)(m0 + ty * 4 + a) * 1152 + nc) = r;
    }
}

__global__ void k_combine(const float* __restrict__ bout, float* __restrict__ out) {
    int i = blockIdx.x * 256 + threadIdx.x;
    out[i] = g_part[0][i] + g_part[1][i] + g_part[2][i] + g_part[3][i] + bout[i % 384];
}

// ---------------- LayerNorm over split-K partials (se = LN(part0+part1+bias)) ---
__global__ void k_ln(const float* __restrict__ bexp,
                     const float* __restrict__ gamma, const float* __restrict__ beta) {
    int n = blockIdx.x, t = threadIdx.x;
    const float* P0 = g_part[0] + (size_t)n * CSD;
    const float* P1 = g_part[1] + (size_t)n * CSD;
    float x0 = P0[t]       + P1[t]       + bexp[t];
    float x1 = P0[t + 128] + P1[t + 128] + bexp[t + 128];
    float x2 = P0[t + 256] + P1[t + 256] + bexp[t + 256];
    float s1 = x0 + x1 + x2;
    float s2 = x0 * x0 + x1 * x1 + x2 * x2;
    __shared__ float r1[4], r2[4];
    #pragma unroll
    for (int o = 16; o; o >>= 1) {
        s1 += __shfl_xor_sync(0xffffffffu, s1, o);
        s2 += __shfl_xor_sync(0xffffffffu, s2, o);
    }
    if ((t & 31) == 0) { r1[t >> 5] = s1; r2[t >> 5] = s2; }
    __syncthreads();
    float ts1 = r1[0] + r1[1] + r1[2] + r1[3];
    float ts2 = r2[0] + r2[1] + r2[2] + r2[3];
    float mu  = ts1 * (1.f / 384.f);
    float var = ts2 * (1.f / 384.f) - mu * mu;
    float inv = rsqrtf(var + 1e-5f);
    float* row = g_se + (size_t)n * CSD;
    row[t]       = (x0 - mu) * inv * gamma[t]       + beta[t];
    row[t + 128] = (x1 - mu) * inv * gamma[t + 128] + beta[t + 128];
    row[t + 256] = (x2 - mu) * inv * gamma[t + 256] + beta[t + 256];
}

// ---------------- assemble qhat/khat/kc/v/v_pts (warp per n) ----------------
__global__ void k_assemble(const float* __restrict__ r_rot, const float* __restrict__ r_trans,
                           const float* __restrict__ head_w) {
    int gw   = blockIdx.x * 8 + (threadIdx.x >> 5);
    int lane = threadIdx.x & 31;
    if (gw >= NRES || lane >= NHD) return;
    int n = gw, h = lane;
    float rot[9], t0[3];
    #pragma unroll
    for (int i = 0; i < 9; i++) rot[i] = r_rot[n * 45 + i];
    #pragma unroll
    for (int i = 0; i < 3; i++) t0[i] = r_trans[n * 15 + i];
    float hw = log1pf(expf(head_w[h])) * rsqrtf(54.0f);
    const float c1 = rsqrtf(48.0f);
    const float* P = g_proj + (size_t)n * 1152;
    float* qh = g_qhat + (size_t)n * 336 + h * 28;
    float* kh = g_khat + (size_t)n * 336 + h * 28;
    float* va = g_vall + ((size_t)n * NHD + h) * 40;
    #pragma unroll
    for (int c = 0; c < 16; c++) {
        qh[c] = c1 * P[h * 16 + c];
        kh[c] = P[192 + h * 32 + c];
        va[c] = P[192 + h * 32 + 16 + c];
    }
    #pragma unroll
    for (int pp = 0; pp < 4; pp++) {
        float l0 = P[576 +   0 + h * 4 + pp];
        float l1 = P[576 +  48 + h * 4 + pp];
        float l2 = P[576 +  96 + h * 4 + pp];
        #pragma unroll
        for (int i = 0; i < 3; i++) {
            float o = rot[i * 3] * l0 + rot[i * 3 + 1] * l1 + rot[i * 3 + 2] * l2 + t0[i];
            qh[16 + pp * 3 + i] = hw * o;
        }
    }
    float kc = 0.f;
    #pragma unroll
    for (int pp = 0; pp < 4; pp++) {
        float l0 = P[720 +   0 + h * 12 + pp];
        float l1 = P[720 + 144 + h * 12 + pp];
        float l2 = P[720 + 288 + h * 12 + pp];
        #pragma unroll
        for (int i = 0; i < 3; i++) {
            float o = rot[i * 3] * l0 + rot[i * 3 + 1] * l1 + rot[i * 3 + 2] * l2 + t0[i];
            kh[16 + pp * 3 + i] = o;
            kc += o * o;
        }
    }
    g_kc[n * NHD + h] = -0.5f * hw * kc;
    #pragma unroll
    for (int pv = 0; pv < 8; pv++) {
        int pp = 4 + pv;
        float l0 = P[720 +   0 + h * 12 + pp];
        float l1 = P[720 + 144 + h * 12 + pp];
        float l2 = P[720 + 288 + h * 12 + pp];
        #pragma unroll
        for (int i = 0; i < 3; i++) {
            float o = rot[i * 3] * l0 + rot[i * 3 + 1] * l1 + rot[i * 3 + 2] * l2 + t0[i];
            va[16 + pv * 3 + i] = o;
        }
    }
}

// ---------------- qk logits (K=28 GEMM) + kc + mask per head ----------------
__global__ __launch_bounds__(256) void k_qk(const float* __restrict__ mask) {
    __shared__ __align__(16) float Qs[28][68];
    __shared__ __align__(16) float Ks[28][68];
    __shared__ float kcs[64], uli[64], ulj[64];
    int h = blockIdx.z, i0 = blockIdx.y * 64, j0 = blockIdx.x * 64;
    int t = threadIdx.x;
    for (int idx = t; idx < 64 * 28; idx += 256) {
        int m = idx / 28, k = idx % 28;
        Qs[k][m] = g_qhat[(size_t)(i0 + m) * 336 + h * 28 + k];
        Ks[k][m] = g_khat[(size_t)(j0 + m) * 336 + h * 28 + k];
    }
    if (t < 64) {
        kcs[t] = g_kc[(j0 + t) * NHD + h];
        uli[t] = mask[(i0 + t) * 5];
        ulj[t] = mask[(j0 + t) * 5];
    }
    __syncthreads();
    int tx = t & 15, ty = t >> 4;
    u64 acc2[4][2] = {};
    #pragma unroll
    for (int k = 0; k < 28; k++) {
        float4 av = *(const float4*)(&Qs[k][ty * 4]);
        ulonglong2 wv = *(const ulonglong2*)(&Ks[k][tx * 4]);
        u64 a0 = dup2(av.x), a1 = dup2(av.y), a2 = dup2(av.z), a3 = dup2(av.w);
        ffma2(acc2[0][0], a0, wv.x); ffma2(acc2[0][1], a0, wv.y);
        ffma2(acc2[1][0], a1, wv.x); ffma2(acc2[1][1], a1, wv.y);
        ffma2(acc2[2][0], a2, wv.x); ffma2(acc2[2][1], a2, wv.y);
        ffma2(acc2[3][0], a3, wv.x); ffma2(acc2[3][1], a3, wv.y);
    }
    int jb = tx * 4;
    #pragma unroll
    for (int a = 0; a < 4; a++) {
        int i = i0 + ty * 4 + a;
        float mi = uli[ty * 4 + a];
        float2 p0 = up2(acc2[a][0]), p1 = up2(acc2[a][1]);
        float4 r;
        r.x = p0.x + kcs[jb + 0] + INF_ * (mi * ulj[jb + 0] - 1.f);
        r.y = p0.y + kcs[jb + 1] + INF_ * (mi * ulj[jb + 1] - 1.f);
        r.z = p1.x + kcs[jb + 2] + INF_ * (mi * ulj[jb + 2] - 1.f);
        r.w = p1.y + kcs[jb + 3] + INF_ * (mi * ulj[jb + 3] - 1.f);
        *(float4*)(&g_logits[((size_t)i * NHD + h) * NRES + j0 + jb]) = r;
    }
}

// ---------------- persistent fused z-pass per i: bias + exp + S + o_pair ----
#define ZT_STRIDE 132
#define ZTILE (64 * ZT_STRIDE)
#define ZAT_ES   (2 * ZTILE * 4)                 // 67584
#define ZAT_WB2  (ZAT_ES + 64 * 12 * 4)          // 70656
#define ZAT_PH   (ZAT_WB2 + 128 * 6 * 8)         // 76800
#define ZAT_SS   (ZAT_PH + 256 * 12 * 8)         // 101376
#define ZAT_SMEM (ZAT_SS + 64)                   // 101440

__global__ __launch_bounds__(256) void k_zattn(const float* __restrict__ z,
                                               const float* __restrict__ wb) {
    extern __shared__ __align__(16) unsigned char smraw[];
    float* zs  = (float*)smraw;
    float* es  = (float*)(smraw + ZAT_ES);
    u64*   wb2 = (u64*)(smraw + ZAT_WB2);
    u64*   ph  = (u64*)(smraw + ZAT_PH);
    float* Ssum= (float*)(smraw + ZAT_SS);

    int i = blockIdx.x;
    int t = threadIdx.x;
    int lane = t & 31, warp = t >> 5;
    const float c2 = 0.57735026918962576f;  // sqrt(1/3)

    for (int e = t; e < 768; e += 256) {
        int c = e / 6, p = e % 6;
        wb2[e] = pk2(c2 * wb[(2 * p) * 128 + c], c2 * wb[(2 * p + 1) * 128 + c]);
    }

    const float4* zbase = (const float4*)(z + (size_t)i * NRES * CZD);
    #pragma unroll
    for (int l = 0; l < 8; l++) {
        int idx = t + l * 256;
        cpa16(zs + (idx >> 5) * ZT_STRIDE + (idx & 31) * 4, zbase + idx);
    }
    cpa_commit();

    u64 accO[12] = {};
    float sacc[2] = {0.f, 0.f};
    int buf = 0;

    for (int jt = 0; jt < 12; jt++) {
        __syncthreads();
        if (jt < 11) {
            float* zb = zs + (buf ^ 1) * ZTILE;
            const float4* zrow = zbase + (jt + 1) * 2048;
            #pragma unroll
            for (int l = 0; l < 8; l++) {
                int idx = t + l * 256;
                cpa16(zb + (idx >> 5) * ZT_STRIDE + (idx & 31) * 4, zrow + idx);
            }
            cpa_commit();
            cpa_wait1();
        } else {
            cpa_wait0();
        }
        __syncthreads();
        const float* zt = zs + buf * ZTILE;

        // phase 1: 2 j rows per thread (ja = t&31, jb = ja+32), 16-c eighth q8 = t>>5
        {
            int ja = t & 31, q8 = t >> 5;
            const float* zja = zt + ja * ZT_STRIDE + q8 * 16;
            const float* zjb = zja + 32 * ZT_STRIDE;
            u64 acc[12] = {};
            #pragma unroll
            for (int c4 = 0; c4 < 4; c4++) {
                float va[4], vb[4];
                *(float4*)va = *(const float4*)(zja + c4 * 4);
                *(float4*)vb = *(const float4*)(zjb + c4 * 4);
                int cb = (q8 * 16 + c4 * 4) * 6;
                #pragma unroll
                for (int cc = 0; cc < 4; cc++) {
                    u64 za = dup2(va[cc]), zb2 = dup2(vb[cc]);
                    ulonglong2 wA = *(const ulonglong2*)(wb2 + cb + cc * 6);
                    ulonglong2 wB = *(const ulonglong2*)(wb2 + cb + cc * 6 + 2);
                    ulonglong2 wC = *(const ulonglong2*)(wb2 + cb + cc * 6 + 4);
                    ffma2(acc[0], za, wA.x);  ffma2(acc[1], za, wA.y);
                    ffma2(acc[2], za, wB.x);  ffma2(acc[3], za, wB.y);
                    ffma2(acc[4], za, wC.x);  ffma2(acc[5], za, wC.y);
                    ffma2(acc[6], zb2, wA.x); ffma2(acc[7], zb2, wA.y);
                    ffma2(acc[8], zb2, wB.x); ffma2(acc[9], zb2, wB.y);
                    ffma2(acc[10], zb2, wC.x); ffma2(acc[11], zb2, wC.y);
                }
            }
            #pragma unroll
            for (int p = 0; p < 12; p++) ph[t * 12 + p] = acc[p];
        }
        __syncthreads();

        // combine 8 c-eighths + qk logits + exp (unnormalized)
        if (t < 64) {
            int j = t, j0 = jt * 64;
            int jj2 = j & 31, sub = (j >> 5) * 6;
            #pragma unroll
            for (int p = 0; p < 6; p++) {
                float sx = 0.f, sy = 0.f;
                #pragma unroll
                for (int q8 = 0; q8 < 8; q8++) {
                    float2 v = up2(ph[(q8 * 32 + jj2) * 12 + sub + p]);
                    sx += v.x; sy += v.y;
                }
                int h0 = 2 * p, h1 = 2 * p + 1;
                size_t gi0 = ((size_t)i * NHD + h0) * NRES + j0 + j;
                size_t gi1 = ((size_t)i * NHD + h1) * NRES + j0 + j;
                float e0 = __expf(g_logits[gi0] + sx);
                float e1 = __expf(g_logits[gi1] + sy);
                g_logits[gi0] = e0; g_logits[gi1] = e1;
                es[j * 12 + h0] = e0; es[j * 12 + h1] = e1;
            }
        }
        __syncthreads();

        // partial S per head
        {
            int cnt = 0;
            for (int h = warp; h < NHD; h += 8, cnt++) {
                float s = es[lane * 12 + h] + es[(lane + 32) * 12 + h];
                #pragma unroll
                for (int o = 16; o; o >>= 1) s += __shfl_xor_sync(0xffffffffu, s, o);
                sacc[cnt] += s;
            }
        }

        // phase 2: 2 c per thread (c = (t&63)*2), 16-j quarter g = t>>6
        {
            int c = (t & 63) * 2, g = t >> 6;
            #pragma unroll 4
            for (int jj = 0; jj < 16; jj++) {
                int j = g * 16 + jj;
                float2 zv = *(const float2*)(zt + j * ZT_STRIDE + c);
                u64 zd0 = dup2(zv.x), zd1 = dup2(zv.y);
                const ulonglong2* aj = (const ulonglong2*)(es + j * 12);
                ulonglong2 a0 = aj[0], a1 = aj[1], a2 = aj[2];
                ffma2(accO[0], zd0, a0.x); ffma2(accO[1], zd0, a0.y);
                ffma2(accO[2], zd0, a1.x); ffma2(accO[3], zd0, a1.y);
                ffma2(accO[4], zd0, a2.x); ffma2(accO[5], zd0, a2.y);
                ffma2(accO[6], zd1, a0.x); ffma2(accO[7], zd1, a0.y);
                ffma2(accO[8], zd1, a1.x); ffma2(accO[9], zd1, a1.y);
                ffma2(accO[10], zd1, a2.x); ffma2(accO[11], zd1, a2.y);
            }
        }
        buf ^= 1;
    }

    // finalize S
    if (lane == 0) {
        int cnt = 0;
        for (int h = warp; h < NHD; h += 8, cnt++) Ssum[h] = sacc[cnt];
    }
    __syncthreads();
    if (t < NHD) {
        float inv = 1.0f / Ssum[t];
        Ssum[t] = inv;
        g_Sinv[i * NHD + t] = inv;
    }
    __syncthreads();

    // reduce o_pair across 4 j-groups, normalize, write
    {
        u64* red = (u64*)zs;
        int cl = t & 63, g = t >> 6;
        if (g > 0) {
            u64* dst = red + ((g - 1) * 64 + cl) * 12;
            #pragma unroll
            for (int p = 0; p < 12; p++) dst[p] = accO[p];
        }
        __syncthreads();
        if (g == 0) {
            #pragma unroll
            for (int p = 0; p < 12; p++) {
                float2 a = up2(accO[p]);
                #pragma unroll
                for (int gg = 0; gg < 3; gg++) {
                    float2 b = up2(red[(gg * 64 + cl) * 12 + p]);
                    a.x += b.x; a.y += b.y;
                }
                accO[p] = pk2(a.x, a.y);
            }
            int c = cl * 2;
            float* ob = g_cat + (size_t)i * 2112 + 576;
            #pragma unroll
            for (int p = 0; p < 6; p++) {
                int h0 = 2 * p, h1 = 2 * p + 1;
                float2 vc0 = up2(accO[p]);
                float2 vc1 = up2(accO[6 + p]);
                float s0 = Ssum[h0], s1 = Ssum[h1];
                *(float2*)(ob + h0 * 128 + c) = make_float2(vc0.x * s0, vc1.x * s0);
                *(float2*)(ob + h1 * 128 + c) = make_float2(vc0.y * s1, vc1.y * s1);
            }
        }
    }
}

// ---------------- o = (e@v)/S, o_pt = inv-frame((e@v_pts)/S) fused ----------
// 32-i tile, 128 threads, grid (24, 12) = 288 blocks (fully resident).
#define OV_AT   0                       // a_t [64 k][36]: 9216
#define OV_VS   9216                    // v_s [64 k][40]: 10240
#define OV_RED  19456                   // red 2*32*20 u64: 10240
#define OV_OPT  29696                   // opts [32][24]: 3072
#define OV_SMEM 32768

__global__ __launch_bounds__(128) void k_ov(const float* __restrict__ r_rot,
                                            const float* __restrict__ r_trans) {
    extern __shared__ __align__(16) unsigned char sm[];
    float* a_t  = (float*)(sm + OV_AT);
    float* v_s  = (float*)(sm + OV_VS);
    u64*   red  = (u64*)(sm + OV_RED);
    float* opts = (float*)(sm + OV_OPT);
    int i0 = blockIdx.x * 32;
    int h  = blockIdx.y;
    int t  = threadIdx.x;
    int rq = t & 7, cq = (t >> 3) & 3, ks = t >> 5;
    u64 acc[4][5] = {};
    for (int jt = 0; jt < 12; jt++) {
        #pragma unroll
        for (int l = 0; l < 16; l++) {
            int idx = t + l * 128;
            int r = idx >> 6, k = idx & 63;
            a_t[k * 36 + r] = g_logits[((size_t)(i0 + r) * NHD + h) * NRES + jt * 64 + k];
        }
        #pragma unroll
        for (int l = 0; l < 20; l++) {
            int idx = t + l * 128;
            v_s[idx] = g_vall[((size_t)(jt * 64 + idx / 40) * NHD + h) * 40 + idx % 40];
        }
        __syncthreads();
        #pragma unroll
        for (int kk = 0; kk < 16; kk++) {
            int k = ks * 16 + kk;
            float4 av = *(const float4*)(a_t + k * 36 + rq * 4);
            const u64* vv = (const u64*)(v_s + k * 40 + cq * 10);
            u64 v0 = vv[0], v1 = vv[1], v2 = vv[2], v3 = vv[3], v4 = vv[4];
            u64 a0 = dup2(av.x), a1 = dup2(av.y), a2 = dup2(av.z), a3 = dup2(av.w);
            ffma2(acc[0][0], a0, v0); ffma2(acc[0][1], a0, v1); ffma2(acc[0][2], a0, v2);
            ffma2(acc[0][3], a0, v3); ffma2(acc[0][4], a0, v4);
            ffma2(acc[1][0], a1, v0); ffma2(acc[1][1], a1, v1); ffma2(acc[1][2], a1, v2);
            ffma2(acc[1][3], a1, v3); ffma2(acc[1][4], a1, v4);
            ffma2(acc[2][0], a2, v0); ffma2(acc[2][1], a2, v1); ffma2(acc[2][2], a2, v2);
            ffma2(acc[2][3], a2, v3); ffma2(acc[2][4], a2, v4);
            ffma2(acc[3][0], a3, v0); ffma2(acc[3][1], a3, v1); ffma2(acc[3][2], a3, v2);
            ffma2(acc[3][3], a3, v3); ffma2(acc[3][4], a3, v4);
        }
        __syncthreads();
    }
    int slot = t & 31;
    if (ks >= 2) {
        u64* dst = red + ((ks - 2) * 32 + slot) * 20;
        #pragma unroll
        for (int rr = 0; rr < 4; rr++)
            #pragma unroll
            for (int p = 0; p < 5; p++) dst[rr * 5 + p] = acc[rr][p];
    }
    __syncthreads();
    if (ks < 2) {
        const u64* src = red + (ks * 32 + slot) * 20;
        #pragma unroll
        for (int rr = 0; rr < 4; rr++)
            #pragma unroll
            for (int p = 0; p < 5; p++) {
                float2 a = up2(acc[rr][p]), b = up2(src[rr * 5 + p]);
                acc[rr][p] = pk2(a.x + b.x, a.y + b.y);
            }
    }
    __syncthreads();
    if (ks == 1) {
        u64* dst = red + slot * 20;
        #pragma unroll
        for (int rr = 0; rr < 4; rr++)
            #pragma unroll
            for (int p = 0; p < 5; p++) dst[rr * 5 + p] = acc[rr][p];
    }
    __syncthreads();
    if (ks == 0) {
        const u64* src = red + slot * 20;
        #pragma unroll
        for (int rr = 0; rr < 4; rr++) {
            int rl = rq * 4 + rr;
            float inv = g_Sinv[(i0 + rl) * NHD + h];
            #pragma unroll
            for (int p = 0; p < 5; p++) {
                float2 a = up2(acc[rr][p]), b = up2(src[rr * 5 + p]);
                float vx = (a.x + b.x) * inv, vy = (a.y + b.y) * inv;
                int c0 = cq * 10 + 2 * p;
                if (c0 < 16)     g_cat[(size_t)(i0 + rl) * 2112 + h * 16 + c0] = vx;
                else             opts[rl * 24 + (c0 - 16)] = vx;
                int c1 = c0 + 1;
                if (c1 < 16)     g_cat[(size_t)(i0 + rl) * 2112 + h * 16 + c1] = vy;
                else             opts[rl * 24 + (c1 - 16)] = vy;
            }
        }
    }
    __syncthreads();
    for (int e2 = t; e2 < 256; e2 += 128) {
        int rl = e2 >> 3, pv = e2 & 7;
        int n = i0 + rl;
        const float* pp = opts + rl * 24 + pv * 3;
        float d0 = pp[0] - r_trans[n * 15 + 0];
        float d1 = pp[1] - r_trans[n * 15 + 1];
        float d2 = pp[2] - r_trans[n * 15 + 2];
        const float* R = r_rot + n * 45;
        float o0 = R[0] * d0 + R[3] * d1 + R[6] * d2;
        float o1 = R[1] * d0 + R[4] * d1 + R[7] * d2;
        float o2 = R[2] * d0 + R[5] * d1 + R[8] * d2;
        float nm = sqrtf(o0 * o0 + o1 * o1 + o2 * o2 + 1e-8f);
        float* cb = g_cat + (size_t)n * 2112 + 192;
        int rr2 = h * 8 + pv;
        cb[rr2] = o0; cb[96 + rr2] = o1; cb[192 + rr2] = o2; cb[288 + rr2] = nm;
    }
}

// ---------------- launch ----------------
extern "C" void kernel_launch(void* const* d_in, const int* in_sizes, int n_in,
                              void* d_out, int out_size) {
    const float* s       = (const float*)d_in[0];
    const float* z       = (const float*)d_in[1];
    const float* r_rot   = (const float*)d_in[2];
    const float* r_trans = (const float*)d_in[3];
    const float* mask    = (const float*)d_in[4];
    const float* wq      = (const float*)d_in[5];
    const float* bq      = (const float*)d_in[6];
    const float* wkv     = (const float*)d_in[7];
    const float* bkv     = (const float*)d_in[8];
    const float* wqp     = (const float*)d_in[9];
    const float* bqp     = (const float*)d_in[10];
    const float* wkvp    = (const float*)d_in[11];
    const float* bkvp    = (const float*)d_in[12];
    const float* wb      = (const float*)d_in[13];
    const float* head_w  = (const float*)d_in[15];
    const float* wout    = (const float*)d_in[16];
    const float* bout    = (const float*)d_in[17];
    const float* wexp    = (const float*)d_in[18];
    const float* bexp    = (const float*)d_in[19];
    const float* ln_g    = (const float*)d_in[20];
    const float* ln_b    = (const float*)d_in[21];
    float* out = (float*)d_out;

    float *p_cat = nullptr, *p_part = nullptr;
    cudaGetSymbolAddress((void**)&p_cat,  g_cat);
    cudaGetSymbolAddress((void**)&p_part, g_part);

    static int attn_cfg = 0;
    if (!attn_cfg) {
        cudaFuncSetAttribute(k_zattn, cudaFuncAttributeMaxDynamicSharedMemorySize, ZAT_SMEM);
        cudaFuncSetAttribute(k_ov, cudaFuncAttributeMaxDynamicSharedMemorySize, OV_SMEM);
        attn_cfg = 1;
    }

    // se partials (split-K=2), LN fuses combine+bias
    k_gemm64<<<dim3(6, 12, 2), 256>>>(s, wexp, nullptr, p_part, 384, 384, 12, 0, NRES * CSD);
    k_ln<<<768, 128>>>(bexp, ln_g, ln_b);
    k_gemm_proj<<<dim3(18, 12), 256>>>(wq, bq, wkv, bkv, wqp, bqp, wkvp, bkvp);
    k_assemble<<<96, 256>>>(r_rot, r_trans, head_w);
    k_qk<<<dim3(12, 12, 12), 256>>>(mask);
    k_zattn<<<768, 256, ZAT_SMEM>>>(z, wb);
    k_ov<<<dim3(24, 12), 128, OV_SMEM>>>(r_rot, r_trans);
    k_gemm64<<<dim3(6, 12, 4), 256>>>(p_cat, wout, nullptr, p_part, 2112, 384, 33, 0, NRES * CSD);
    k_combine<<<1152, 256>>>(bout, out);
}

// round 15
// speedup vs baseline: 1.3689x; 1.0827x over previous
#include <cuda_runtime.h>
#include <math.h>

#define NRES 768
#define CSD  384
#define CZD  128
#define NHD  12
#define INF_ 100000.0f

typedef unsigned long long u64;

// ---------------- packed f32x2 helpers ----------------
__device__ __forceinline__ void ffma2(u64& d, u64 a, u64 b) {
    asm("fma.rn.f32x2 %0, %1, %2, %0;" : "+l"(d) : "l"(a), "l"(b));
}
__device__ __forceinline__ u64 dup2(float x) {
    u64 r; asm("mov.b64 %0, {%1, %1};" : "=l"(r) : "f"(x)); return r;
}
__device__ __forceinline__ u64 pk2(float lo, float hi) {
    u64 r; asm("mov.b64 %0, {%1, %2};" : "=l"(r) : "f"(lo), "f"(hi)); return r;
}
__device__ __forceinline__ float2 up2(u64 v) {
    float lo, hi; asm("mov.b64 {%0, %1}, %2;" : "=f"(lo), "=f"(hi) : "l"(v));
    return make_float2(lo, hi);
}
// ---------------- cp.async helpers ----------------
__device__ __forceinline__ void cpa16(void* dst, const void* src) {
    unsigned sdst = (unsigned)__cvta_generic_to_shared(dst);
    asm volatile("cp.async.cg.shared.global [%0], [%1], 16;" :: "r"(sdst), "l"(src));
}
__device__ __forceinline__ void cpa_commit() { asm volatile("cp.async.commit_group;"); }
__device__ __forceinline__ void cpa_wait1() { asm volatile("cp.async.wait_group 1;"); }
__device__ __forceinline__ void cpa_wait0() { asm volatile("cp.async.wait_group 0;"); }

// ---------------- scratch (device globals; no allocation) ----------------
__device__ float g_se[NRES * CSD];
__device__ float g_proj[NRES * 1152];
__device__ float g_qhat[NRES * 336];
__device__ float g_khat[NRES * 336];
__device__ float g_kc[NRES * NHD];
__device__ float g_vall[NRES * NHD * 40];
__device__ float g_cat[NRES * 2112];
__device__ float g_part[4][NRES * CSD];
__device__ float g_logits[NHD * NRES * NRES]; // [i][h][j]: qk-logits, then unnormalized exp
__device__ float g_Sinv[NRES * NHD];          // 1/S per (i,h)

// =====================================================================
// fp32 GEMM with FFMA2: C = A(MxK) @ W(NxK)^T [+ bias]; 64x64 tile, BK=16.
// =====================================================================
__device__ __forceinline__ void mm16(const float* Ab, const float* Wb,
                                     int ty, int tx, u64 acc2[4][2]) {
    #pragma unroll
    for (int k = 0; k < 16; k++) {
        float4 av = *(const float4*)(Ab + k * 68 + ty * 4);
        ulonglong2 wv = *(const ulonglong2*)(Wb + k * 68 + tx * 4);
        u64 a0 = dup2(av.x), a1 = dup2(av.y), a2 = dup2(av.z), a3 = dup2(av.w);
        ffma2(acc2[0][0], a0, wv.x); ffma2(acc2[0][1], a0, wv.y);
        ffma2(acc2[1][0], a1, wv.x); ffma2(acc2[1][1], a1, wv.y);
        ffma2(acc2[2][0], a2, wv.x); ffma2(acc2[2][1], a2, wv.y);
        ffma2(acc2[3][0], a3, wv.x); ffma2(acc2[3][1], a3, wv.y);
    }
}

__global__ __launch_bounds__(256) void k_gemm64(
    const float* __restrict__ A, const float* __restrict__ W,
    const float* __restrict__ bias, float* __restrict__ C,
    int ld, int ldc, int nkt, int add_bias, int partStride)
{
    __shared__ __align__(16) float As[2][16][68];
    __shared__ __align__(16) float Ws[2][16][68];
    int t  = threadIdx.x;
    int m0 = blockIdx.y * 64, n0 = blockIdx.x * 64;
    int kt0 = blockIdx.z * nkt;
    C += (size_t)blockIdx.z * partStride;
    int lr = t >> 2, lk = (t & 3) * 4;
    const float* arow = A + (size_t)(m0 + lr) * ld + kt0 * 16 + lk;
    const float* wrow = W + (size_t)(n0 + lr) * ld + kt0 * 16 + lk;
    int tx = t & 15, ty = t >> 4;

    u64 acc2[4][2] = {};
    float4 ra = *(const float4*)arow;
    float4 rw = *(const float4*)wrow;
    int buf = 0;
    As[0][lk+0][lr]=ra.x; As[0][lk+1][lr]=ra.y; As[0][lk+2][lr]=ra.z; As[0][lk+3][lr]=ra.w;
    Ws[0][lk+0][lr]=rw.x; Ws[0][lk+1][lr]=rw.y; Ws[0][lk+2][lr]=rw.z; Ws[0][lk+3][lr]=rw.w;

    for (int kt = 0; kt < nkt - 1; kt++) {
        __syncthreads();
        ra = *(const float4*)(arow + (kt + 1) * 16);
        rw = *(const float4*)(wrow + (kt + 1) * 16);
        mm16(&As[buf][0][0], &Ws[buf][0][0], ty, tx, acc2);
        int nb = buf ^ 1;
        As[nb][lk+0][lr]=ra.x; As[nb][lk+1][lr]=ra.y; As[nb][lk+2][lr]=ra.z; As[nb][lk+3][lr]=ra.w;
        Ws[nb][lk+0][lr]=rw.x; Ws[nb][lk+1][lr]=rw.y; Ws[nb][lk+2][lr]=rw.z; Ws[nb][lk+3][lr]=rw.w;
        buf = nb;
    }
    __syncthreads();
    mm16(&As[buf][0][0], &Ws[buf][0][0], ty, tx, acc2);

    float4 bv = make_float4(0.f, 0.f, 0.f, 0.f);
    if (add_bias) bv = *(const float4*)(bias + n0 + tx * 4);
    #pragma unroll
    for (int a = 0; a < 4; a++) {
        float2 p0 = up2(acc2[a][0]), p1 = up2(acc2[a][1]);
        float4 r = make_float4(p0.x + bv.x, p0.y + bv.y, p1.x + bv.z, p1.y + bv.w);
        *(float4*)(C + (size_t)(m0 + ty * 4 + a) * ldc + n0 + tx * 4) = r;
    }
}

__device__ __forceinline__ float proj_bias(int n, const float* bq, const float* bkv,
                                           const float* bqp, const float* bkvp) {
    if (n < 192) return bq[n];
    if (n < 576) return bkv[n - 192];
    if (n < 720) return bqp[n - 576];
    return bkvp[n - 720];
}

__global__ __launch_bounds__(256) void k_gemm_proj(
    const float* __restrict__ wq,  const float* __restrict__ bq,
    const float* __restrict__ wkv, const float* __restrict__ bkv,
    const float* __restrict__ wqp, const float* __restrict__ bqp,
    const float* __restrict__ wkvp,const float* __restrict__ bkvp)
{
    __shared__ __align__(16) float As[2][16][68];
    __shared__ __align__(16) float Ws[2][16][68];
    int t  = threadIdx.x;
    int m0 = blockIdx.y * 64, n0 = blockIdx.x * 64;
    int lr = t >> 2, lk = (t & 3) * 4;
    const float* arow = g_se + (size_t)(m0 + lr) * 384 + lk;
    int n = n0 + lr;
    const float* wbase; int nl;
    if      (n < 192) { wbase = wq;   nl = n; }
    else if (n < 576) { wbase = wkv;  nl = n - 192; }
    else if (n < 720) { wbase = wqp;  nl = n - 576; }
    else              { wbase = wkvp; nl = n - 720; }
    const float* wrow = wbase + (size_t)nl * 384 + lk;
    int tx = t & 15, ty = t >> 4;

    u64 acc2[4][2] = {};
    float4 ra = *(const float4*)arow;
    float4 rw = *(const float4*)wrow;
    int buf = 0;
    As[0][lk+0][lr]=ra.x; As[0][lk+1][lr]=ra.y; As[0][lk+2][lr]=ra.z; As[0][lk+3][lr]=ra.w;
    Ws[0][lk+0][lr]=rw.x; Ws[0][lk+1][lr]=rw.y; Ws[0][lk+2][lr]=rw.z; Ws[0][lk+3][lr]=rw.w;

    const int nkt = 24;
    for (int kt = 0; kt < nkt - 1; kt++) {
        __syncthreads();
        ra = *(const float4*)(arow + (kt + 1) * 16);
        rw = *(const float4*)(wrow + (kt + 1) * 16);
        mm16(&As[buf][0][0], &Ws[buf][0][0], ty, tx, acc2);
        int nb = buf ^ 1;
        As[nb][lk+0][lr]=ra.x; As[nb][lk+1][lr]=ra.y; As[nb][lk+2][lr]=ra.z; As[nb][lk+3][lr]=ra.w;
        Ws[nb][lk+0][lr]=rw.x; Ws[nb][lk+1][lr]=rw.y; Ws[nb][lk+2][lr]=rw.z; Ws[nb][lk+3][lr]=rw.w;
        buf = nb;
    }
    __syncthreads();
    mm16(&As[buf][0][0], &Ws[buf][0][0], ty, tx, acc2);

    int nc = n0 + tx * 4;
    float4 bv = make_float4(proj_bias(nc + 0, bq, bkv, bqp, bkvp),
                            proj_bias(nc + 1, bq, bkv, bqp, bkvp),
                            proj_bias(nc + 2, bq, bkv, bqp, bkvp),
                            proj_bias(nc + 3, bq, bkv, bqp, bkvp));
    #pragma unroll
    for (int a = 0; a < 4; a++) {
        float2 p0 = up2(acc2[a][0]), p1 = up2(acc2[a][1]);
        float4 r = make_float4(p0.x + bv.x, p0.y + bv.y, p1.x + bv.z, p1.y + bv.w);
        *(float4*)(g_proj + (size_t)(m0 + ty * 4 + a) * 1152 + nc) = r;
    }
}

__global__ void k_combine(const float* __restrict__ bout, float* __restrict__ out) {
    int i = blockIdx.x * 256 + threadIdx.x;
    out[i] = g_part[0][i] + g_part[1][i] + g_part[2][i] + g_part[3][i] + bout[i % 384];
}

// ---------------- LayerNorm over split-K partials (se = LN(part0+part1+bias)) ---
__global__ void k_ln(const float* __restrict__ bexp,
                     const float* __restrict__ gamma, const float* __restrict__ beta) {
    int n = blockIdx.x, t = threadIdx.x;
    const float* P0 = g_part[0] + (size_t)n * CSD;
    const float* P1 = g_part[1] + (size_t)n * CSD;
    float x0 = P0[t]       + P1[t]       + bexp[t];
    float x1 = P0[t + 128] + P1[t + 128] + bexp[t + 128];
    float x2 = P0[t + 256] + P1[t + 256] + bexp[t + 256];
    float s1 = x0 + x1 + x2;
    float s2 = x0 * x0 + x1 * x1 + x2 * x2;
    __shared__ float r1[4], r2[4];
    #pragma unroll
    for (int o = 16; o; o >>= 1) {
        s1 += __shfl_xor_sync(0xffffffffu, s1, o);
        s2 += __shfl_xor_sync(0xffffffffu, s2, o);
    }
    if ((t & 31) == 0) { r1[t >> 5] = s1; r2[t >> 5] = s2; }
    __syncthreads();
    float ts1 = r1[0] + r1[1] + r1[2] + r1[3];
    float ts2 = r2[0] + r2[1] + r2[2] + r2[3];
    float mu  = ts1 * (1.f / 384.f);
    float var = ts2 * (1.f / 384.f) - mu * mu;
    float inv = rsqrtf(var + 1e-5f);
    float* row = g_se + (size_t)n * CSD;
    row[t]       = (x0 - mu) * inv * gamma[t]       + beta[t];
    row[t + 128] = (x1 - mu) * inv * gamma[t + 128] + beta[t + 128];
    row[t + 256] = (x2 - mu) * inv * gamma[t + 256] + beta[t + 256];
}

// ---------------- assemble qhat/khat/kc/v/v_pts (warp per n) ----------------
__global__ void k_assemble(const float* __restrict__ r_rot, const float* __restrict__ r_trans,
                           const float* __restrict__ head_w) {
    int gw   = blockIdx.x * 8 + (threadIdx.x >> 5);
    int lane = threadIdx.x & 31;
    if (gw >= NRES || lane >= NHD) return;
    int n = gw, h = lane;
    float rot[9], t0[3];
    #pragma unroll
    for (int i = 0; i < 9; i++) rot[i] = r_rot[n * 45 + i];
    #pragma unroll
    for (int i = 0; i < 3; i++) t0[i] = r_trans[n * 15 + i];
    float hw = log1pf(expf(head_w[h])) * rsqrtf(54.0f);
    const float c1 = rsqrtf(48.0f);
    const float* P = g_proj + (size_t)n * 1152;
    float* qh = g_qhat + (size_t)n * 336 + h * 28;
    float* kh = g_khat + (size_t)n * 336 + h * 28;
    float* va = g_vall + ((size_t)n * NHD + h) * 40;
    #pragma unroll
    for (int c = 0; c < 16; c++) {
        qh[c] = c1 * P[h * 16 + c];
        kh[c] = P[192 + h * 32 + c];
        va[c] = P[192 + h * 32 + 16 + c];
    }
    #pragma unroll
    for (int pp = 0; pp < 4; pp++) {
        float l0 = P[576 +   0 + h * 4 + pp];
        float l1 = P[576 +  48 + h * 4 + pp];
        float l2 = P[576 +  96 + h * 4 + pp];
        #pragma unroll
        for (int i = 0; i < 3; i++) {
            float o = rot[i * 3] * l0 + rot[i * 3 + 1] * l1 + rot[i * 3 + 2] * l2 + t0[i];
            qh[16 + pp * 3 + i] = hw * o;
        }
    }
    float kc = 0.f;
    #pragma unroll
    for (int pp = 0; pp < 4; pp++) {
        float l0 = P[720 +   0 + h * 12 + pp];
        float l1 = P[720 + 144 + h * 12 + pp];
        float l2 = P[720 + 288 + h * 12 + pp];
        #pragma unroll
        for (int i = 0; i < 3; i++) {
            float o = rot[i * 3] * l0 + rot[i * 3 + 1] * l1 + rot[i * 3 + 2] * l2 + t0[i];
            kh[16 + pp * 3 + i] = o;
            kc += o * o;
        }
    }
    g_kc[n * NHD + h] = -0.5f * hw * kc;
    #pragma unroll
    for (int pv = 0; pv < 8; pv++) {
        int pp = 4 + pv;
        float l0 = P[720 +   0 + h * 12 + pp];
        float l1 = P[720 + 144 + h * 12 + pp];
        float l2 = P[720 + 288 + h * 12 + pp];
        #pragma unroll
        for (int i = 0; i < 3; i++) {
            float o = rot[i * 3] * l0 + rot[i * 3 + 1] * l1 + rot[i * 3 + 2] * l2 + t0[i];
            va[16 + pv * 3 + i] = o;
        }
    }
}

// ---------------- qk logits (K=28 GEMM) + kc + mask per head ----------------
__global__ __launch_bounds__(256) void k_qk(const float* __restrict__ mask) {
    __shared__ __align__(16) float Qs[28][68];
    __shared__ __align__(16) float Ks[28][68];
    __shared__ float kcs[64], uli[64], ulj[64];
    int h = blockIdx.z, i0 = blockIdx.y * 64, j0 = blockIdx.x * 64;
    int t = threadIdx.x;
    for (int idx = t; idx < 64 * 28; idx += 256) {
        int m = idx / 28, k = idx % 28;
        Qs[k][m] = g_qhat[(size_t)(i0 + m) * 336 + h * 28 + k];
        Ks[k][m] = g_khat[(size_t)(j0 + m) * 336 + h * 28 + k];
    }
    if (t < 64) {
        kcs[t] = g_kc[(j0 + t) * NHD + h];
        uli[t] = mask[(i0 + t) * 5];
        ulj[t] = mask[(j0 + t) * 5];
    }
    __syncthreads();
    int tx = t & 15, ty = t >> 4;
    u64 acc2[4][2] = {};
    #pragma unroll
    for (int k = 0; k < 28; k++) {
        float4 av = *(const float4*)(&Qs[k][ty * 4]);
        ulonglong2 wv = *(const ulonglong2*)(&Ks[k][tx * 4]);
        u64 a0 = dup2(av.x), a1 = dup2(av.y), a2 = dup2(av.z), a3 = dup2(av.w);
        ffma2(acc2[0][0], a0, wv.x); ffma2(acc2[0][1], a0, wv.y);
        ffma2(acc2[1][0], a1, wv.x); ffma2(acc2[1][1], a1, wv.y);
        ffma2(acc2[2][0], a2, wv.x); ffma2(acc2[2][1], a2, wv.y);
        ffma2(acc2[3][0], a3, wv.x); ffma2(acc2[3][1], a3, wv.y);
    }
    int jb = tx * 4;
    #pragma unroll
    for (int a = 0; a < 4; a++) {
        int i = i0 + ty * 4 + a;
        float mi = uli[ty * 4 + a];
        float2 p0 = up2(acc2[a][0]), p1 = up2(acc2[a][1]);
        float4 r;
        r.x = p0.x + kcs[jb + 0] + INF_ * (mi * ulj[jb + 0] - 1.f);
        r.y = p0.y + kcs[jb + 1] + INF_ * (mi * ulj[jb + 1] - 1.f);
        r.z = p1.x + kcs[jb + 2] + INF_ * (mi * ulj[jb + 2] - 1.f);
        r.w = p1.y + kcs[jb + 3] + INF_ * (mi * ulj[jb + 3] - 1.f);
        *(float4*)(&g_logits[((size_t)i * NHD + h) * NRES + j0 + jb]) = r;
    }
}

// ---------------- persistent fused z-pass per i: bias + exp + S + o_pair ----
#define ZT_STRIDE 132
#define ZTILE (64 * ZT_STRIDE)
#define ZAT_ES   (2 * ZTILE * 4)                 // 67584
#define ZAT_WB2  (ZAT_ES + 64 * 12 * 4)          // 70656
#define ZAT_PH   (ZAT_WB2 + 128 * 6 * 8)         // 76800
#define ZAT_SS   (ZAT_PH + 256 * 12 * 8)         // 101376
#define ZAT_SMEM (ZAT_SS + 64)                   // 101440

__global__ __launch_bounds__(256) void k_zattn(const float* __restrict__ z,
                                               const float* __restrict__ wb) {
    extern __shared__ __align__(16) unsigned char smraw[];
    float* zs  = (float*)smraw;
    float* es  = (float*)(smraw + ZAT_ES);
    u64*   wb2 = (u64*)(smraw + ZAT_WB2);
    u64*   ph  = (u64*)(smraw + ZAT_PH);
    float* Ssum= (float*)(smraw + ZAT_SS);

    int i = blockIdx.x;
    int t = threadIdx.x;
    int lane = t & 31, warp = t >> 5;
    const float c2 = 0.57735026918962576f;  // sqrt(1/3)

    for (int e = t; e < 768; e += 256) {
        int c = e / 6, p = e % 6;
        wb2[e] = pk2(c2 * wb[(2 * p) * 128 + c], c2 * wb[(2 * p + 1) * 128 + c]);
    }

    const float4* zbase = (const float4*)(z + (size_t)i * NRES * CZD);
    #pragma unroll
    for (int l = 0; l < 8; l++) {
        int idx = t + l * 256;
        cpa16(zs + (idx >> 5) * ZT_STRIDE + (idx & 31) * 4, zbase + idx);
    }
    cpa_commit();

    u64 accO[12] = {};
    float sacc[2] = {0.f, 0.f};
    int buf = 0;

    for (int jt = 0; jt < 12; jt++) {
        __syncthreads();
        if (jt < 11) {
            float* zb = zs + (buf ^ 1) * ZTILE;
            const float4* zrow = zbase + (jt + 1) * 2048;
            #pragma unroll
            for (int l = 0; l < 8; l++) {
                int idx = t + l * 256;
                cpa16(zb + (idx >> 5) * ZT_STRIDE + (idx & 31) * 4, zrow + idx);
            }
            cpa_commit();
            cpa_wait1();
        } else {
            cpa_wait0();
        }
        __syncthreads();
        const float* zt = zs + buf * ZTILE;

        // phase 1: 2 j rows per thread (ja = t&31, jb = ja+32), 16-c eighth q8 = t>>5
        {
            int ja = t & 31, q8 = t >> 5;
            const float* zja = zt + ja * ZT_STRIDE + q8 * 16;
            const float* zjb = zja + 32 * ZT_STRIDE;
            u64 acc[12] = {};
            #pragma unroll
            for (int c4 = 0; c4 < 4; c4++) {
                float va[4], vb[4];
                *(float4*)va = *(const float4*)(zja + c4 * 4);
                *(float4*)vb = *(const float4*)(zjb + c4 * 4);
                int cb = (q8 * 16 + c4 * 4) * 6;
                #pragma unroll
                for (int cc = 0; cc < 4; cc++) {
                    u64 za = dup2(va[cc]), zb2 = dup2(vb[cc]);
                    ulonglong2 wA = *(const ulonglong2*)(wb2 + cb + cc * 6);
                    ulonglong2 wB = *(const ulonglong2*)(wb2 + cb + cc * 6 + 2);
                    ulonglong2 wC = *(const ulonglong2*)(wb2 + cb + cc * 6 + 4);
                    ffma2(acc[0], za, wA.x);  ffma2(acc[1], za, wA.y);
                    ffma2(acc[2], za, wB.x);  ffma2(acc[3], za, wB.y);
                    ffma2(acc[4], za, wC.x);  ffma2(acc[5], za, wC.y);
                    ffma2(acc[6], zb2, wA.x); ffma2(acc[7], zb2, wA.y);
                    ffma2(acc[8], zb2, wB.x); ffma2(acc[9], zb2, wB.y);
                    ffma2(acc[10], zb2, wC.x); ffma2(acc[11], zb2, wC.y);
                }
            }
            #pragma unroll
            for (int p = 0; p < 12; p++) ph[t * 12 + p] = acc[p];
        }
        __syncthreads();

        // combine 8 c-eighths + qk logits + exp (spread over 192 threads:
        // j = t&63, pg = t>>6 in {0,1,2}, each handles head-pairs 2pg, 2pg+1)
        if (t < 192) {
            int j = t & 63, pg = t >> 6;
            int j0 = jt * 64;
            int jj2 = j & 31, sub = (j >> 5) * 6;
            #pragma unroll
            for (int pp2 = 0; pp2 < 2; pp2++) {
                int p = pg * 2 + pp2;
                float sx = 0.f, sy = 0.f;
                #pragma unroll
                for (int q8 = 0; q8 < 8; q8++) {
                    float2 v = up2(ph[(q8 * 32 + jj2) * 12 + sub + p]);
                    sx += v.x; sy += v.y;
                }
                int h0 = 2 * p, h1 = 2 * p + 1;
                size_t gi0 = ((size_t)i * NHD + h0) * NRES + j0 + j;
                size_t gi1 = ((size_t)i * NHD + h1) * NRES + j0 + j;
                float e0 = __expf(g_logits[gi0] + sx);
                float e1 = __expf(g_logits[gi1] + sy);
                g_logits[gi0] = e0; g_logits[gi1] = e1;
                es[j * 12 + h0] = e0; es[j * 12 + h1] = e1;
            }
        }
        __syncthreads();

        // partial S per head
        {
            int cnt = 0;
            for (int h = warp; h < NHD; h += 8, cnt++) {
                float s = es[lane * 12 + h] + es[(lane + 32) * 12 + h];
                #pragma unroll
                for (int o = 16; o; o >>= 1) s += __shfl_xor_sync(0xffffffffu, s, o);
                sacc[cnt] += s;
            }
        }

        // phase 2: 2 c per thread (c = (t&63)*2), 16-j quarter g = t>>6
        {
            int c = (t & 63) * 2, g = t >> 6;
            #pragma unroll 4
            for (int jj = 0; jj < 16; jj++) {
                int j = g * 16 + jj;
                float2 zv = *(const float2*)(zt + j * ZT_STRIDE + c);
                u64 zd0 = dup2(zv.x), zd1 = dup2(zv.y);
                const ulonglong2* aj = (const ulonglong2*)(es + j * 12);
                ulonglong2 a0 = aj[0], a1 = aj[1], a2 = aj[2];
                ffma2(accO[0], zd0, a0.x); ffma2(accO[1], zd0, a0.y);
                ffma2(accO[2], zd0, a1.x); ffma2(accO[3], zd0, a1.y);
                ffma2(accO[4], zd0, a2.x); ffma2(accO[5], zd0, a2.y);
                ffma2(accO[6], zd1, a0.x); ffma2(accO[7], zd1, a0.y);
                ffma2(accO[8], zd1, a1.x); ffma2(accO[9], zd1, a1.y);
                ffma2(accO[10], zd1, a2.x); ffma2(accO[11], zd1, a2.y);
            }
        }
        buf ^= 1;
    }

    // finalize S
    if (lane == 0) {
        int cnt = 0;
        for (int h = warp; h < NHD; h += 8, cnt++) Ssum[h] = sacc[cnt];
    }
    __syncthreads();
    if (t < NHD) {
        float inv = 1.0f / Ssum[t];
        Ssum[t] = inv;
        g_Sinv[i * NHD + t] = inv;
    }
    __syncthreads();

    // reduce o_pair across 4 j-groups, normalize, write
    {
        u64* red = (u64*)zs;
        int cl = t & 63, g = t >> 6;
        if (g > 0) {
            u64* dst = red + ((g - 1) * 64 + cl) * 12;
            #pragma unroll
            for (int p = 0; p < 12; p++) dst[p] = accO[p];
        }
        __syncthreads();
        if (g == 0) {
            #pragma unroll
            for (int p = 0; p < 12; p++) {
                float2 a = up2(accO[p]);
                #pragma unroll
                for (int gg = 0; gg < 3; gg++) {
                    float2 b = up2(red[(gg * 64 + cl) * 12 + p]);
                    a.x += b.x; a.y += b.y;
                }
                accO[p] = pk2(a.x, a.y);
            }
            int c = cl * 2;
            float* ob = g_cat + (size_t)i * 2112 + 576;
            #pragma unroll
            for (int p = 0; p < 6; p++) {
                int h0 = 2 * p, h1 = 2 * p + 1;
                float2 vc0 = up2(accO[p]);
                float2 vc1 = up2(accO[6 + p]);
                float s0 = Ssum[h0], s1 = Ssum[h1];
                *(float2*)(ob + h0 * 128 + c) = make_float2(vc0.x * s0, vc1.x * s0);
                *(float2*)(ob + h1 * 128 + c) = make_float2(vc0.y * s1, vc1.y * s1);
            }
        }
    }
}

// ---------------- o = (e@v)/S, o_pt = inv-frame((e@v_pts)/S) fused ----------
// 32-i tile, 128 threads, grid (24, 12) = 288 blocks (fully resident).
#define OV_AT   0                       // a_t [64 k][36]: 9216
#define OV_VS   9216                    // v_s [64 k][40]: 10240
#define OV_RED  19456                   // red 2*32*20 u64: 10240
#define OV_OPT  29696                   // opts [32][24]: 3072
#define OV_SMEM 32768

__global__ __launch_bounds__(128) void k_ov(const float* __restrict__ r_rot,
                                            const float* __restrict__ r_trans) {
    extern __shared__ __align__(16) unsigned char sm[];
    float* a_t  = (float*)(sm + OV_AT);
    float* v_s  = (float*)(sm + OV_VS);
    u64*   red  = (u64*)(sm + OV_RED);
    float* opts = (float*)(sm + OV_OPT);
    int i0 = blockIdx.x * 32;
    int h  = blockIdx.y;
    int t  = threadIdx.x;
    int rq = t & 7, cq = (t >> 3) & 3, ks = t >> 5;
    u64 acc[4][5] = {};
    for (int jt = 0; jt < 12; jt++) {
        #pragma unroll
        for (int l = 0; l < 16; l++) {
            int idx = t + l * 128;
            int r = idx >> 6, k = idx & 63;
            a_t[k * 36 + r] = g_logits[((size_t)(i0 + r) * NHD + h) * NRES + jt * 64 + k];
        }
        #pragma unroll
        for (int l = 0; l < 20; l++) {
            int idx = t + l * 128;
            v_s[idx] = g_vall[((size_t)(jt * 64 + idx / 40) * NHD + h) * 40 + idx % 40];
        }
        __syncthreads();
        #pragma unroll
        for (int kk = 0; kk < 16; kk++) {
            int k = ks * 16 + kk;
            float4 av = *(const float4*)(a_t + k * 36 + rq * 4);
            const u64* vv = (const u64*)(v_s + k * 40 + cq * 10);
            u64 v0 = vv[0], v1 = vv[1], v2 = vv[2], v3 = vv[3], v4 = vv[4];
            u64 a0 = dup2(av.x), a1 = dup2(av.y), a2 = dup2(av.z), a3 = dup2(av.w);
            ffma2(acc[0][0], a0, v0); ffma2(acc[0][1], a0, v1); ffma2(acc[0][2], a0, v2);
            ffma2(acc[0][3], a0, v3); ffma2(acc[0][4], a0, v4);
            ffma2(acc[1][0], a1, v0); ffma2(acc[1][1], a1, v1); ffma2(acc[1][2], a1, v2);
            ffma2(acc[1][3], a1, v3); ffma2(acc[1][4], a1, v4);
            ffma2(acc[2][0], a2, v0); ffma2(acc[2][1], a2, v1); ffma2(acc[2][2], a2, v2);
            ffma2(acc[2][3], a2, v3); ffma2(acc[2][4], a2, v4);
            ffma2(acc[3][0], a3, v0); ffma2(acc[3][1], a3, v1); ffma2(acc[3][2], a3, v2);
            ffma2(acc[3][3], a3, v3); ffma2(acc[3][4], a3, v4);
        }
        __syncthreads();
    }
    int slot = t & 31;
    if (ks >= 2) {
        u64* dst = red + ((ks - 2) * 32 + slot) * 20;
        #pragma unroll
        for (int rr = 0; rr < 4; rr++)
            #pragma unroll
            for (int p = 0; p < 5; p++) dst[rr * 5 + p] = acc[rr][p];
    }
    __syncthreads();
    if (ks < 2) {
        const u64* src = red + (ks * 32 + slot) * 20;
        #pragma unroll
        for (int rr = 0; rr < 4; rr++)
            #pragma unroll
            for (int p = 0; p < 5; p++) {
                float2 a = up2(acc[rr][p]), b = up2(src[rr * 5 + p]);
                acc[rr][p] = pk2(a.x + b.x, a.y + b.y);
            }
    }
    __syncthreads();
    if (ks == 1) {
        u64* dst = red + slot * 20;
        #pragma unroll
        for (int rr = 0; rr < 4; rr++)
            #pragma unroll
            for (int p = 0; p < 5; p++) dst[rr * 5 + p] = acc[rr][p];
    }
    __syncthreads();
    if (ks == 0) {
        const u64* src = red + slot * 20;
        #pragma unroll
        for (int rr = 0; rr < 4; rr++) {
            int rl = rq * 4 + rr;
            float inv = g_Sinv[(i0 + rl) * NHD + h];
            #pragma unroll
            for (int p = 0; p < 5; p++) {
                float2 a = up2(acc[rr][p]), b = up2(src[rr * 5 + p]);
                float vx = (a.x + b.x) * inv, vy = (a.y + b.y) * inv;
                int c0 = cq * 10 + 2 * p;
                if (c0 < 16)     g_cat[(size_t)(i0 + rl) * 2112 + h * 16 + c0] = vx;
                else             opts[rl * 24 + (c0 - 16)] = vx;
                int c1 = c0 + 1;
                if (c1 < 16)     g_cat[(size_t)(i0 + rl) * 2112 + h * 16 + c1] = vy;
                else             opts[rl * 24 + (c1 - 16)] = vy;
            }
        }
    }
    __syncthreads();
    for (int e2 = t; e2 < 256; e2 += 128) {
        int rl = e2 >> 3, pv = e2 & 7;
        int n = i0 + rl;
        const float* pp = opts + rl * 24 + pv * 3;
        float d0 = pp[0] - r_trans[n * 15 + 0];
        float d1 = pp[1] - r_trans[n * 15 + 1];
        float d2 = pp[2] - r_trans[n * 15 + 2];
        const float* R = r_rot + n * 45;
        float o0 = R[0] * d0 + R[3] * d1 + R[6] * d2;
        float o1 = R[1] * d0 + R[4] * d1 + R[7] * d2;
        float o2 = R[2] * d0 + R[5] * d1 + R[8] * d2;
        float nm = sqrtf(o0 * o0 + o1 * o1 + o2 * o2 + 1e-8f);
        float* cb = g_cat + (size_t)n * 2112 + 192;
        int rr2 = h * 8 + pv;
        cb[rr2] = o0; cb[96 + rr2] = o1; cb[192 + rr2] = o2; cb[288 + rr2] = nm;
    }
}

// ---------------- launch ----------------
extern "C" void kernel_launch(void* const* d_in, const int* in_sizes, int n_in,
                              void* d_out, int out_size) {
    const float* s       = (const float*)d_in[0];
    const float* z       = (const float*)d_in[1];
    const float* r_rot   = (const float*)d_in[2];
    const float* r_trans = (const float*)d_in[3];
    const float* mask    = (const float*)d_in[4];
    const float* wq      = (const float*)d_in[5];
    const float* bq      = (const float*)d_in[6];
    const float* wkv     = (const float*)d_in[7];
    const float* bkv     = (const float*)d_in[8];
    const float* wqp     = (const float*)d_in[9];
    const float* bqp     = (const float*)d_in[10];
    const float* wkvp    = (const float*)d_in[11];
    const float* bkvp    = (const float*)d_in[12];
    const float* wb      = (const float*)d_in[13];
    const float* head_w  = (const float*)d_in[15];
    const float* wout    = (const float*)d_in[16];
    const float* bout    = (const float*)d_in[17];
    const float* wexp    = (const float*)d_in[18];
    const float* bexp    = (const float*)d_in[19];
    const float* ln_g    = (const float*)d_in[20];
    const float* ln_b    = (const float*)d_in[21];
    float* out = (float*)d_out;

    float *p_cat = nullptr, *p_part = nullptr;
    cudaGetSymbolAddress((void**)&p_cat,  g_cat);
    cudaGetSymbolAddress((void**)&p_part, g_part);

    static int attn_cfg = 0;
    if (!attn_cfg) {
        cudaFuncSetAttribute(k_zattn, cudaFuncAttributeMaxDynamicSharedMemorySize, ZAT_SMEM);
        cudaFuncSetAttribute(k_ov, cudaFuncAttributeMaxDynamicSharedMemorySize, OV_SMEM);
        attn_cfg = 1;
    }

    k_gemm64<<<dim3(6, 12, 2), 256>>>(s, wexp, nullptr, p_part, 384, 384, 12, 0, NRES * CSD);
    k_ln<<<768, 128>>>(bexp, ln_g, ln_b);
    k_gemm_proj<<<dim3(18, 12), 256>>>(wq, bq, wkv, bkv, wqp, bqp, wkvp, bkvp);
    k_assemble<<<96, 256>>>(r_rot, r_trans, head_w);
    k_qk<<<dim3(12, 12, 12), 256>>>(mask);
    k_zattn<<<768, 256, ZAT_SMEM>>>(z, wb);
    k_ov<<<dim3(24, 12), 128, OV_SMEM>>>(r_rot, r_trans);
    k_gemm64<<<dim3(6, 12, 4), 256>>>(p_cat, wout, nullptr, p_part, 2112, 384, 33, 0, NRES * CSD);
    k_combine<<<1152, 256>>>(bout, out);
}